// round 1
// baseline (speedup 1.0000x reference)
#include <cuda_runtime.h>
#include <cstdint>

#define NN 10000
#define NE 320000
#define D  256
#define DE 32

// ---------------- scratch (device globals; no allocation allowed) ----------
__device__ float g_nf[NN * D];        // relu(input@Wn+bn)
__device__ float g_A1[NN * D];        // nf @ Wm1
__device__ float g_A2[NN * D];        // nf @ Wm2
__device__ float g_ef[(size_t)NE * D];// relu(edgefeats@We+be)
__device__ float g_sum[NN * D];       // segment sums
__device__ int   g_cnt[NN];           // segment counts

// ---------------- tiling params -------------------------------------------
#define BM 128
#define BN 128
#define BKT 16
#define AS_STRIDE 132   // padded to break STS bank conflicts on the transpose

// ===========================================================================
// Generic fp32 GEMM: C[M,256] = op(A[M,K] @ B[K,256] (+bias, relu))
// block = 256 threads, tile 128x128x16, 8x8 per-thread microtile
// ===========================================================================
template<bool BIAS_RELU>
__global__ __launch_bounds__(256)
void gemm_n256(const float* __restrict__ A, const float* __restrict__ B,
               const float* __restrict__ bias, float* __restrict__ C,
               int M, int K)
{
    __shared__ float As[BKT * AS_STRIDE];
    __shared__ float Bs[BKT * BN];

    const int tid = threadIdx.x;
    const int rowBase = blockIdx.x * BM;
    const int colBase = blockIdx.y * BN;
    const int ty = tid >> 4;      // 0..15
    const int tx = tid & 15;      // 0..15

    float acc[8][8];
#pragma unroll
    for (int i = 0; i < 8; ++i)
#pragma unroll
        for (int j = 0; j < 8; ++j) acc[i][j] = 0.f;

    for (int k0 = 0; k0 < K; k0 += BKT) {
        // load A tile (128 x 16) transposed into As[k][m]
#pragma unroll
        for (int l = 0; l < 2; ++l) {
            int idx = tid + l * 256;          // 0..511
            int r   = idx >> 2;               // 0..127
            int kg  = (idx & 3) * 4;          // 0,4,8,12
            int gr  = rowBase + r;
            float4 v = make_float4(0.f, 0.f, 0.f, 0.f);
            if (gr < M) v = *(const float4*)&A[(size_t)gr * K + k0 + kg];
            As[(kg + 0) * AS_STRIDE + r] = v.x;
            As[(kg + 1) * AS_STRIDE + r] = v.y;
            As[(kg + 2) * AS_STRIDE + r] = v.z;
            As[(kg + 3) * AS_STRIDE + r] = v.w;
        }
        // load B tile (16 x 128)
#pragma unroll
        for (int l = 0; l < 2; ++l) {
            int idx = tid + l * 256;
            int r   = idx >> 5;               // 0..15
            int c   = (idx & 31) * 4;         // 0..124
            float4 v = *(const float4*)&B[(size_t)(k0 + r) * 256 + colBase + c];
            *(float4*)&Bs[r * BN + c] = v;
        }
        __syncthreads();

#pragma unroll
        for (int kk = 0; kk < BKT; ++kk) {
            float a[8], b[8];
            *(float4*)&a[0] = *(const float4*)&As[kk * AS_STRIDE + ty * 8];
            *(float4*)&a[4] = *(const float4*)&As[kk * AS_STRIDE + ty * 8 + 4];
            *(float4*)&b[0] = *(const float4*)&Bs[kk * BN + tx * 8];
            *(float4*)&b[4] = *(const float4*)&Bs[kk * BN + tx * 8 + 4];
#pragma unroll
            for (int i = 0; i < 8; ++i)
#pragma unroll
                for (int j = 0; j < 8; ++j)
                    acc[i][j] += a[i] * b[j];
        }
        __syncthreads();
    }

    // epilogue
    const int cb = colBase + tx * 8;
    float bv[8];
    if (BIAS_RELU) {
        *(float4*)&bv[0] = *(const float4*)&bias[cb];
        *(float4*)&bv[4] = *(const float4*)&bias[cb + 4];
    }
#pragma unroll
    for (int i = 0; i < 8; ++i) {
        int gr = rowBase + ty * 8 + i;
        if (gr < M) {
            float v[8];
#pragma unroll
            for (int j = 0; j < 8; ++j) {
                float t = acc[i][j];
                if (BIAS_RELU) t = fmaxf(t + bv[j], 0.f);
                v[j] = t;
            }
            *(float4*)&C[(size_t)gr * 256 + cb]     = *(float4*)&v[0];
            *(float4*)&C[(size_t)gr * 256 + cb + 4] = *(float4*)&v[4];
        }
    }
}

// ===========================================================================
// Mix kernel: T = g_ef @ Wm3, v = relu(T + A1[idxn[e]] + A2[seg[e]] + bm),
// then register-level segmented sum (seg sorted) + atomic flush into g_sum.
// M = NE (exact multiple of 128), K = 256.
// ===========================================================================
__global__ __launch_bounds__(256)
void mix_kernel(const float* __restrict__ EF, const float* __restrict__ B,
                const float* __restrict__ bm,
                const float* __restrict__ A1, const float* __restrict__ A2,
                const int* __restrict__ idxn, const int* __restrict__ seg)
{
    __shared__ float As[BKT * AS_STRIDE];
    __shared__ float Bs[BKT * BN];
    __shared__ int   s_i1[BM];
    __shared__ int   s_i2[BM];

    const int tid = threadIdx.x;
    const int rowBase = blockIdx.x * BM;
    const int colBase = blockIdx.y * BN;
    const int ty = tid >> 4;
    const int tx = tid & 15;

    if (tid < BM) {
        s_i1[tid] = idxn[rowBase + tid];
        s_i2[tid] = seg[rowBase + tid];
    }

    float acc[8][8];
#pragma unroll
    for (int i = 0; i < 8; ++i)
#pragma unroll
        for (int j = 0; j < 8; ++j) acc[i][j] = 0.f;

    for (int k0 = 0; k0 < 256; k0 += BKT) {
#pragma unroll
        for (int l = 0; l < 2; ++l) {
            int idx = tid + l * 256;
            int r   = idx >> 2;
            int kg  = (idx & 3) * 4;
            float4 v = *(const float4*)&EF[(size_t)(rowBase + r) * 256 + k0 + kg];
            As[(kg + 0) * AS_STRIDE + r] = v.x;
            As[(kg + 1) * AS_STRIDE + r] = v.y;
            As[(kg + 2) * AS_STRIDE + r] = v.z;
            As[(kg + 3) * AS_STRIDE + r] = v.w;
        }
#pragma unroll
        for (int l = 0; l < 2; ++l) {
            int idx = tid + l * 256;
            int r   = idx >> 5;
            int c   = (idx & 31) * 4;
            float4 v = *(const float4*)&B[(size_t)(k0 + r) * 256 + colBase + c];
            *(float4*)&Bs[r * BN + c] = v;
        }
        __syncthreads();
#pragma unroll
        for (int kk = 0; kk < BKT; ++kk) {
            float a[8], b[8];
            *(float4*)&a[0] = *(const float4*)&As[kk * AS_STRIDE + ty * 8];
            *(float4*)&a[4] = *(const float4*)&As[kk * AS_STRIDE + ty * 8 + 4];
            *(float4*)&b[0] = *(const float4*)&Bs[kk * BN + tx * 8];
            *(float4*)&b[4] = *(const float4*)&Bs[kk * BN + tx * 8 + 4];
#pragma unroll
            for (int i = 0; i < 8; ++i)
#pragma unroll
                for (int j = 0; j < 8; ++j)
                    acc[i][j] += a[i] * b[j];
        }
        __syncthreads();
    }

    // epilogue: bias+gathers+relu, then run-compressed segmented atomic add
    const int cb = colBase + tx * 8;
    float bv[8];
    *(float4*)&bv[0] = *(const float4*)&bm[cb];
    *(float4*)&bv[4] = *(const float4*)&bm[cb + 4];

    float run[8];
    int runSeg = -1;
#pragma unroll
    for (int i = 0; i < 8; ++i) {
        int lr = ty * 8 + i;
        int i1 = s_i1[lr];
        int i2 = s_i2[lr];
        float4 p0 = *(const float4*)&A1[(size_t)i1 * 256 + cb];
        float4 p1 = *(const float4*)&A1[(size_t)i1 * 256 + cb + 4];
        float4 q0 = *(const float4*)&A2[(size_t)i2 * 256 + cb];
        float4 q1 = *(const float4*)&A2[(size_t)i2 * 256 + cb + 4];
        float v[8];
        v[0] = fmaxf(acc[i][0] + p0.x + q0.x + bv[0], 0.f);
        v[1] = fmaxf(acc[i][1] + p0.y + q0.y + bv[1], 0.f);
        v[2] = fmaxf(acc[i][2] + p0.z + q0.z + bv[2], 0.f);
        v[3] = fmaxf(acc[i][3] + p0.w + q0.w + bv[3], 0.f);
        v[4] = fmaxf(acc[i][4] + p1.x + q1.x + bv[4], 0.f);
        v[5] = fmaxf(acc[i][5] + p1.y + q1.y + bv[5], 0.f);
        v[6] = fmaxf(acc[i][6] + p1.z + q1.z + bv[6], 0.f);
        v[7] = fmaxf(acc[i][7] + p1.w + q1.w + bv[7], 0.f);

        if (i2 != runSeg) {
            if (runSeg >= 0) {
#pragma unroll
                for (int j = 0; j < 8; ++j)
                    atomicAdd(&g_sum[(size_t)runSeg * 256 + cb + j], run[j]);
            }
            runSeg = i2;
#pragma unroll
            for (int j = 0; j < 8; ++j) run[j] = v[j];
        } else {
#pragma unroll
            for (int j = 0; j < 8; ++j) run[j] += v[j];
        }
    }
#pragma unroll
    for (int j = 0; j < 8; ++j)
        atomicAdd(&g_sum[(size_t)runSeg * 256 + cb + j], run[j]);
}

// ---------------- small helper kernels ------------------------------------
__global__ void zero_kernel()
{
    int i = blockIdx.x * blockDim.x + threadIdx.x;
    if (i < NN * D) g_sum[i] = 0.f;
    if (i < NN)     g_cnt[i] = 0;
}

__global__ void cnt_kernel(const int* __restrict__ seg)
{
    int i = blockIdx.x * blockDim.x + threadIdx.x;
    if (i < NE) atomicAdd(&g_cnt[seg[i]], 1);
}

__global__ void final_kernel(float* __restrict__ out)
{
    int i = blockIdx.x * blockDim.x + threadIdx.x;
    if (i < NN * D) {
        int n = i >> 8;
        int c = g_cnt[n];
        out[i] = (c > 0) ? g_sum[i] / (float)c : 0.f;
    }
}

// ===========================================================================
extern "C" void kernel_launch(void* const* d_in, const int* in_sizes, int n_in,
                              void* d_out, int out_size)
{
    const float* input     = (const float*)d_in[0];   // [NN, 256]
    const float* edgefeats = (const float*)d_in[1];   // [NE, 32]
    const int*   idxn      = (const int*)  d_in[2];   // [NE]
    const int*   seg_ids   = (const int*)  d_in[3];   // [NE]
    const float* Wn        = (const float*)d_in[4];   // [256,256]
    const float* bn        = (const float*)d_in[5];   // [256]
    const float* We        = (const float*)d_in[6];   // [32,256]
    const float* be        = (const float*)d_in[7];   // [256]
    const float* Wm        = (const float*)d_in[8];   // [768,256]
    const float* bm        = (const float*)d_in[9];   // [256]
    float* out = (float*)d_out;

    float* p_nf = nullptr; float* p_A1 = nullptr; float* p_A2 = nullptr;
    float* p_ef = nullptr;
    cudaGetSymbolAddress((void**)&p_nf, g_nf);
    cudaGetSymbolAddress((void**)&p_A1, g_A1);
    cudaGetSymbolAddress((void**)&p_A2, g_A2);
    cudaGetSymbolAddress((void**)&p_ef, g_ef);

    // 0) zero segment accumulators (replayed every graph launch)
    zero_kernel<<<(NN * D + 255) / 256, 256>>>();

    // 1) counts
    cnt_kernel<<<(NE + 255) / 256, 256>>>(seg_ids);

    // 2) nf = relu(input @ Wn + bn)       [NN,256]
    {
        dim3 g((NN + BM - 1) / BM, 2);
        gemm_n256<true><<<g, 256>>>(input, Wn, bn, p_nf, NN, 256);
    }
    // 3) A1 = nf @ Wm1, A2 = nf @ Wm2     [NN,256] each (no bias/relu)
    {
        dim3 g((NN + BM - 1) / BM, 2);
        gemm_n256<false><<<g, 256>>>(p_nf, Wm,             nullptr, p_A1, NN, 256);
        gemm_n256<false><<<g, 256>>>(p_nf, Wm + 256 * 256, nullptr, p_A2, NN, 256);
    }
    // 4) ef = relu(edgefeats @ We + be)   [NE,256]
    {
        dim3 g(NE / BM, 2);
        gemm_n256<true><<<g, 256>>>(edgefeats, We, be, p_ef, NE, 32);
    }
    // 5) fused mix GEMM + gathers + relu + segmented sum
    {
        dim3 g(NE / BM, 2);
        mix_kernel<<<g, 256>>>(p_ef, Wm + 512 * 256, bm, p_A1, p_A2, idxn, seg_ids);
    }
    // 6) mean + zero-degree handling
    final_kernel<<<(NN * D + 255) / 256, 256>>>(out);
}

// round 4
// speedup vs baseline: 1.4487x; 1.4487x over previous
#include <cuda_runtime.h>
#include <cuda_bf16.h>
#include <cstdint>

#define NN 10000
#define NE 320000
#define D  256
#define DE 32

// ---------------- scratch (device globals; no allocation allowed) ----------
__device__ __align__(256) float g_nf[NN * D];
__device__ __align__(256) float g_A1[NN * D];
__device__ __align__(256) float g_A2[NN * D];
__device__ __align__(256) __nv_bfloat16 g_efh[(size_t)NE * D];  // bf16(relu(edgefeats@We+be))
__device__ __align__(256) __nv_bfloat16 g_wm3t_h[D * D];        // Wm3^T hi [N][K]
__device__ __align__(256) __nv_bfloat16 g_wm3t_l[D * D];        // Wm3^T lo [N][K]
__device__ __align__(256) float g_sum[NN * D];
__device__ int g_cnt[NN];

// =============================== PTX helpers ===============================
__device__ __forceinline__ uint32_t smem_u32(const void* p) {
    uint32_t a;
    asm("{ .reg .u64 t; cvta.to.shared.u64 t, %1; cvt.u32.u64 %0, t; }"
        : "=r"(a) : "l"(p));
    return a;
}
#define SW128(off) ((off) ^ (((off) >> 3) & 0x70))

#define CP_ASYNC16(dst, src) \
    asm volatile("cp.async.cg.shared.global [%0], [%1], 16;" \
        :: "r"(dst), "l"(src) : "memory")
#define CP_COMMIT() asm volatile("cp.async.commit_group;" ::: "memory")
#define CP_WAIT(n)  asm volatile("cp.async.wait_group %0;" :: "n"(n) : "memory")

#define LDSM_X4(r0, r1, r2, r3, addr) \
    asm volatile("ldmatrix.sync.aligned.m8n8.x4.shared.b16 {%0,%1,%2,%3}, [%4];" \
        : "=r"(r0), "=r"(r1), "=r"(r2), "=r"(r3) : "r"(addr))

#define MMA_BF16(c, a, b0, b1) \
    asm volatile("mma.sync.aligned.m16n8k16.row.col.f32.bf16.bf16.f32 " \
        "{%0,%1,%2,%3}, {%4,%5,%6,%7}, {%8,%9}, {%0,%1,%2,%3};" \
        : "+f"((c)[0]), "+f"((c)[1]), "+f"((c)[2]), "+f"((c)[3]) \
        : "r"((a)[0]), "r"((a)[1]), "r"((a)[2]), "r"((a)[3]), "r"(b0), "r"(b1))

// ---------------- fp32 GEMM tiling params ----------------------------------
#define BM 128
#define BN 128
#define BKT 16
#define AS_STRIDE 132

// ===========================================================================
// fp32 SIMT GEMM: C[M,256] = op(A[M,K] @ B[K,256] (+bias, relu))
// ===========================================================================
template<bool BIAS_RELU>
__global__ __launch_bounds__(256)
void gemm_n256(const float* __restrict__ A, const float* __restrict__ B,
               const float* __restrict__ bias, float* __restrict__ C,
               int M, int K)
{
    __shared__ float As[BKT * AS_STRIDE];
    __shared__ float Bs[BKT * BN];

    const int tid = threadIdx.x;
    const int rowBase = blockIdx.x * BM;
    const int colBase = blockIdx.y * BN;
    const int ty = tid >> 4, tx = tid & 15;

    float acc[8][8];
#pragma unroll
    for (int i = 0; i < 8; ++i)
#pragma unroll
        for (int j = 0; j < 8; ++j) acc[i][j] = 0.f;

    for (int k0 = 0; k0 < K; k0 += BKT) {
#pragma unroll
        for (int l = 0; l < 2; ++l) {
            int idx = tid + l * 256;
            int r = idx >> 2, kg = (idx & 3) * 4;
            int gr = rowBase + r;
            float4 v = make_float4(0.f, 0.f, 0.f, 0.f);
            if (gr < M) v = *(const float4*)&A[(size_t)gr * K + k0 + kg];
            As[(kg + 0) * AS_STRIDE + r] = v.x;
            As[(kg + 1) * AS_STRIDE + r] = v.y;
            As[(kg + 2) * AS_STRIDE + r] = v.z;
            As[(kg + 3) * AS_STRIDE + r] = v.w;
        }
#pragma unroll
        for (int l = 0; l < 2; ++l) {
            int idx = tid + l * 256;
            int r = idx >> 5, c = (idx & 31) * 4;
            *(float4*)&Bs[r * BN + c] = *(const float4*)&B[(size_t)(k0 + r) * 256 + colBase + c];
        }
        __syncthreads();
#pragma unroll
        for (int kk = 0; kk < BKT; ++kk) {
            float a[8], b[8];
            *(float4*)&a[0] = *(const float4*)&As[kk * AS_STRIDE + ty * 8];
            *(float4*)&a[4] = *(const float4*)&As[kk * AS_STRIDE + ty * 8 + 4];
            *(float4*)&b[0] = *(const float4*)&Bs[kk * BN + tx * 8];
            *(float4*)&b[4] = *(const float4*)&Bs[kk * BN + tx * 8 + 4];
#pragma unroll
            for (int i = 0; i < 8; ++i)
#pragma unroll
                for (int j = 0; j < 8; ++j) acc[i][j] += a[i] * b[j];
        }
        __syncthreads();
    }

    const int cb = colBase + tx * 8;
    float bv[8];
    if (BIAS_RELU) {
        *(float4*)&bv[0] = *(const float4*)&bias[cb];
        *(float4*)&bv[4] = *(const float4*)&bias[cb + 4];
    }
#pragma unroll
    for (int i = 0; i < 8; ++i) {
        int gr = rowBase + ty * 8 + i;
        if (gr < M) {
            float v[8];
#pragma unroll
            for (int j = 0; j < 8; ++j) {
                float t = acc[i][j];
                if (BIAS_RELU) t = fmaxf(t + bv[j], 0.f);
                v[j] = t;
            }
            *(float4*)&C[(size_t)gr * 256 + cb]     = *(float4*)&v[0];
            *(float4*)&C[(size_t)gr * 256 + cb + 4] = *(float4*)&v[4];
        }
    }
}

// ===========================================================================
// ef GEMM: relu(edgefeats[E,32] @ We[32,256] + be) -> bf16 (hi only)
// ===========================================================================
__global__ __launch_bounds__(256)
void gemm_ef(const float* __restrict__ A, const float* __restrict__ B,
             const float* __restrict__ bias, __nv_bfloat16* __restrict__ Ch)
{
    __shared__ float As[BKT * AS_STRIDE];
    __shared__ float Bs[BKT * BN];

    const int tid = threadIdx.x;
    const int rowBase = blockIdx.x * BM;
    const int colBase = blockIdx.y * BN;
    const int ty = tid >> 4, tx = tid & 15;
    const int K = 32;

    float acc[8][8];
#pragma unroll
    for (int i = 0; i < 8; ++i)
#pragma unroll
        for (int j = 0; j < 8; ++j) acc[i][j] = 0.f;

#pragma unroll
    for (int k0 = 0; k0 < K; k0 += BKT) {
#pragma unroll
        for (int l = 0; l < 2; ++l) {
            int idx = tid + l * 256;
            int r = idx >> 2, kg = (idx & 3) * 4;
            float4 v = *(const float4*)&A[(size_t)(rowBase + r) * K + k0 + kg];
            As[(kg + 0) * AS_STRIDE + r] = v.x;
            As[(kg + 1) * AS_STRIDE + r] = v.y;
            As[(kg + 2) * AS_STRIDE + r] = v.z;
            As[(kg + 3) * AS_STRIDE + r] = v.w;
        }
#pragma unroll
        for (int l = 0; l < 2; ++l) {
            int idx = tid + l * 256;
            int r = idx >> 5, c = (idx & 31) * 4;
            *(float4*)&Bs[r * BN + c] = *(const float4*)&B[(size_t)(k0 + r) * 256 + colBase + c];
        }
        __syncthreads();
#pragma unroll
        for (int kk = 0; kk < BKT; ++kk) {
            float a[8], b[8];
            *(float4*)&a[0] = *(const float4*)&As[kk * AS_STRIDE + ty * 8];
            *(float4*)&a[4] = *(const float4*)&As[kk * AS_STRIDE + ty * 8 + 4];
            *(float4*)&b[0] = *(const float4*)&Bs[kk * BN + tx * 8];
            *(float4*)&b[4] = *(const float4*)&Bs[kk * BN + tx * 8 + 4];
#pragma unroll
            for (int i = 0; i < 8; ++i)
#pragma unroll
                for (int j = 0; j < 8; ++j) acc[i][j] += a[i] * b[j];
        }
        __syncthreads();
    }

    const int cb = colBase + tx * 8;
    float bv[8];
    *(float4*)&bv[0] = *(const float4*)&bias[cb];
    *(float4*)&bv[4] = *(const float4*)&bias[cb + 4];
#pragma unroll
    for (int i = 0; i < 8; ++i) {
        int gr = rowBase + ty * 8 + i;
        __nv_bfloat16 h[8];
#pragma unroll
        for (int j = 0; j < 8; ++j)
            h[j] = __float2bfloat16(fmaxf(acc[i][j] + bv[j], 0.f));
        *(uint4*)&Ch[(size_t)gr * 256 + cb] = *(uint4*)h;
    }
}

// ===========================================================================
// Wm3^T prep: [K,N] fp32 -> [N,K] bf16 hi/lo (hi+lo captures ~16 mantissa bits)
// ===========================================================================
__global__ void prep_wm3t(const float* __restrict__ Wm3)
{
    int idx = blockIdx.x * blockDim.x + threadIdx.x;  // 65536
    int n = idx & 255, k = idx >> 8;
    float w = Wm3[k * 256 + n];
    __nv_bfloat16 h = __float2bfloat16(w);
    g_wm3t_h[n * 256 + k] = h;
    g_wm3t_l[n * 256 + k] = __float2bfloat16(w - __bfloat162float(h));
}

// ===========================================================================
// mix kernel (HMMA): T = EF @ (Wm3h + Wm3l)^T, fused epilogue:
// relu(T + A1[idxn] + A2[seg] + bm), warp segmented reduce, atomicAdd
// Tile: 128x128, BK=64, 2-stage cp.async, 8 warps of 64x32 mma tiles.
// ===========================================================================
#define MIX_BK      64
#define STAGE_BYTES 49152                 // A 16K + Bh 16K + Bl 16K
#define OFF_BH      16384
#define OFF_BL      32768
#define EPI_STRIDE  132                   // floats
#define MIX_SMEM    (2 * STAGE_BYTES)     // 96KB (epilogue 67.6KB overlays it)

__device__ __forceinline__ void mix_load_stage(
    uint32_t sbase, int buf, int kc, int rowBase, int colBase,
    const __nv_bfloat16* EFh, const __nv_bfloat16* Bh, const __nv_bfloat16* Bl,
    int tid)
{
    const uint32_t st = sbase + buf * STAGE_BYTES;
    const int kBase = kc * MIX_BK;
    // A: 128 rows x 64 bf16 (8 chunks/row)
#pragma unroll
    for (int l = 0; l < 4; ++l) {
        int idx = tid + l * 256;
        int r = idx >> 3, cc = idx & 7;
        const char* src = (const char*)(EFh + (size_t)(rowBase + r) * 256 + kBase) + cc * 16;
        CP_ASYNC16(st + SW128((uint32_t)(r * 128 + cc * 16)), src);
    }
    // Bh/Bl: 128 n-rows x 64 bf16
#pragma unroll
    for (int l = 0; l < 4; ++l) {
        int idx = tid + l * 256;
        int r = idx >> 3, cc = idx & 7;
        uint32_t doff = SW128((uint32_t)(r * 128 + cc * 16));
        const char* sh = (const char*)(Bh + (size_t)(colBase + r) * 256 + kBase) + cc * 16;
        const char* sl = (const char*)(Bl + (size_t)(colBase + r) * 256 + kBase) + cc * 16;
        CP_ASYNC16(st + OFF_BH + doff, sh);
        CP_ASYNC16(st + OFF_BL + doff, sl);
    }
}

__global__ __launch_bounds__(256)
void mix_mma_kernel(const __nv_bfloat16* __restrict__ EFh,
                    const __nv_bfloat16* __restrict__ Bh,
                    const __nv_bfloat16* __restrict__ Bl,
                    const float* __restrict__ bm,
                    const float* __restrict__ A1, const float* __restrict__ A2,
                    const int* __restrict__ idxn, const int* __restrict__ seg)
{
    extern __shared__ char smem[];
    const uint32_t sbase = smem_u32(smem);
    const int tid = threadIdx.x;
    const int wid = tid >> 5;
    const int lane = tid & 31;
    const int rowBase = blockIdx.x * 128;
    const int colBase = blockIdx.y * 128;

    const int wm = wid >> 2;        // 0..1  (64-row band)
    const int wn = wid & 3;         // 0..3  (32-col band)
    const int lr = lane & 15;
    const int lc = lane >> 4;

    float acc[4][4][4];
#pragma unroll
    for (int mt = 0; mt < 4; ++mt)
#pragma unroll
        for (int nt = 0; nt < 4; ++nt)
#pragma unroll
            for (int q = 0; q < 4; ++q) acc[mt][nt][q] = 0.f;

    mix_load_stage(sbase, 0, 0, rowBase, colBase, EFh, Bh, Bl, tid);
    CP_COMMIT();

    for (int kc = 0; kc < 4; ++kc) {
        if (kc < 3) {
            mix_load_stage(sbase, (kc + 1) & 1, kc + 1, rowBase, colBase, EFh, Bh, Bl, tid);
            CP_COMMIT();
            CP_WAIT(1);
        } else {
            CP_WAIT(0);
        }
        __syncthreads();

        const uint32_t st = sbase + (kc & 1) * STAGE_BYTES;
#pragma unroll
        for (int k16 = 0; k16 < 4; ++k16) {
            const uint32_t kOff = k16 * 32 + lc * 16;
            uint32_t a[4][4];
#pragma unroll
            for (int mt = 0; mt < 4; ++mt) {
                int row = wm * 64 + mt * 16 + lr;
                LDSM_X4(a[mt][0], a[mt][1], a[mt][2], a[mt][3],
                        st + SW128((uint32_t)(row * 128) + kOff));
            }
            uint32_t bh[2][4], bl[2][4];
#pragma unroll
            for (int ng = 0; ng < 2; ++ng) {
                int row = wn * 32 + ng * 16 + lr;
                uint32_t off = SW128((uint32_t)(row * 128) + kOff);
                LDSM_X4(bh[ng][0], bh[ng][1], bh[ng][2], bh[ng][3], st + OFF_BH + off);
                LDSM_X4(bl[ng][0], bl[ng][1], bl[ng][2], bl[ng][3], st + OFF_BL + off);
            }
#pragma unroll
            for (int mt = 0; mt < 4; ++mt)
#pragma unroll
                for (int nt = 0; nt < 4; ++nt) {
                    const int ng = nt >> 1, s = nt & 1;
                    MMA_BF16(acc[mt][nt], a[mt], bh[ng][s], bh[ng][s + 2]);
                    MMA_BF16(acc[mt][nt], a[mt], bl[ng][s], bl[ng][s + 2]);
                }
        }
        __syncthreads();
    }

    // ---- fragments -> padded smem [128][EPI_STRIDE] fp32 ----
    float* sC = (float*)smem;
    {
        const int r0 = wm * 64 + (lane >> 2);
        const int c0 = wn * 32 + (lane & 3) * 2;
#pragma unroll
        for (int mt = 0; mt < 4; ++mt)
#pragma unroll
            for (int nt = 0; nt < 4; ++nt) {
                int rr = r0 + mt * 16;
                int cc = c0 + nt * 8;
                *(float2*)&sC[rr * EPI_STRIDE + cc] =
                    make_float2(acc[mt][nt][0], acc[mt][nt][1]);
                *(float2*)&sC[(rr + 8) * EPI_STRIDE + cc] =
                    make_float2(acc[mt][nt][2], acc[mt][nt][3]);
            }
    }
    __syncthreads();

    // ---- row-oriented epilogue: lane = edge row ----
    const int wrow = (wid & 3) * 32 + lane;     // 0..127
    const int e = rowBase + wrow;
    const int i1 = idxn[e];
    const int i2 = seg[e];
    const int ch = (wid >> 2) * 64;             // warps 0-3: cols 0..63, 4-7: 64..127

    int prevseg = __shfl_up_sync(0xFFFFFFFFu, i2, 1);
    bool head = (lane == 0) || (prevseg != i2);
    unsigned hm = __ballot_sync(0xFFFFFFFFu, head);
    unsigned rest = (lane < 31) ? (hm & (0xFFFFFFFEu << lane)) : 0u;
    int e_end = rest ? (__ffs(rest) - 2) : 31;
    float* srow = &g_sum[(size_t)i2 * 256 + colBase];
    const float* a1row = &A1[(size_t)i1 * 256 + colBase];
    const float* a2row = &A2[(size_t)i2 * 256 + colBase];

#pragma unroll
    for (int g = 0; g < 16; ++g) {
        const int cb = ch + g * 4;
        float4 t  = *(const float4*)&sC[wrow * EPI_STRIDE + cb];
        float4 a1 = *(const float4*)&a1row[cb];
        float4 a2 = *(const float4*)&a2row[cb];
        float4 bv = *(const float4*)&bm[colBase + cb];
        float v[4];
        v[0] = fmaxf(t.x + a1.x + a2.x + bv.x, 0.f);
        v[1] = fmaxf(t.y + a1.y + a2.y + bv.y, 0.f);
        v[2] = fmaxf(t.z + a1.z + a2.z + bv.z, 0.f);
        v[3] = fmaxf(t.w + a1.w + a2.w + bv.w, 0.f);
#pragma unroll
        for (int j = 0; j < 4; ++j) {
            float x = v[j];
#pragma unroll
            for (int d2 = 1; d2 < 32; d2 <<= 1) {
                float o = __shfl_down_sync(0xFFFFFFFFu, x, d2);
                if (lane + d2 <= e_end) x += o;
            }
            if (head) atomicAdd(&srow[cb + j], x);
        }
    }
}

// ---------------- small helper kernels ------------------------------------
__global__ void zero_kernel()
{
    int i = blockIdx.x * blockDim.x + threadIdx.x;
    if (i < NN * D) g_sum[i] = 0.f;
    if (i < NN)     g_cnt[i] = 0;
}

__global__ void cnt_kernel(const int* __restrict__ seg)
{
    int i = blockIdx.x * blockDim.x + threadIdx.x;
    if (i < NE) atomicAdd(&g_cnt[seg[i]], 1);
}

__global__ void final_kernel(float* __restrict__ out)
{
    int i = blockIdx.x * blockDim.x + threadIdx.x;
    if (i < NN * D) {
        int n = i >> 8;
        int c = g_cnt[n];
        out[i] = (c > 0) ? g_sum[i] / (float)c : 0.f;
    }
}

// ===========================================================================
extern "C" void kernel_launch(void* const* d_in, const int* in_sizes, int n_in,
                              void* d_out, int out_size)
{
    const float* input     = (const float*)d_in[0];
    const float* edgefeats = (const float*)d_in[1];
    const int*   idxn      = (const int*)  d_in[2];
    const int*   seg_ids   = (const int*)  d_in[3];
    const float* Wn        = (const float*)d_in[4];
    const float* bn        = (const float*)d_in[5];
    const float* We        = (const float*)d_in[6];
    const float* be        = (const float*)d_in[7];
    const float* Wm        = (const float*)d_in[8];
    const float* bm        = (const float*)d_in[9];
    float* out = (float*)d_out;

    float *p_nf, *p_A1, *p_A2;
    __nv_bfloat16 *p_efh, *p_wh, *p_wl;
    cudaGetSymbolAddress((void**)&p_nf, g_nf);
    cudaGetSymbolAddress((void**)&p_A1, g_A1);
    cudaGetSymbolAddress((void**)&p_A2, g_A2);
    cudaGetSymbolAddress((void**)&p_efh, g_efh);
    cudaGetSymbolAddress((void**)&p_wh, g_wm3t_h);
    cudaGetSymbolAddress((void**)&p_wl, g_wm3t_l);

    cudaFuncSetAttribute(mix_mma_kernel,
                         cudaFuncAttributeMaxDynamicSharedMemorySize, MIX_SMEM);

    zero_kernel<<<(NN * D + 255) / 256, 256>>>();
    cnt_kernel<<<(NE + 255) / 256, 256>>>(seg_ids);
    prep_wm3t<<<256, 256>>>(Wm + 512 * 256);

    {
        dim3 g((NN + BM - 1) / BM, 2);
        gemm_n256<true><<<g, 256>>>(input, Wn, bn, p_nf, NN, 256);
        gemm_n256<false><<<g, 256>>>(p_nf, Wm,             nullptr, p_A1, NN, 256);
        gemm_n256<false><<<g, 256>>>(p_nf, Wm + 256 * 256, nullptr, p_A2, NN, 256);
    }
    {
        dim3 g(NE / BM, 2);
        gemm_ef<<<g, 256>>>(edgefeats, We, be, p_efh);
    }
    {
        dim3 g(NE / 128, 2);
        mix_mma_kernel<<<g, 256, MIX_SMEM>>>(p_efh, p_wh, p_wl, bm,
                                             p_A1, p_A2, idxn, seg_ids);
    }
    final_kernel<<<(NN * D + 255) / 256, 256>>>(out);
}

// round 5
// speedup vs baseline: 1.5916x; 1.0987x over previous
#include <cuda_runtime.h>
#include <cuda_bf16.h>
#include <cstdint>

#define NN 10000
#define NE 320000
#define D  256

// ---------------- scratch (device globals; no allocation allowed) ----------
__device__ __align__(256) float g_A1[NN * D];
__device__ __align__(256) float g_A2[NN * D];
__device__ __align__(256) float g_sum[NN * D];
__device__ int g_cnt[NN];

__device__ __align__(256) __nv_bfloat16 g_in_h[NN * D];
__device__ __align__(256) __nv_bfloat16 g_in_l[NN * D];
__device__ __align__(256) __nv_bfloat16 g_nf_h[NN * D];
__device__ __align__(256) __nv_bfloat16 g_nf_l[NN * D];
__device__ __align__(256) __nv_bfloat16 g_efin[(size_t)NE * 64];   // padded K=64
__device__ __align__(256) __nv_bfloat16 g_efh[(size_t)NE * D];

__device__ __align__(256) __nv_bfloat16 g_wnt_h[D * D],  g_wnt_l[D * D];
__device__ __align__(256) __nv_bfloat16 g_wm1t_h[D * D], g_wm1t_l[D * D];
__device__ __align__(256) __nv_bfloat16 g_wm2t_h[D * D], g_wm2t_l[D * D];
__device__ __align__(256) __nv_bfloat16 g_wm3t_h[D * D], g_wm3t_l[D * D];
__device__ __align__(256) __nv_bfloat16 g_wet_h[D * 64], g_wet_l[D * 64];

// =============================== PTX helpers ===============================
__device__ __forceinline__ uint32_t smem_u32(const void* p) {
    uint32_t a;
    asm("{ .reg .u64 t; cvta.to.shared.u64 t, %1; cvt.u32.u64 %0, t; }"
        : "=r"(a) : "l"(p));
    return a;
}
#define SW128(off) ((off) ^ (((off) >> 3) & 0x70))

#define CP_ASYNC16(dst, src) \
    asm volatile("cp.async.cg.shared.global [%0], [%1], 16;" \
        :: "r"(dst), "l"(src) : "memory")
#define CP_ASYNC16Z(dst, src, sz) \
    asm volatile("cp.async.cg.shared.global [%0], [%1], 16, %2;" \
        :: "r"(dst), "l"(src), "r"(sz) : "memory")
#define CP_COMMIT() asm volatile("cp.async.commit_group;" ::: "memory")
#define CP_WAIT(n)  asm volatile("cp.async.wait_group %0;" :: "n"(n) : "memory")

#define LDSM_X4(r0, r1, r2, r3, addr) \
    asm volatile("ldmatrix.sync.aligned.m8n8.x4.shared.b16 {%0,%1,%2,%3}, [%4];" \
        : "=r"(r0), "=r"(r1), "=r"(r2), "=r"(r3) : "r"(addr))

#define MMA_BF16(c, a, b0, b1) \
    asm volatile("mma.sync.aligned.m16n8k16.row.col.f32.bf16.bf16.f32 " \
        "{%0,%1,%2,%3}, {%4,%5,%6,%7}, {%8,%9}, {%0,%1,%2,%3};" \
        : "+f"((c)[0]), "+f"((c)[1]), "+f"((c)[2]), "+f"((c)[3]) \
        : "r"((a)[0]), "r"((a)[1]), "r"((a)[2]), "r"((a)[3]), "r"(b0), "r"(b1))

// ===========================================================================
// Unified HMMA GEMM: C[M,256] = op(A[M,KDIM] @ B[256,KDIM]^T)
// NPASS=3: Ah·Bh + Ah·Bl + Al·Bh ; NPASS=2: Ah·Bh + Ah·Bl
// OUT: 0=fp32 Cf, 1=bf16 hi/lo Ch/Cl, 2=bf16 hi Ch
// Tile 128x128, BK=64, 8 warps of 64x32 mma tiles. Same layout as mix.
// ===========================================================================
template<int KDIM, int NPASS, bool RELU, int OUT>
__global__ __launch_bounds__(256)
void hmma_gemm(const __nv_bfloat16* __restrict__ Ah,
               const __nv_bfloat16* __restrict__ Al,
               const __nv_bfloat16* __restrict__ Bh_,
               const __nv_bfloat16* __restrict__ Bl_,
               const float* __restrict__ bias,
               float* __restrict__ Cf,
               __nv_bfloat16* __restrict__ Ch,
               __nv_bfloat16* __restrict__ Cl,
               int M)
{
    constexpr int OFF_AL2 = 16384;
    constexpr int OFF_BH2 = (NPASS == 3) ? 32768 : 16384;
    constexpr int OFF_BL2 = OFF_BH2 + 16384;
    constexpr int SBYTES  = OFF_BL2 + 16384;
    constexpr int NKC     = KDIM / 64;

    extern __shared__ char smem[];
    const uint32_t sbase = smem_u32(smem);
    const int tid = threadIdx.x;
    const int wid = tid >> 5;
    const int lane = tid & 31;
    const int rowBase = blockIdx.x * 128;
    const int colBase = blockIdx.y * 128;

    const int wm = wid >> 2;
    const int wn = wid & 3;
    const int lr = lane & 15;
    const int lc = lane >> 4;

    float acc[4][4][4];
#pragma unroll
    for (int mt = 0; mt < 4; ++mt)
#pragma unroll
        for (int nt = 0; nt < 4; ++nt)
#pragma unroll
            for (int q = 0; q < 4; ++q) acc[mt][nt][q] = 0.f;

    auto load_stage = [&](int buf, int kc) {
        const uint32_t st = sbase + buf * SBYTES;
        const int kBase = kc * 64;
#pragma unroll
        for (int l = 0; l < 4; ++l) {
            int idx = tid + l * 256;
            int r = idx >> 3, cc = idx & 7;
            int gr = rowBase + r;
            uint32_t sz = (gr < M) ? 16u : 0u;
            int grc = (gr < M) ? gr : (M - 1);
            uint32_t doff = SW128((uint32_t)(r * 128 + cc * 16));
            const char* sh = (const char*)(Ah + (size_t)grc * KDIM + kBase) + cc * 16;
            CP_ASYNC16Z(st + doff, sh, sz);
            if (NPASS == 3) {
                const char* sl = (const char*)(Al + (size_t)grc * KDIM + kBase) + cc * 16;
                CP_ASYNC16Z(st + OFF_AL2 + doff, sl, sz);
            }
        }
#pragma unroll
        for (int l = 0; l < 4; ++l) {
            int idx = tid + l * 256;
            int r = idx >> 3, cc = idx & 7;
            uint32_t doff = SW128((uint32_t)(r * 128 + cc * 16));
            const char* sh = (const char*)(Bh_ + (size_t)(colBase + r) * KDIM + kBase) + cc * 16;
            const char* sl = (const char*)(Bl_ + (size_t)(colBase + r) * KDIM + kBase) + cc * 16;
            CP_ASYNC16(st + OFF_BH2 + doff, sh);
            CP_ASYNC16(st + OFF_BL2 + doff, sl);
        }
    };

    load_stage(0, 0);
    CP_COMMIT();

    for (int kc = 0; kc < NKC; ++kc) {
        if (kc + 1 < NKC) {
            load_stage((kc + 1) & 1, kc + 1);
            CP_COMMIT();
            CP_WAIT(1);
        } else {
            CP_WAIT(0);
        }
        __syncthreads();

        const uint32_t st = sbase + (kc & 1) * SBYTES;
#pragma unroll
        for (int k16 = 0; k16 < 4; ++k16) {
            const uint32_t kOff = k16 * 32 + lc * 16;
            uint32_t ah[4][4], al[4][4];
#pragma unroll
            for (int mt = 0; mt < 4; ++mt) {
                int row = wm * 64 + mt * 16 + lr;
                uint32_t off = SW128((uint32_t)(row * 128) + kOff);
                LDSM_X4(ah[mt][0], ah[mt][1], ah[mt][2], ah[mt][3], st + off);
                if (NPASS == 3)
                    LDSM_X4(al[mt][0], al[mt][1], al[mt][2], al[mt][3],
                            st + OFF_AL2 + off);
            }
            uint32_t bh[2][4], bl[2][4];
#pragma unroll
            for (int ng = 0; ng < 2; ++ng) {
                int row = wn * 32 + ng * 16 + lr;
                uint32_t off = SW128((uint32_t)(row * 128) + kOff);
                LDSM_X4(bh[ng][0], bh[ng][1], bh[ng][2], bh[ng][3], st + OFF_BH2 + off);
                LDSM_X4(bl[ng][0], bl[ng][1], bl[ng][2], bl[ng][3], st + OFF_BL2 + off);
            }
#pragma unroll
            for (int mt = 0; mt < 4; ++mt)
#pragma unroll
                for (int nt = 0; nt < 4; ++nt) {
                    const int ng = nt >> 1, s = nt & 1;
                    MMA_BF16(acc[mt][nt], ah[mt], bh[ng][s], bh[ng][s + 2]);
                    MMA_BF16(acc[mt][nt], ah[mt], bl[ng][s], bl[ng][s + 2]);
                    if (NPASS == 3)
                        MMA_BF16(acc[mt][nt], al[mt], bh[ng][s], bh[ng][s + 2]);
                }
        }
        __syncthreads();
    }

    // ---- epilogue: fragment-direct global stores ----
    const int row0 = rowBase + wm * 64 + (lane >> 2);
    const int col0 = colBase + wn * 32 + ((lane & 3) << 1);
#pragma unroll
    for (int mt = 0; mt < 4; ++mt)
#pragma unroll
        for (int nt = 0; nt < 4; ++nt) {
            const int c = col0 + nt * 8;
            float v0 = acc[mt][nt][0], v1 = acc[mt][nt][1];
            float v2 = acc[mt][nt][2], v3 = acc[mt][nt][3];
            if (RELU) {
                float2 bb = *(const float2*)&bias[c];
                v0 = fmaxf(v0 + bb.x, 0.f); v1 = fmaxf(v1 + bb.y, 0.f);
                v2 = fmaxf(v2 + bb.x, 0.f); v3 = fmaxf(v3 + bb.y, 0.f);
            }
            const int r1 = row0 + mt * 16;
            const int r2 = r1 + 8;
            if (OUT == 0) {
                if (r1 < M) *(float2*)&Cf[(size_t)r1 * 256 + c] = make_float2(v0, v1);
                if (r2 < M) *(float2*)&Cf[(size_t)r2 * 256 + c] = make_float2(v2, v3);
            } else {
                __nv_bfloat162 h1, h2;
                h1.x = __float2bfloat16(v0); h1.y = __float2bfloat16(v1);
                h2.x = __float2bfloat16(v2); h2.y = __float2bfloat16(v3);
                if (r1 < M) *(__nv_bfloat162*)&Ch[(size_t)r1 * 256 + c] = h1;
                if (r2 < M) *(__nv_bfloat162*)&Ch[(size_t)r2 * 256 + c] = h2;
                if (OUT == 1) {
                    __nv_bfloat162 l1, l2;
                    l1.x = __float2bfloat16(v0 - __bfloat162float(h1.x));
                    l1.y = __float2bfloat16(v1 - __bfloat162float(h1.y));
                    l2.x = __float2bfloat16(v2 - __bfloat162float(h2.x));
                    l2.y = __float2bfloat16(v3 - __bfloat162float(h2.y));
                    if (r1 < M) *(__nv_bfloat162*)&Cl[(size_t)r1 * 256 + c] = l1;
                    if (r2 < M) *(__nv_bfloat162*)&Cl[(size_t)r2 * 256 + c] = l2;
                }
            }
        }
}

// ===========================================================================
// mix kernel (HMMA, unchanged from R3): T = EF @ (Wm3h+Wm3l)^T, fused
// epilogue: relu(T + A1[idxn] + A2[seg] + bm), warp seg-reduce, atomicAdd
// ===========================================================================
#define STAGE_BYTES 49152
#define OFF_BH      16384
#define OFF_BL      32768
#define EPI_STRIDE  132
#define MIX_SMEM    (2 * STAGE_BYTES)

__device__ __forceinline__ void mix_load_stage(
    uint32_t sbase, int buf, int kc, int rowBase, int colBase,
    const __nv_bfloat16* EFh, const __nv_bfloat16* Bh, const __nv_bfloat16* Bl,
    int tid)
{
    const uint32_t st = sbase + buf * STAGE_BYTES;
    const int kBase = kc * 64;
#pragma unroll
    for (int l = 0; l < 4; ++l) {
        int idx = tid + l * 256;
        int r = idx >> 3, cc = idx & 7;
        const char* src = (const char*)(EFh + (size_t)(rowBase + r) * 256 + kBase) + cc * 16;
        CP_ASYNC16(st + SW128((uint32_t)(r * 128 + cc * 16)), src);
    }
#pragma unroll
    for (int l = 0; l < 4; ++l) {
        int idx = tid + l * 256;
        int r = idx >> 3, cc = idx & 7;
        uint32_t doff = SW128((uint32_t)(r * 128 + cc * 16));
        const char* sh = (const char*)(Bh + (size_t)(colBase + r) * 256 + kBase) + cc * 16;
        const char* sl = (const char*)(Bl + (size_t)(colBase + r) * 256 + kBase) + cc * 16;
        CP_ASYNC16(st + OFF_BH + doff, sh);
        CP_ASYNC16(st + OFF_BL + doff, sl);
    }
}

__global__ __launch_bounds__(256)
void mix_mma_kernel(const __nv_bfloat16* __restrict__ EFh,
                    const __nv_bfloat16* __restrict__ Bh,
                    const __nv_bfloat16* __restrict__ Bl,
                    const float* __restrict__ bm,
                    const float* __restrict__ A1, const float* __restrict__ A2,
                    const int* __restrict__ idxn, const int* __restrict__ seg)
{
    extern __shared__ char smem[];
    const uint32_t sbase = smem_u32(smem);
    const int tid = threadIdx.x;
    const int wid = tid >> 5;
    const int lane = tid & 31;
    const int rowBase = blockIdx.x * 128;
    const int colBase = blockIdx.y * 128;

    const int wm = wid >> 2;
    const int wn = wid & 3;
    const int lr = lane & 15;
    const int lc = lane >> 4;

    float acc[4][4][4];
#pragma unroll
    for (int mt = 0; mt < 4; ++mt)
#pragma unroll
        for (int nt = 0; nt < 4; ++nt)
#pragma unroll
            for (int q = 0; q < 4; ++q) acc[mt][nt][q] = 0.f;

    mix_load_stage(sbase, 0, 0, rowBase, colBase, EFh, Bh, Bl, tid);
    CP_COMMIT();

    for (int kc = 0; kc < 4; ++kc) {
        if (kc < 3) {
            mix_load_stage(sbase, (kc + 1) & 1, kc + 1, rowBase, colBase, EFh, Bh, Bl, tid);
            CP_COMMIT();
            CP_WAIT(1);
        } else {
            CP_WAIT(0);
        }
        __syncthreads();

        const uint32_t st = sbase + (kc & 1) * STAGE_BYTES;
#pragma unroll
        for (int k16 = 0; k16 < 4; ++k16) {
            const uint32_t kOff = k16 * 32 + lc * 16;
            uint32_t a[4][4];
#pragma unroll
            for (int mt = 0; mt < 4; ++mt) {
                int row = wm * 64 + mt * 16 + lr;
                LDSM_X4(a[mt][0], a[mt][1], a[mt][2], a[mt][3],
                        st + SW128((uint32_t)(row * 128) + kOff));
            }
            uint32_t bh[2][4], bl[2][4];
#pragma unroll
            for (int ng = 0; ng < 2; ++ng) {
                int row = wn * 32 + ng * 16 + lr;
                uint32_t off = SW128((uint32_t)(row * 128) + kOff);
                LDSM_X4(bh[ng][0], bh[ng][1], bh[ng][2], bh[ng][3], st + OFF_BH + off);
                LDSM_X4(bl[ng][0], bl[ng][1], bl[ng][2], bl[ng][3], st + OFF_BL + off);
            }
#pragma unroll
            for (int mt = 0; mt < 4; ++mt)
#pragma unroll
                for (int nt = 0; nt < 4; ++nt) {
                    const int ng = nt >> 1, s = nt & 1;
                    MMA_BF16(acc[mt][nt], a[mt], bh[ng][s], bh[ng][s + 2]);
                    MMA_BF16(acc[mt][nt], a[mt], bl[ng][s], bl[ng][s + 2]);
                }
        }
        __syncthreads();
    }

    float* sC = (float*)smem;
    {
        const int r0 = wm * 64 + (lane >> 2);
        const int c0 = wn * 32 + (lane & 3) * 2;
#pragma unroll
        for (int mt = 0; mt < 4; ++mt)
#pragma unroll
            for (int nt = 0; nt < 4; ++nt) {
                int rr = r0 + mt * 16;
                int cc = c0 + nt * 8;
                *(float2*)&sC[rr * EPI_STRIDE + cc] =
                    make_float2(acc[mt][nt][0], acc[mt][nt][1]);
                *(float2*)&sC[(rr + 8) * EPI_STRIDE + cc] =
                    make_float2(acc[mt][nt][2], acc[mt][nt][3]);
            }
    }
    __syncthreads();

    const int wrow = (wid & 3) * 32 + lane;
    const int e = rowBase + wrow;
    const int i1 = idxn[e];
    const int i2 = seg[e];
    const int ch = (wid >> 2) * 64;

    int prevseg = __shfl_up_sync(0xFFFFFFFFu, i2, 1);
    bool head = (lane == 0) || (prevseg != i2);
    unsigned hm = __ballot_sync(0xFFFFFFFFu, head);
    unsigned rest = (lane < 31) ? (hm & (0xFFFFFFFEu << lane)) : 0u;
    int e_end = rest ? (__ffs(rest) - 2) : 31;
    float* srow = &g_sum[(size_t)i2 * 256 + colBase];
    const float* a1row = &A1[(size_t)i1 * 256 + colBase];
    const float* a2row = &A2[(size_t)i2 * 256 + colBase];

#pragma unroll
    for (int g = 0; g < 16; ++g) {
        const int cb = ch + g * 4;
        float4 t  = *(const float4*)&sC[wrow * EPI_STRIDE + cb];
        float4 a1 = *(const float4*)&a1row[cb];
        float4 a2 = *(const float4*)&a2row[cb];
        float4 bv = *(const float4*)&bm[colBase + cb];
        float v[4];
        v[0] = fmaxf(t.x + a1.x + a2.x + bv.x, 0.f);
        v[1] = fmaxf(t.y + a1.y + a2.y + bv.y, 0.f);
        v[2] = fmaxf(t.z + a1.z + a2.z + bv.z, 0.f);
        v[3] = fmaxf(t.w + a1.w + a2.w + bv.w, 0.f);
#pragma unroll
        for (int j = 0; j < 4; ++j) {
            float x = v[j];
#pragma unroll
            for (int d2 = 1; d2 < 32; d2 <<= 1) {
                float o = __shfl_down_sync(0xFFFFFFFFu, x, d2);
                if (lane + d2 <= e_end) x += o;
            }
            if (head) atomicAdd(&srow[cb + j], x);
        }
    }
}

// ---------------- prep + small kernels ------------------------------------
__global__ void prep_weights(const float* __restrict__ Wn,
                             const float* __restrict__ Wm,
                             const float* __restrict__ We)
{
    int idx = blockIdx.x * blockDim.x + threadIdx.x;  // 65536
    int n = idx >> 8, k = idx & 255;

    float w0 = Wn[k * 256 + n];
    float w1 = Wm[k * 256 + n];
    float w2 = Wm[(256 + k) * 256 + n];
    float w3 = Wm[(512 + k) * 256 + n];
    __nv_bfloat16 h;
    h = __float2bfloat16(w0); g_wnt_h[n * 256 + k] = h;
    g_wnt_l[n * 256 + k] = __float2bfloat16(w0 - __bfloat162float(h));
    h = __float2bfloat16(w1); g_wm1t_h[n * 256 + k] = h;
    g_wm1t_l[n * 256 + k] = __float2bfloat16(w1 - __bfloat162float(h));
    h = __float2bfloat16(w2); g_wm2t_h[n * 256 + k] = h;
    g_wm2t_l[n * 256 + k] = __float2bfloat16(w2 - __bfloat162float(h));
    h = __float2bfloat16(w3); g_wm3t_h[n * 256 + k] = h;
    g_wm3t_l[n * 256 + k] = __float2bfloat16(w3 - __bfloat162float(h));

    if (k < 64) {
        float we = (k < 32) ? We[k * 256 + n] : 0.f;
        h = __float2bfloat16(we);
        g_wet_h[n * 64 + k] = h;
        g_wet_l[n * 64 + k] = __float2bfloat16(we - __bfloat162float(h));
    }
}

__global__ void prep_input(const float* __restrict__ input)
{
    int i = blockIdx.x * blockDim.x + threadIdx.x;
    if (i < NN * D) {
        float v = input[i];
        __nv_bfloat16 h = __float2bfloat16(v);
        g_in_h[i] = h;
        g_in_l[i] = __float2bfloat16(v - __bfloat162float(h));
    }
}

__global__ void prep_ef(const float* __restrict__ edgefeats)
{
    size_t i = (size_t)blockIdx.x * blockDim.x + threadIdx.x;
    if (i < (size_t)NE * 64) {
        int e = (int)(i >> 6), k = (int)(i & 63);
        float v = (k < 32) ? edgefeats[(size_t)e * 32 + k] : 0.f;
        g_efin[i] = __float2bfloat16(v);
    }
}

__global__ void zero_kernel()
{
    int i = blockIdx.x * blockDim.x + threadIdx.x;
    if (i < NN * D) g_sum[i] = 0.f;
    if (i < NN)     g_cnt[i] = 0;
}

__global__ void cnt_kernel(const int* __restrict__ seg)
{
    int i = blockIdx.x * blockDim.x + threadIdx.x;
    if (i < NE) atomicAdd(&g_cnt[seg[i]], 1);
}

__global__ void final_kernel(float* __restrict__ out)
{
    int i = blockIdx.x * blockDim.x + threadIdx.x;
    if (i < NN * D) {
        int n = i >> 8;
        int c = g_cnt[n];
        out[i] = (c > 0) ? g_sum[i] / (float)c : 0.f;
    }
}

// ===========================================================================
extern "C" void kernel_launch(void* const* d_in, const int* in_sizes, int n_in,
                              void* d_out, int out_size)
{
    const float* input     = (const float*)d_in[0];
    const float* edgefeats = (const float*)d_in[1];
    const int*   idxn      = (const int*)  d_in[2];
    const int*   seg_ids   = (const int*)  d_in[3];
    const float* Wn        = (const float*)d_in[4];
    const float* bn        = (const float*)d_in[5];
    const float* We        = (const float*)d_in[6];
    const float* be        = (const float*)d_in[7];
    const float* Wm        = (const float*)d_in[8];
    const float* bm        = (const float*)d_in[9];
    float* out = (float*)d_out;

    float *p_A1, *p_A2;
    __nv_bfloat16 *p_inh, *p_inl, *p_nfh, *p_nfl, *p_efin, *p_efh;
    __nv_bfloat16 *p_wnth, *p_wntl, *p_w1h, *p_w1l, *p_w2h, *p_w2l, *p_w3h, *p_w3l;
    __nv_bfloat16 *p_weh, *p_wel;
    cudaGetSymbolAddress((void**)&p_A1, g_A1);
    cudaGetSymbolAddress((void**)&p_A2, g_A2);
    cudaGetSymbolAddress((void**)&p_inh, g_in_h);
    cudaGetSymbolAddress((void**)&p_inl, g_in_l);
    cudaGetSymbolAddress((void**)&p_nfh, g_nf_h);
    cudaGetSymbolAddress((void**)&p_nfl, g_nf_l);
    cudaGetSymbolAddress((void**)&p_efin, g_efin);
    cudaGetSymbolAddress((void**)&p_efh, g_efh);
    cudaGetSymbolAddress((void**)&p_wnth, g_wnt_h);
    cudaGetSymbolAddress((void**)&p_wntl, g_wnt_l);
    cudaGetSymbolAddress((void**)&p_w1h, g_wm1t_h);
    cudaGetSymbolAddress((void**)&p_w1l, g_wm1t_l);
    cudaGetSymbolAddress((void**)&p_w2h, g_wm2t_h);
    cudaGetSymbolAddress((void**)&p_w2l, g_wm2t_l);
    cudaGetSymbolAddress((void**)&p_w3h, g_wm3t_h);
    cudaGetSymbolAddress((void**)&p_w3l, g_wm3t_l);
    cudaGetSymbolAddress((void**)&p_weh, g_wet_h);
    cudaGetSymbolAddress((void**)&p_wel, g_wet_l);

    cudaFuncSetAttribute(mix_mma_kernel,
                         cudaFuncAttributeMaxDynamicSharedMemorySize, MIX_SMEM);
    cudaFuncSetAttribute(hmma_gemm<256, 3, true, 1>,
                         cudaFuncAttributeMaxDynamicSharedMemorySize, 131072);
    cudaFuncSetAttribute(hmma_gemm<256, 3, false, 0>,
                         cudaFuncAttributeMaxDynamicSharedMemorySize, 131072);
    cudaFuncSetAttribute(hmma_gemm<64, 2, true, 2>,
                         cudaFuncAttributeMaxDynamicSharedMemorySize, 49152);

    zero_kernel<<<(NN * D + 255) / 256, 256>>>();
    cnt_kernel<<<(NE + 255) / 256, 256>>>(seg_ids);
    prep_weights<<<256, 256>>>(Wn, Wm, We);
    prep_input<<<(NN * D + 255) / 256, 256>>>(input);
    prep_ef<<<(int)(((size_t)NE * 64 + 255) / 256), 256>>>(edgefeats);

    // nf = relu(input @ Wn + bn) -> bf16 hi/lo
    {
        dim3 g((NN + 127) / 128, 2);
        hmma_gemm<256, 3, true, 1><<<g, 256, 131072>>>(
            p_inh, p_inl, p_wnth, p_wntl, bn, nullptr, p_nfh, p_nfl, NN);
        // A1 = nf @ Wm1, A2 = nf @ Wm2 (fp32 out)
        hmma_gemm<256, 3, false, 0><<<g, 256, 131072>>>(
            p_nfh, p_nfl, p_w1h, p_w1l, nullptr, p_A1, nullptr, nullptr, NN);
        hmma_gemm<256, 3, false, 0><<<g, 256, 131072>>>(
            p_nfh, p_nfl, p_w2h, p_w2l, nullptr, p_A2, nullptr, nullptr, NN);
    }
    // ef = relu(edgefeats @ We + be) -> bf16 hi
    {
        dim3 g(NE / 128, 2);
        hmma_gemm<64, 2, true, 2><<<g, 256, 49152>>>(
            p_efin, nullptr, p_weh, p_wel, be, nullptr, p_efh, nullptr, NE);
    }
    // mix
    {
        dim3 g(NE / 128, 2);
        mix_mma_kernel<<<g, 256, MIX_SMEM>>>(p_efh, p_w3h, p_w3l, bm,
                                             p_A1, p_A2, idxn, seg_ids);
    }
    final_kernel<<<(NN * D + 255) / 256, 256>>>(out);
}

// round 6
// speedup vs baseline: 1.7077x; 1.0730x over previous
#include <cuda_runtime.h>
#include <cuda_bf16.h>
#include <cstdint>

#define NN 10000
#define NE 320000
#define D  256

// ---------------- scratch (device globals; no allocation allowed) ----------
__device__ __align__(256) float g_A1[NN * D];
__device__ __align__(256) float g_A2[NN * D];
__device__ __align__(256) float g_sum[NN * D];
__device__ int g_cnt[NN];

__device__ __align__(256) __nv_bfloat16 g_in_h[NN * D];
__device__ __align__(256) __nv_bfloat16 g_in_l[NN * D];
__device__ __align__(256) __nv_bfloat16 g_nf_h[NN * D];
__device__ __align__(256) __nv_bfloat16 g_nf_l[NN * D];
__device__ __align__(256) __nv_bfloat16 g_efin[(size_t)NE * 64];   // padded K=64

__device__ __align__(256) __nv_bfloat16 g_wnt_h[D * D],  g_wnt_l[D * D];
__device__ __align__(256) __nv_bfloat16 g_wm1t_h[D * D], g_wm1t_l[D * D];
__device__ __align__(256) __nv_bfloat16 g_wm2t_h[D * D], g_wm2t_l[D * D];
__device__ __align__(256) __nv_bfloat16 g_wm3t_h[D * D], g_wm3t_l[D * D];
__device__ __align__(256) __nv_bfloat16 g_wet_h[D * 64], g_wet_l[D * 64];

// =============================== PTX helpers ===============================
__device__ __forceinline__ uint32_t smem_u32(const void* p) {
    uint32_t a;
    asm("{ .reg .u64 t; cvta.to.shared.u64 t, %1; cvt.u32.u64 %0, t; }"
        : "=r"(a) : "l"(p));
    return a;
}
#define SW128(off) ((off) ^ (((off) >> 3) & 0x70))

#define CP_ASYNC16(dst, src) \
    asm volatile("cp.async.cg.shared.global [%0], [%1], 16;" \
        :: "r"(dst), "l"(src) : "memory")
#define CP_ASYNC16Z(dst, src, sz) \
    asm volatile("cp.async.cg.shared.global [%0], [%1], 16, %2;" \
        :: "r"(dst), "l"(src), "r"(sz) : "memory")
#define CP_COMMIT() asm volatile("cp.async.commit_group;" ::: "memory")
#define CP_WAIT(n)  asm volatile("cp.async.wait_group %0;" :: "n"(n) : "memory")

#define LDSM_X4(r0, r1, r2, r3, addr) \
    asm volatile("ldmatrix.sync.aligned.m8n8.x4.shared.b16 {%0,%1,%2,%3}, [%4];" \
        : "=r"(r0), "=r"(r1), "=r"(r2), "=r"(r3) : "r"(addr))

#define MMA_BF16(c, a, b0, b1) \
    asm volatile("mma.sync.aligned.m16n8k16.row.col.f32.bf16.bf16.f32 " \
        "{%0,%1,%2,%3}, {%4,%5,%6,%7}, {%8,%9}, {%0,%1,%2,%3};" \
        : "+f"((c)[0]), "+f"((c)[1]), "+f"((c)[2]), "+f"((c)[3]) \
        : "r"((a)[0]), "r"((a)[1]), "r"((a)[2]), "r"((a)[3]), "r"(b0), "r"(b1))

// ===========================================================================
// Unified HMMA GEMM for node-side (unchanged, proven): C[M,256]
// ===========================================================================
template<int KDIM, int NPASS, bool RELU, int OUT>
__global__ __launch_bounds__(256)
void hmma_gemm(const __nv_bfloat16* __restrict__ Ah,
               const __nv_bfloat16* __restrict__ Al,
               const __nv_bfloat16* __restrict__ Bh_,
               const __nv_bfloat16* __restrict__ Bl_,
               const float* __restrict__ bias,
               float* __restrict__ Cf,
               __nv_bfloat16* __restrict__ Ch,
               __nv_bfloat16* __restrict__ Cl,
               int M)
{
    constexpr int OFF_AL2 = 16384;
    constexpr int OFF_BH2 = (NPASS == 3) ? 32768 : 16384;
    constexpr int OFF_BL2 = OFF_BH2 + 16384;
    constexpr int SBYTES  = OFF_BL2 + 16384;
    constexpr int NKC     = KDIM / 64;

    extern __shared__ char smem[];
    const uint32_t sbase = smem_u32(smem);
    const int tid = threadIdx.x;
    const int wid = tid >> 5;
    const int lane = tid & 31;
    const int rowBase = blockIdx.x * 128;
    const int colBase = blockIdx.y * 128;

    const int wm = wid >> 2;
    const int wn = wid & 3;
    const int lr = lane & 15;
    const int lc = lane >> 4;

    float acc[4][4][4];
#pragma unroll
    for (int mt = 0; mt < 4; ++mt)
#pragma unroll
        for (int nt = 0; nt < 4; ++nt)
#pragma unroll
            for (int q = 0; q < 4; ++q) acc[mt][nt][q] = 0.f;

    auto load_stage = [&](int buf, int kc) {
        const uint32_t st = sbase + buf * SBYTES;
        const int kBase = kc * 64;
#pragma unroll
        for (int l = 0; l < 4; ++l) {
            int idx = tid + l * 256;
            int r = idx >> 3, cc = idx & 7;
            int gr = rowBase + r;
            uint32_t sz = (gr < M) ? 16u : 0u;
            int grc = (gr < M) ? gr : (M - 1);
            uint32_t doff = SW128((uint32_t)(r * 128 + cc * 16));
            const char* sh = (const char*)(Ah + (size_t)grc * KDIM + kBase) + cc * 16;
            CP_ASYNC16Z(st + doff, sh, sz);
            if (NPASS == 3) {
                const char* sl = (const char*)(Al + (size_t)grc * KDIM + kBase) + cc * 16;
                CP_ASYNC16Z(st + OFF_AL2 + doff, sl, sz);
            }
        }
#pragma unroll
        for (int l = 0; l < 4; ++l) {
            int idx = tid + l * 256;
            int r = idx >> 3, cc = idx & 7;
            uint32_t doff = SW128((uint32_t)(r * 128 + cc * 16));
            const char* sh = (const char*)(Bh_ + (size_t)(colBase + r) * KDIM + kBase) + cc * 16;
            const char* sl = (const char*)(Bl_ + (size_t)(colBase + r) * KDIM + kBase) + cc * 16;
            CP_ASYNC16(st + OFF_BH2 + doff, sh);
            CP_ASYNC16(st + OFF_BL2 + doff, sl);
        }
    };

    load_stage(0, 0);
    CP_COMMIT();

    for (int kc = 0; kc < NKC; ++kc) {
        if (kc + 1 < NKC) {
            load_stage((kc + 1) & 1, kc + 1);
            CP_COMMIT();
            CP_WAIT(1);
        } else {
            CP_WAIT(0);
        }
        __syncthreads();

        const uint32_t st = sbase + (kc & 1) * SBYTES;
#pragma unroll
        for (int k16 = 0; k16 < 4; ++k16) {
            const uint32_t kOff = k16 * 32 + lc * 16;
            uint32_t ah[4][4], al[4][4];
#pragma unroll
            for (int mt = 0; mt < 4; ++mt) {
                int row = wm * 64 + mt * 16 + lr;
                uint32_t off = SW128((uint32_t)(row * 128) + kOff);
                LDSM_X4(ah[mt][0], ah[mt][1], ah[mt][2], ah[mt][3], st + off);
                if (NPASS == 3)
                    LDSM_X4(al[mt][0], al[mt][1], al[mt][2], al[mt][3],
                            st + OFF_AL2 + off);
            }
            uint32_t bh[2][4], bl[2][4];
#pragma unroll
            for (int ng = 0; ng < 2; ++ng) {
                int row = wn * 32 + ng * 16 + lr;
                uint32_t off = SW128((uint32_t)(row * 128) + kOff);
                LDSM_X4(bh[ng][0], bh[ng][1], bh[ng][2], bh[ng][3], st + OFF_BH2 + off);
                LDSM_X4(bl[ng][0], bl[ng][1], bl[ng][2], bl[ng][3], st + OFF_BL2 + off);
            }
#pragma unroll
            for (int mt = 0; mt < 4; ++mt)
#pragma unroll
                for (int nt = 0; nt < 4; ++nt) {
                    const int ng = nt >> 1, s = nt & 1;
                    MMA_BF16(acc[mt][nt], ah[mt], bh[ng][s], bh[ng][s + 2]);
                    MMA_BF16(acc[mt][nt], ah[mt], bl[ng][s], bl[ng][s + 2]);
                    if (NPASS == 3)
                        MMA_BF16(acc[mt][nt], al[mt], bh[ng][s], bh[ng][s + 2]);
                }
        }
        __syncthreads();
    }

    const int row0 = rowBase + wm * 64 + (lane >> 2);
    const int col0 = colBase + wn * 32 + ((lane & 3) << 1);
#pragma unroll
    for (int mt = 0; mt < 4; ++mt)
#pragma unroll
        for (int nt = 0; nt < 4; ++nt) {
            const int c = col0 + nt * 8;
            float v0 = acc[mt][nt][0], v1 = acc[mt][nt][1];
            float v2 = acc[mt][nt][2], v3 = acc[mt][nt][3];
            if (RELU) {
                float2 bb = *(const float2*)&bias[c];
                v0 = fmaxf(v0 + bb.x, 0.f); v1 = fmaxf(v1 + bb.y, 0.f);
                v2 = fmaxf(v2 + bb.x, 0.f); v3 = fmaxf(v3 + bb.y, 0.f);
            }
            const int r1 = row0 + mt * 16;
            const int r2 = r1 + 8;
            if (OUT == 0) {
                if (r1 < M) *(float2*)&Cf[(size_t)r1 * 256 + c] = make_float2(v0, v1);
                if (r2 < M) *(float2*)&Cf[(size_t)r2 * 256 + c] = make_float2(v2, v3);
            } else {
                __nv_bfloat162 h1, h2;
                h1.x = __float2bfloat16(v0); h1.y = __float2bfloat16(v1);
                h2.x = __float2bfloat16(v2); h2.y = __float2bfloat16(v3);
                if (r1 < M) *(__nv_bfloat162*)&Ch[(size_t)r1 * 256 + c] = h1;
                if (r2 < M) *(__nv_bfloat162*)&Ch[(size_t)r2 * 256 + c] = h2;
                if (OUT == 1) {
                    __nv_bfloat162 l1, l2;
                    l1.x = __float2bfloat16(v0 - __bfloat162float(h1.x));
                    l1.y = __float2bfloat16(v1 - __bfloat162float(h1.y));
                    l2.x = __float2bfloat16(v2 - __bfloat162float(h2.x));
                    l2.y = __float2bfloat16(v3 - __bfloat162float(h2.y));
                    if (r1 < M) *(__nv_bfloat162*)&Cl[(size_t)r1 * 256 + c] = l1;
                    if (r2 < M) *(__nv_bfloat162*)&Cl[(size_t)r2 * 256 + c] = l2;
                }
            }
        }
}

// ===========================================================================
// FUSED mix kernel: per CTA of 128 edges
//   stage 1: EF = relu(efin@We + be)  (HMMA, 2-pass We hi/lo) -> smem bf16
//   stage 2: T = EF @ Wm3^T (2-pass hi/lo), N=256
//   epilogue: relu(T + A1[idxn] + A2[seg] + bm), warp seg-reduce, atomicAdd
// smem: EF 64KB (4 K-chunks of [128x64]) + 2 weight stages of 64KB = 192KB
// ===========================================================================
#define EF_CHUNK  16384
#define S_BASE    65536
#define S_SIZE    65536
#define S_BL      32768
#define MIX_SMEM  196608
#define EPI_STRIDE 260

__global__ __launch_bounds__(256)
void mix_fused_kernel(const __nv_bfloat16* __restrict__ EFin,
                      const __nv_bfloat16* __restrict__ Weh,
                      const __nv_bfloat16* __restrict__ Wel,
                      const float* __restrict__ be,
                      const __nv_bfloat16* __restrict__ W3h,
                      const __nv_bfloat16* __restrict__ W3l,
                      const float* __restrict__ bm,
                      const float* __restrict__ A1, const float* __restrict__ A2,
                      const int* __restrict__ idxn, const int* __restrict__ seg)
{
    extern __shared__ char smem[];
    const uint32_t sbase = smem_u32(smem);
    const int tid = threadIdx.x;
    const int wid = tid >> 5;
    const int lane = tid & 31;
    const int rowBase = blockIdx.x * 128;

    const int wm = wid >> 2;       // 0..1 (64-row band)
    const int wn = wid & 3;        // 0..3 (64-col band)
    const int lr = lane & 15;
    const int lc = lane >> 4;

    float acc[4][8][4];
#pragma unroll
    for (int mt = 0; mt < 4; ++mt)
#pragma unroll
        for (int nt = 0; nt < 8; ++nt)
#pragma unroll
            for (int q = 0; q < 4; ++q) acc[mt][nt][q] = 0.f;

    // ---- prologue loads: efin tile + We hi/lo ----
#pragma unroll
    for (int l = 0; l < 4; ++l) {          // efin: 128 rows x 128B
        int idx = tid + l * 256;
        int r = idx >> 3, cc = idx & 7;
        const char* src = (const char*)(EFin + (size_t)(rowBase + r) * 64) + cc * 16;
        CP_ASYNC16(sbase + S_BASE + SW128((uint32_t)(r * 128 + cc * 16)), src);
    }
#pragma unroll
    for (int l = 0; l < 8; ++l) {          // Weh/Wel: 256 rows x 128B each
        int idx = tid + l * 256;
        int r = idx >> 3, cc = idx & 7;
        uint32_t off = SW128((uint32_t)(r * 128 + cc * 16));
        CP_ASYNC16(sbase + S_BASE + S_BL + off,
                   (const char*)(Weh + (size_t)r * 64) + cc * 16);
        CP_ASYNC16(sbase + S_BASE + S_SIZE + off,
                   (const char*)(Wel + (size_t)r * 64) + cc * 16);
    }
    CP_COMMIT();
    CP_WAIT(0);
    __syncthreads();

    // ---- stage 1: EF MMA (K=64) ----
    {
        const uint32_t stA  = sbase + S_BASE;
        const uint32_t stBh = sbase + S_BASE + S_BL;
        const uint32_t stBl = sbase + S_BASE + S_SIZE;
#pragma unroll
        for (int k16 = 0; k16 < 4; ++k16) {
            const uint32_t kOff = k16 * 32 + lc * 16;
            uint32_t a[4][4];
#pragma unroll
            for (int mt = 0; mt < 4; ++mt) {
                int row = wm * 64 + mt * 16 + lr;
                LDSM_X4(a[mt][0], a[mt][1], a[mt][2], a[mt][3],
                        stA + SW128((uint32_t)(row * 128) + kOff));
            }
            uint32_t bh[4][4], bl[4][4];
#pragma unroll
            for (int ng = 0; ng < 4; ++ng) {
                int row = wn * 64 + ng * 16 + lr;
                uint32_t off = SW128((uint32_t)(row * 128) + kOff);
                LDSM_X4(bh[ng][0], bh[ng][1], bh[ng][2], bh[ng][3], stBh + off);
                LDSM_X4(bl[ng][0], bl[ng][1], bl[ng][2], bl[ng][3], stBl + off);
            }
#pragma unroll
            for (int mt = 0; mt < 4; ++mt)
#pragma unroll
                for (int nt = 0; nt < 8; ++nt) {
                    const int ng = nt >> 1, s = nt & 1;
                    MMA_BF16(acc[mt][nt], a[mt], bh[ng][s], bh[ng][s + 2]);
                    MMA_BF16(acc[mt][nt], a[mt], bl[ng][s], bl[ng][s + 2]);
                }
        }
    }
    __syncthreads();   // all LDSM reads of prologue buffers done

    // ---- bias + relu + store EF bf16 into smem chunks, zero acc ----
    {
        const int r0 = wm * 64 + (lane >> 2);
        const int c0 = wn * 64 + ((lane & 3) << 1);
#pragma unroll
        for (int mt = 0; mt < 4; ++mt)
#pragma unroll
            for (int nt = 0; nt < 8; ++nt) {
                const int c = c0 + nt * 8;
                float2 bb = *(const float2*)&be[c];
                float v0 = fmaxf(acc[mt][nt][0] + bb.x, 0.f);
                float v1 = fmaxf(acc[mt][nt][1] + bb.y, 0.f);
                float v2 = fmaxf(acc[mt][nt][2] + bb.x, 0.f);
                float v3 = fmaxf(acc[mt][nt][3] + bb.y, 0.f);
                __nv_bfloat162 p1, p2;
                p1.x = __float2bfloat16(v0); p1.y = __float2bfloat16(v1);
                p2.x = __float2bfloat16(v2); p2.y = __float2bfloat16(v3);
                const int chunk = c >> 6, cl2 = (c & 63) * 2;
                const int r1 = r0 + mt * 16, r2 = r1 + 8;
                *(__nv_bfloat162*)(smem + chunk * EF_CHUNK +
                    SW128((uint32_t)(r1 * 128 + cl2))) = p1;
                *(__nv_bfloat162*)(smem + chunk * EF_CHUNK +
                    SW128((uint32_t)(r2 * 128 + cl2))) = p2;
                acc[mt][nt][0] = 0.f; acc[mt][nt][1] = 0.f;
                acc[mt][nt][2] = 0.f; acc[mt][nt][3] = 0.f;
            }
    }
    __syncthreads();   // EF visible; prologue buffers free for reuse

    // ---- stage 2: main loop, A from smem EF chunks, B = Wm3 h/l staged ----
    auto load_wstage = [&](int buf, int kc) {
        const uint32_t st = sbase + S_BASE + buf * S_SIZE;
        const int kBase = kc * 64;
#pragma unroll
        for (int l = 0; l < 8; ++l) {
            int idx = tid + l * 256;
            int r = idx >> 3, cc = idx & 7;
            uint32_t off = SW128((uint32_t)(r * 128 + cc * 16));
            CP_ASYNC16(st + off,        (const char*)(W3h + (size_t)r * 256 + kBase) + cc * 16);
            CP_ASYNC16(st + S_BL + off, (const char*)(W3l + (size_t)r * 256 + kBase) + cc * 16);
        }
    };

    load_wstage(0, 0);
    CP_COMMIT();

    for (int kc = 0; kc < 4; ++kc) {
        if (kc < 3) {
            load_wstage((kc + 1) & 1, kc + 1);
            CP_COMMIT();
            CP_WAIT(1);
        } else {
            CP_WAIT(0);
        }
        __syncthreads();

        const uint32_t stA = sbase + kc * EF_CHUNK;
        const uint32_t stB = sbase + S_BASE + (kc & 1) * S_SIZE;
#pragma unroll
        for (int k16 = 0; k16 < 4; ++k16) {
            const uint32_t kOff = k16 * 32 + lc * 16;
            uint32_t a[4][4];
#pragma unroll
            for (int mt = 0; mt < 4; ++mt) {
                int row = wm * 64 + mt * 16 + lr;
                LDSM_X4(a[mt][0], a[mt][1], a[mt][2], a[mt][3],
                        stA + SW128((uint32_t)(row * 128) + kOff));
            }
            uint32_t bh[4][4], bl[4][4];
#pragma unroll
            for (int ng = 0; ng < 4; ++ng) {
                int row = wn * 64 + ng * 16 + lr;
                uint32_t off = SW128((uint32_t)(row * 128) + kOff);
                LDSM_X4(bh[ng][0], bh[ng][1], bh[ng][2], bh[ng][3], stB + off);
                LDSM_X4(bl[ng][0], bl[ng][1], bl[ng][2], bl[ng][3], stB + S_BL + off);
            }
#pragma unroll
            for (int mt = 0; mt < 4; ++mt)
#pragma unroll
                for (int nt = 0; nt < 8; ++nt) {
                    const int ng = nt >> 1, s = nt & 1;
                    MMA_BF16(acc[mt][nt], a[mt], bh[ng][s], bh[ng][s + 2]);
                    MMA_BF16(acc[mt][nt], a[mt], bl[ng][s], bl[ng][s + 2]);
                }
        }
        __syncthreads();
    }

    // ---- fragments -> padded smem [128][EPI_STRIDE] fp32 ----
    float* sC = (float*)smem;
    {
        const int r0 = wm * 64 + (lane >> 2);
        const int c0 = wn * 64 + ((lane & 3) << 1);
#pragma unroll
        for (int mt = 0; mt < 4; ++mt)
#pragma unroll
            for (int nt = 0; nt < 8; ++nt) {
                int rr = r0 + mt * 16;
                int cc = c0 + nt * 8;
                *(float2*)&sC[rr * EPI_STRIDE + cc] =
                    make_float2(acc[mt][nt][0], acc[mt][nt][1]);
                *(float2*)&sC[(rr + 8) * EPI_STRIDE + cc] =
                    make_float2(acc[mt][nt][2], acc[mt][nt][3]);
            }
    }
    __syncthreads();

    // ---- row-oriented epilogue: lane = edge row, 128 cols per warp ----
    const int wrow = (wid & 3) * 32 + lane;
    const int e = rowBase + wrow;
    const int i1 = idxn[e];
    const int i2 = seg[e];
    const int ch = (wid >> 2) * 128;

    int prevseg = __shfl_up_sync(0xFFFFFFFFu, i2, 1);
    bool head = (lane == 0) || (prevseg != i2);
    unsigned hm = __ballot_sync(0xFFFFFFFFu, head);
    unsigned rest = (lane < 31) ? (hm & (0xFFFFFFFEu << lane)) : 0u;
    int e_end = rest ? (__ffs(rest) - 2) : 31;
    float* srow = &g_sum[(size_t)i2 * 256];
    const float* a1row = &A1[(size_t)i1 * 256];
    const float* a2row = &A2[(size_t)i2 * 256];

#pragma unroll
    for (int g = 0; g < 32; ++g) {
        const int cb = ch + g * 4;
        float4 t  = *(const float4*)&sC[wrow * EPI_STRIDE + cb];
        float4 a1 = *(const float4*)&a1row[cb];
        float4 a2 = *(const float4*)&a2row[cb];
        float4 bv = *(const float4*)&bm[cb];
        float v[4];
        v[0] = fmaxf(t.x + a1.x + a2.x + bv.x, 0.f);
        v[1] = fmaxf(t.y + a1.y + a2.y + bv.y, 0.f);
        v[2] = fmaxf(t.z + a1.z + a2.z + bv.z, 0.f);
        v[3] = fmaxf(t.w + a1.w + a2.w + bv.w, 0.f);
#pragma unroll
        for (int j = 0; j < 4; ++j) {
            float x = v[j];
#pragma unroll
            for (int d2 = 1; d2 < 32; d2 <<= 1) {
                float o = __shfl_down_sync(0xFFFFFFFFu, x, d2);
                if (lane + d2 <= e_end) x += o;
            }
            if (head) atomicAdd(&srow[cb + j], x);
        }
    }
}

// ---------------- prep + small kernels ------------------------------------
__global__ void prep_weights(const float* __restrict__ Wn,
                             const float* __restrict__ Wm,
                             const float* __restrict__ We)
{
    int idx = blockIdx.x * blockDim.x + threadIdx.x;  // 65536
    int n = idx >> 8, k = idx & 255;

    float w0 = Wn[k * 256 + n];
    float w1 = Wm[k * 256 + n];
    float w2 = Wm[(256 + k) * 256 + n];
    float w3 = Wm[(512 + k) * 256 + n];
    __nv_bfloat16 h;
    h = __float2bfloat16(w0); g_wnt_h[n * 256 + k] = h;
    g_wnt_l[n * 256 + k] = __float2bfloat16(w0 - __bfloat162float(h));
    h = __float2bfloat16(w1); g_wm1t_h[n * 256 + k] = h;
    g_wm1t_l[n * 256 + k] = __float2bfloat16(w1 - __bfloat162float(h));
    h = __float2bfloat16(w2); g_wm2t_h[n * 256 + k] = h;
    g_wm2t_l[n * 256 + k] = __float2bfloat16(w2 - __bfloat162float(h));
    h = __float2bfloat16(w3); g_wm3t_h[n * 256 + k] = h;
    g_wm3t_l[n * 256 + k] = __float2bfloat16(w3 - __bfloat162float(h));

    if (k < 64) {
        float we = (k < 32) ? We[k * 256 + n] : 0.f;
        h = __float2bfloat16(we);
        g_wet_h[n * 64 + k] = h;
        g_wet_l[n * 64 + k] = __float2bfloat16(we - __bfloat162float(h));
    }
}

__global__ void prep_input(const float* __restrict__ input)
{
    int i = blockIdx.x * blockDim.x + threadIdx.x;
    if (i < NN * D) {
        float v = input[i];
        __nv_bfloat16 h = __float2bfloat16(v);
        g_in_h[i] = h;
        g_in_l[i] = __float2bfloat16(v - __bfloat162float(h));
    }
}

__global__ void prep_ef(const float* __restrict__ edgefeats)
{
    size_t i = (size_t)blockIdx.x * blockDim.x + threadIdx.x;
    if (i < (size_t)NE * 64) {
        int e = (int)(i >> 6), k = (int)(i & 63);
        float v = (k < 32) ? edgefeats[(size_t)e * 32 + k] : 0.f;
        g_efin[i] = __float2bfloat16(v);
    }
}

__global__ void zero_kernel()
{
    int i = blockIdx.x * blockDim.x + threadIdx.x;
    if (i < NN * D) g_sum[i] = 0.f;
    if (i < NN)     g_cnt[i] = 0;
}

__global__ void cnt_kernel(const int* __restrict__ seg)
{
    int i = blockIdx.x * blockDim.x + threadIdx.x;
    if (i < NE) atomicAdd(&g_cnt[seg[i]], 1);
}

__global__ void final_kernel(float* __restrict__ out)
{
    int i = blockIdx.x * blockDim.x + threadIdx.x;
    if (i < NN * D) {
        int n = i >> 8;
        int c = g_cnt[n];
        out[i] = (c > 0) ? g_sum[i] / (float)c : 0.f;
    }
}

// ===========================================================================
extern "C" void kernel_launch(void* const* d_in, const int* in_sizes, int n_in,
                              void* d_out, int out_size)
{
    const float* input     = (const float*)d_in[0];
    const float* edgefeats = (const float*)d_in[1];
    const int*   idxn      = (const int*)  d_in[2];
    const int*   seg_ids   = (const int*)  d_in[3];
    const float* Wn        = (const float*)d_in[4];
    const float* bn        = (const float*)d_in[5];
    const float* We        = (const float*)d_in[6];
    const float* be        = (const float*)d_in[7];
    const float* Wm        = (const float*)d_in[8];
    const float* bm        = (const float*)d_in[9];
    float* out = (float*)d_out;

    float *p_A1, *p_A2;
    __nv_bfloat16 *p_inh, *p_inl, *p_nfh, *p_nfl, *p_efin;
    __nv_bfloat16 *p_wnth, *p_wntl, *p_w1h, *p_w1l, *p_w2h, *p_w2l, *p_w3h, *p_w3l;
    __nv_bfloat16 *p_weh, *p_wel;
    cudaGetSymbolAddress((void**)&p_A1, g_A1);
    cudaGetSymbolAddress((void**)&p_A2, g_A2);
    cudaGetSymbolAddress((void**)&p_inh, g_in_h);
    cudaGetSymbolAddress((void**)&p_inl, g_in_l);
    cudaGetSymbolAddress((void**)&p_nfh, g_nf_h);
    cudaGetSymbolAddress((void**)&p_nfl, g_nf_l);
    cudaGetSymbolAddress((void**)&p_efin, g_efin);
    cudaGetSymbolAddress((void**)&p_wnth, g_wnt_h);
    cudaGetSymbolAddress((void**)&p_wntl, g_wnt_l);
    cudaGetSymbolAddress((void**)&p_w1h, g_wm1t_h);
    cudaGetSymbolAddress((void**)&p_w1l, g_wm1t_l);
    cudaGetSymbolAddress((void**)&p_w2h, g_wm2t_h);
    cudaGetSymbolAddress((void**)&p_w2l, g_wm2t_l);
    cudaGetSymbolAddress((void**)&p_w3h, g_wm3t_h);
    cudaGetSymbolAddress((void**)&p_w3l, g_wm3t_l);
    cudaGetSymbolAddress((void**)&p_weh, g_wet_h);
    cudaGetSymbolAddress((void**)&p_wel, g_wet_l);

    cudaFuncSetAttribute(mix_fused_kernel,
                         cudaFuncAttributeMaxDynamicSharedMemorySize, MIX_SMEM);
    cudaFuncSetAttribute(hmma_gemm<256, 3, true, 1>,
                         cudaFuncAttributeMaxDynamicSharedMemorySize, 131072);
    cudaFuncSetAttribute(hmma_gemm<256, 3, false, 0>,
                         cudaFuncAttributeMaxDynamicSharedMemorySize, 131072);

    zero_kernel<<<(NN * D + 255) / 256, 256>>>();
    cnt_kernel<<<(NE + 255) / 256, 256>>>(seg_ids);
    prep_weights<<<256, 256>>>(Wn, Wm, We);
    prep_input<<<(NN * D + 255) / 256, 256>>>(input);
    prep_ef<<<(int)(((size_t)NE * 64 + 255) / 256), 256>>>(edgefeats);

    {
        dim3 g((NN + 127) / 128, 2);
        hmma_gemm<256, 3, true, 1><<<g, 256, 131072>>>(
            p_inh, p_inl, p_wnth, p_wntl, bn, nullptr, p_nfh, p_nfl, NN);
        hmma_gemm<256, 3, false, 0><<<g, 256, 131072>>>(
            p_nfh, p_nfl, p_w1h, p_w1l, nullptr, p_A1, nullptr, nullptr, NN);
        hmma_gemm<256, 3, false, 0><<<g, 256, 131072>>>(
            p_nfh, p_nfl, p_w2h, p_w2l, nullptr, p_A2, nullptr, nullptr, NN);
    }
    mix_fused_kernel<<<NE / 128, 256, MIX_SMEM>>>(
        p_efin, p_weh, p_wel, be, p_w3h, p_w3l, bm, p_A1, p_A2, idxn, seg_ids);

    final_kernel<<<(NN * D + 255) / 256, 256>>>(out);
}

// round 7
// speedup vs baseline: 1.7381x; 1.0178x over previous
#include <cuda_runtime.h>
#include <cuda_bf16.h>
#include <cstdint>

#define NN 10000
#define NE 320000
#define D  256

// ---------------- scratch (device globals; no allocation allowed) ----------
__device__ __align__(256) float g_A1[NN * D];
__device__ __align__(256) float g_A2[NN * D];
__device__ __align__(256) float g_sum[NN * D];   // zero-init at load; self-resetting

__device__ __align__(256) __nv_bfloat16 g_in_h[NN * D];
__device__ __align__(256) __nv_bfloat16 g_in_l[NN * D];
__device__ __align__(256) __nv_bfloat16 g_nf_h[NN * D];
__device__ __align__(256) __nv_bfloat16 g_nf_l[NN * D];

__device__ __align__(256) __nv_bfloat16 g_wnt_h[D * D],  g_wnt_l[D * D];
__device__ __align__(256) __nv_bfloat16 g_wm1t_h[D * D], g_wm1t_l[D * D];
__device__ __align__(256) __nv_bfloat16 g_wm2t_h[D * D], g_wm2t_l[D * D];
__device__ __align__(256) __nv_bfloat16 g_wm3t_h[D * D], g_wm3t_l[D * D];
__device__ __align__(256) __nv_bfloat16 g_wet_h[D * 64], g_wet_l[D * 64];

// =============================== PTX helpers ===============================
__device__ __forceinline__ uint32_t smem_u32(const void* p) {
    uint32_t a;
    asm("{ .reg .u64 t; cvta.to.shared.u64 t, %1; cvt.u32.u64 %0, t; }"
        : "=r"(a) : "l"(p));
    return a;
}
#define SW128(off) ((off) ^ (((off) >> 3) & 0x70))

#define CP_ASYNC16(dst, src) \
    asm volatile("cp.async.cg.shared.global [%0], [%1], 16;" \
        :: "r"(dst), "l"(src) : "memory")
#define CP_ASYNC16Z(dst, src, sz) \
    asm volatile("cp.async.cg.shared.global [%0], [%1], 16, %2;" \
        :: "r"(dst), "l"(src), "r"(sz) : "memory")
#define CP_COMMIT() asm volatile("cp.async.commit_group;" ::: "memory")
#define CP_WAIT(n)  asm volatile("cp.async.wait_group %0;" :: "n"(n) : "memory")

#define LDSM_X4(r0, r1, r2, r3, addr) \
    asm volatile("ldmatrix.sync.aligned.m8n8.x4.shared.b16 {%0,%1,%2,%3}, [%4];" \
        : "=r"(r0), "=r"(r1), "=r"(r2), "=r"(r3) : "r"(addr))

#define MMA_BF16(c, a, b0, b1) \
    asm volatile("mma.sync.aligned.m16n8k16.row.col.f32.bf16.bf16.f32 " \
        "{%0,%1,%2,%3}, {%4,%5,%6,%7}, {%8,%9}, {%0,%1,%2,%3};" \
        : "+f"((c)[0]), "+f"((c)[1]), "+f"((c)[2]), "+f"((c)[3]) \
        : "r"((a)[0]), "r"((a)[1]), "r"((a)[2]), "r"((a)[3]), "r"(b0), "r"(b1))

// ===========================================================================
// Unified HMMA GEMM for node-side (unchanged, proven): C[M,256]
// ===========================================================================
template<int KDIM, int NPASS, bool RELU, int OUT>
__global__ __launch_bounds__(256)
void hmma_gemm(const __nv_bfloat16* __restrict__ Ah,
               const __nv_bfloat16* __restrict__ Al,
               const __nv_bfloat16* __restrict__ Bh_,
               const __nv_bfloat16* __restrict__ Bl_,
               const float* __restrict__ bias,
               float* __restrict__ Cf,
               __nv_bfloat16* __restrict__ Ch,
               __nv_bfloat16* __restrict__ Cl,
               int M)
{
    constexpr int OFF_AL2 = 16384;
    constexpr int OFF_BH2 = (NPASS == 3) ? 32768 : 16384;
    constexpr int OFF_BL2 = OFF_BH2 + 16384;
    constexpr int SBYTES  = OFF_BL2 + 16384;
    constexpr int NKC     = KDIM / 64;

    extern __shared__ char smem[];
    const uint32_t sbase = smem_u32(smem);
    const int tid = threadIdx.x;
    const int wid = tid >> 5;
    const int lane = tid & 31;
    const int rowBase = blockIdx.x * 128;
    const int colBase = blockIdx.y * 128;

    const int wm = wid >> 2;
    const int wn = wid & 3;
    const int lr = lane & 15;
    const int lc = lane >> 4;

    float acc[4][4][4];
#pragma unroll
    for (int mt = 0; mt < 4; ++mt)
#pragma unroll
        for (int nt = 0; nt < 4; ++nt)
#pragma unroll
            for (int q = 0; q < 4; ++q) acc[mt][nt][q] = 0.f;

    auto load_stage = [&](int buf, int kc) {
        const uint32_t st = sbase + buf * SBYTES;
        const int kBase = kc * 64;
#pragma unroll
        for (int l = 0; l < 4; ++l) {
            int idx = tid + l * 256;
            int r = idx >> 3, cc = idx & 7;
            int gr = rowBase + r;
            uint32_t sz = (gr < M) ? 16u : 0u;
            int grc = (gr < M) ? gr : (M - 1);
            uint32_t doff = SW128((uint32_t)(r * 128 + cc * 16));
            const char* sh = (const char*)(Ah + (size_t)grc * KDIM + kBase) + cc * 16;
            CP_ASYNC16Z(st + doff, sh, sz);
            if (NPASS == 3) {
                const char* sl = (const char*)(Al + (size_t)grc * KDIM + kBase) + cc * 16;
                CP_ASYNC16Z(st + OFF_AL2 + doff, sl, sz);
            }
        }
#pragma unroll
        for (int l = 0; l < 4; ++l) {
            int idx = tid + l * 256;
            int r = idx >> 3, cc = idx & 7;
            uint32_t doff = SW128((uint32_t)(r * 128 + cc * 16));
            const char* sh = (const char*)(Bh_ + (size_t)(colBase + r) * KDIM + kBase) + cc * 16;
            const char* sl = (const char*)(Bl_ + (size_t)(colBase + r) * KDIM + kBase) + cc * 16;
            CP_ASYNC16(st + OFF_BH2 + doff, sh);
            CP_ASYNC16(st + OFF_BL2 + doff, sl);
        }
    };

    load_stage(0, 0);
    CP_COMMIT();

    for (int kc = 0; kc < NKC; ++kc) {
        if (kc + 1 < NKC) {
            load_stage((kc + 1) & 1, kc + 1);
            CP_COMMIT();
            CP_WAIT(1);
        } else {
            CP_WAIT(0);
        }
        __syncthreads();

        const uint32_t st = sbase + (kc & 1) * SBYTES;
#pragma unroll
        for (int k16 = 0; k16 < 4; ++k16) {
            const uint32_t kOff = k16 * 32 + lc * 16;
            uint32_t ah[4][4], al[4][4];
#pragma unroll
            for (int mt = 0; mt < 4; ++mt) {
                int row = wm * 64 + mt * 16 + lr;
                uint32_t off = SW128((uint32_t)(row * 128) + kOff);
                LDSM_X4(ah[mt][0], ah[mt][1], ah[mt][2], ah[mt][3], st + off);
                if (NPASS == 3)
                    LDSM_X4(al[mt][0], al[mt][1], al[mt][2], al[mt][3],
                            st + OFF_AL2 + off);
            }
            uint32_t bh[2][4], bl[2][4];
#pragma unroll
            for (int ng = 0; ng < 2; ++ng) {
                int row = wn * 32 + ng * 16 + lr;
                uint32_t off = SW128((uint32_t)(row * 128) + kOff);
                LDSM_X4(bh[ng][0], bh[ng][1], bh[ng][2], bh[ng][3], st + OFF_BH2 + off);
                LDSM_X4(bl[ng][0], bl[ng][1], bl[ng][2], bl[ng][3], st + OFF_BL2 + off);
            }
#pragma unroll
            for (int mt = 0; mt < 4; ++mt)
#pragma unroll
                for (int nt = 0; nt < 4; ++nt) {
                    const int ng = nt >> 1, s = nt & 1;
                    MMA_BF16(acc[mt][nt], ah[mt], bh[ng][s], bh[ng][s + 2]);
                    MMA_BF16(acc[mt][nt], ah[mt], bl[ng][s], bl[ng][s + 2]);
                    if (NPASS == 3)
                        MMA_BF16(acc[mt][nt], al[mt], bh[ng][s], bh[ng][s + 2]);
                }
        }
        __syncthreads();
    }

    const int row0 = rowBase + wm * 64 + (lane >> 2);
    const int col0 = colBase + wn * 32 + ((lane & 3) << 1);
#pragma unroll
    for (int mt = 0; mt < 4; ++mt)
#pragma unroll
        for (int nt = 0; nt < 4; ++nt) {
            const int c = col0 + nt * 8;
            float v0 = acc[mt][nt][0], v1 = acc[mt][nt][1];
            float v2 = acc[mt][nt][2], v3 = acc[mt][nt][3];
            if (RELU) {
                float2 bb = *(const float2*)&bias[c];
                v0 = fmaxf(v0 + bb.x, 0.f); v1 = fmaxf(v1 + bb.y, 0.f);
                v2 = fmaxf(v2 + bb.x, 0.f); v3 = fmaxf(v3 + bb.y, 0.f);
            }
            const int r1 = row0 + mt * 16;
            const int r2 = r1 + 8;
            if (OUT == 0) {
                if (r1 < M) *(float2*)&Cf[(size_t)r1 * 256 + c] = make_float2(v0, v1);
                if (r2 < M) *(float2*)&Cf[(size_t)r2 * 256 + c] = make_float2(v2, v3);
            } else {
                __nv_bfloat162 h1, h2;
                h1.x = __float2bfloat16(v0); h1.y = __float2bfloat16(v1);
                h2.x = __float2bfloat16(v2); h2.y = __float2bfloat16(v3);
                if (r1 < M) *(__nv_bfloat162*)&Ch[(size_t)r1 * 256 + c] = h1;
                if (r2 < M) *(__nv_bfloat162*)&Ch[(size_t)r2 * 256 + c] = h2;
                if (OUT == 1) {
                    __nv_bfloat162 l1, l2;
                    l1.x = __float2bfloat16(v0 - __bfloat162float(h1.x));
                    l1.y = __float2bfloat16(v1 - __bfloat162float(h1.y));
                    l2.x = __float2bfloat16(v2 - __bfloat162float(h2.x));
                    l2.y = __float2bfloat16(v3 - __bfloat162float(h2.y));
                    if (r1 < M) *(__nv_bfloat162*)&Cl[(size_t)r1 * 256 + c] = l1;
                    if (r2 < M) *(__nv_bfloat162*)&Cl[(size_t)r2 * 256 + c] = l2;
                }
            }
        }
}

// ===========================================================================
// FUSED mix kernel with prefetch pipeline.
// smem map (192KB):
//   [0,64K)      EF chunks 0..3 ([128x64] bf16 swizzled, chunk c at c*16K)
//                (prologue: raw fp32 edgefeats parked in chunk2 region,
//                 efin bf16 built in chunk0 region; both dead before EF store)
//   [64K,128K)   buf0: W3 stage (hi 32K + lo 32K)   kc = 0, 2
//   [128K,192K)  buf1: We hi/lo during stage1; W3 stages kc = 1, 3
// ===========================================================================
#define EF_CHUNK  16384
#define RAW_OFF   32768
#define BUF0      65536
#define BUF1      131072
#define S_BL      32768
#define MIX_SMEM  196608
#define EPI_STRIDE 260

__global__ __launch_bounds__(256)
void mix_fused_kernel(const float* __restrict__ EFraw,
                      const __nv_bfloat16* __restrict__ Weh,
                      const __nv_bfloat16* __restrict__ Wel,
                      const float* __restrict__ be,
                      const __nv_bfloat16* __restrict__ W3h,
                      const __nv_bfloat16* __restrict__ W3l,
                      const float* __restrict__ bm,
                      const float* __restrict__ A1, const float* __restrict__ A2,
                      const int* __restrict__ idxn, const int* __restrict__ seg)
{
    extern __shared__ char smem[];
    const uint32_t sbase = smem_u32(smem);
    const int tid = threadIdx.x;
    const int wid = tid >> 5;
    const int lane = tid & 31;
    const int rowBase = blockIdx.x * 128;

    const int wm = wid >> 2;       // 0..1 (64-row band)
    const int wn = wid & 3;        // 0..3 (64-col band)
    const int lr = lane & 15;
    const int lc = lane >> 4;

    float acc[4][8][4];
#pragma unroll
    for (int mt = 0; mt < 4; ++mt)
#pragma unroll
        for (int nt = 0; nt < 8; ++nt)
#pragma unroll
            for (int q = 0; q < 4; ++q) acc[mt][nt][q] = 0.f;

    // W3 stage loader: kc -> buf (64KB: hi then lo)
    auto load_wstage = [&](uint32_t bufoff, int kc) {
        const uint32_t st = sbase + bufoff;
        const int kBase = kc * 64;
#pragma unroll
        for (int l = 0; l < 8; ++l) {
            int idx = tid + l * 256;
            int r = idx >> 3, cc = idx & 7;
            uint32_t off = SW128((uint32_t)(r * 128 + cc * 16));
            CP_ASYNC16(st + off,        (const char*)(W3h + (size_t)r * 256 + kBase) + cc * 16);
            CP_ASYNC16(st + S_BL + off, (const char*)(W3l + (size_t)r * 256 + kBase) + cc * 16);
        }
    };

    // ---- prologue: raw efin fp32 + We hi/lo + W3[kc0], all concurrent ----
#pragma unroll
    for (int l = 0; l < 4; ++l) {          // raw fp32: 128 rows x 128B (linear)
        int idx = tid + l * 256;
        int r = idx >> 3, cc = idx & 7;
        CP_ASYNC16(sbase + RAW_OFF + (uint32_t)(r * 128 + cc * 16),
                   (const char*)(EFraw + (size_t)(rowBase + r) * 32) + cc * 16);
    }
#pragma unroll
    for (int l = 0; l < 8; ++l) {          // Weh/Wel -> buf1
        int idx = tid + l * 256;
        int r = idx >> 3, cc = idx & 7;
        uint32_t off = SW128((uint32_t)(r * 128 + cc * 16));
        CP_ASYNC16(sbase + BUF1 + off,        (const char*)(Weh + (size_t)r * 64) + cc * 16);
        CP_ASYNC16(sbase + BUF1 + S_BL + off, (const char*)(Wel + (size_t)r * 64) + cc * 16);
    }
    load_wstage(BUF0, 0);                  // W3 kc0 prefetch
    CP_COMMIT();
    CP_WAIT(0);
    __syncthreads();

    // ---- convert raw fp32 -> efin bf16 (chunk0 region, zero-pad k 32..63) ----
#pragma unroll
    for (int l = 0; l < 4; ++l) {
        int idx = tid + l * 256;
        int r = idx >> 3, s = idx & 7;
        uint32_t dst = (uint32_t)SW128((uint32_t)(r * 128 + s * 16));
        if (s < 4) {
            float4 f0 = *(const float4*)(smem + RAW_OFF + r * 128 + s * 32);
            float4 f1 = *(const float4*)(smem + RAW_OFF + r * 128 + s * 32 + 16);
            __nv_bfloat16 h[8];
            h[0] = __float2bfloat16(f0.x); h[1] = __float2bfloat16(f0.y);
            h[2] = __float2bfloat16(f0.z); h[3] = __float2bfloat16(f0.w);
            h[4] = __float2bfloat16(f1.x); h[5] = __float2bfloat16(f1.y);
            h[6] = __float2bfloat16(f1.z); h[7] = __float2bfloat16(f1.w);
            *(uint4*)(smem + dst) = *(uint4*)h;
        } else {
            *(uint4*)(smem + dst) = make_uint4(0, 0, 0, 0);
        }
    }
    __syncthreads();

    // ---- stage 1: EF MMA (K=64): A = chunk0 efin, B = buf1 We ----
    {
        const uint32_t stA  = sbase;
        const uint32_t stBh = sbase + BUF1;
        const uint32_t stBl = sbase + BUF1 + S_BL;
#pragma unroll
        for (int k16 = 0; k16 < 4; ++k16) {
            const uint32_t kOff = k16 * 32 + lc * 16;
            uint32_t a[4][4];
#pragma unroll
            for (int mt = 0; mt < 4; ++mt) {
                int row = wm * 64 + mt * 16 + lr;
                LDSM_X4(a[mt][0], a[mt][1], a[mt][2], a[mt][3],
                        stA + SW128((uint32_t)(row * 128) + kOff));
            }
            uint32_t bh[4][4], bl[4][4];
#pragma unroll
            for (int ng = 0; ng < 4; ++ng) {
                int row = wn * 64 + ng * 16 + lr;
                uint32_t off = SW128((uint32_t)(row * 128) + kOff);
                LDSM_X4(bh[ng][0], bh[ng][1], bh[ng][2], bh[ng][3], stBh + off);
                LDSM_X4(bl[ng][0], bl[ng][1], bl[ng][2], bl[ng][3], stBl + off);
            }
#pragma unroll
            for (int mt = 0; mt < 4; ++mt)
#pragma unroll
                for (int nt = 0; nt < 8; ++nt) {
                    const int ng = nt >> 1, s = nt & 1;
                    MMA_BF16(acc[mt][nt], a[mt], bh[ng][s], bh[ng][s + 2]);
                    MMA_BF16(acc[mt][nt], a[mt], bl[ng][s], bl[ng][s + 2]);
                }
        }
    }
    __syncthreads();   // all reads of efin/We done

    // ---- EF store (bias+relu -> bf16 chunks); kick W3[kc1] into buf1 ----
    {
        const int r0 = wm * 64 + (lane >> 2);
        const int c0 = wn * 64 + ((lane & 3) << 1);
#pragma unroll
        for (int mt = 0; mt < 4; ++mt)
#pragma unroll
            for (int nt = 0; nt < 8; ++nt) {
                const int c = c0 + nt * 8;
                float2 bb = *(const float2*)&be[c];
                float v0 = fmaxf(acc[mt][nt][0] + bb.x, 0.f);
                float v1 = fmaxf(acc[mt][nt][1] + bb.y, 0.f);
                float v2 = fmaxf(acc[mt][nt][2] + bb.x, 0.f);
                float v3 = fmaxf(acc[mt][nt][3] + bb.y, 0.f);
                __nv_bfloat162 p1, p2;
                p1.x = __float2bfloat16(v0); p1.y = __float2bfloat16(v1);
                p2.x = __float2bfloat16(v2); p2.y = __float2bfloat16(v3);
                const int chunk = c >> 6, cl2 = (c & 63) * 2;
                const int r1 = r0 + mt * 16, r2 = r1 + 8;
                *(__nv_bfloat162*)(smem + chunk * EF_CHUNK +
                    SW128((uint32_t)(r1 * 128 + cl2))) = p1;
                *(__nv_bfloat162*)(smem + chunk * EF_CHUNK +
                    SW128((uint32_t)(r2 * 128 + cl2))) = p2;
                acc[mt][nt][0] = 0.f; acc[mt][nt][1] = 0.f;
                acc[mt][nt][2] = 0.f; acc[mt][nt][3] = 0.f;
            }
    }
    load_wstage(BUF1, 1);   // G1
    CP_COMMIT();
    __syncthreads();        // EF visible

    // ---- stage 2: kc0 from buf0 (ready), kc1 buf1, kc2 buf0, kc3 buf1 ----
    for (int kc = 0; kc < 4; ++kc) {
        const uint32_t stA = sbase + kc * EF_CHUNK;
        const uint32_t stB = sbase + ((kc & 1) ? BUF1 : BUF0);
#pragma unroll
        for (int k16 = 0; k16 < 4; ++k16) {
            const uint32_t kOff = k16 * 32 + lc * 16;
            uint32_t a[4][4];
#pragma unroll
            for (int mt = 0; mt < 4; ++mt) {
                int row = wm * 64 + mt * 16 + lr;
                LDSM_X4(a[mt][0], a[mt][1], a[mt][2], a[mt][3],
                        stA + SW128((uint32_t)(row * 128) + kOff));
            }
            uint32_t bh[4][4], bl[4][4];
#pragma unroll
            for (int ng = 0; ng < 4; ++ng) {
                int row = wn * 64 + ng * 16 + lr;
                uint32_t off = SW128((uint32_t)(row * 128) + kOff);
                LDSM_X4(bh[ng][0], bh[ng][1], bh[ng][2], bh[ng][3], stB + off);
                LDSM_X4(bl[ng][0], bl[ng][1], bl[ng][2], bl[ng][3], stB + S_BL + off);
            }
#pragma unroll
            for (int mt = 0; mt < 4; ++mt)
#pragma unroll
                for (int nt = 0; nt < 8; ++nt) {
                    const int ng = nt >> 1, s = nt & 1;
                    MMA_BF16(acc[mt][nt], a[mt], bh[ng][s], bh[ng][s + 2]);
                    MMA_BF16(acc[mt][nt], a[mt], bl[ng][s], bl[ng][s + 2]);
                }
        }
        __syncthreads();               // all warps done with this buf
        if (kc < 2) {
            load_wstage((kc & 1) ? BUF1 : BUF0, kc + 2);
            CP_COMMIT();
        }
        if (kc < 3) {
            if (kc < 2) { CP_WAIT(1); } else { CP_WAIT(0); }
            __syncthreads();           // next buf ready
        }
    }

    // ---- fragments -> padded smem [128][EPI_STRIDE] fp32 ----
    float* sC = (float*)smem;
    {
        const int r0 = wm * 64 + (lane >> 2);
        const int c0 = wn * 64 + ((lane & 3) << 1);
#pragma unroll
        for (int mt = 0; mt < 4; ++mt)
#pragma unroll
            for (int nt = 0; nt < 8; ++nt) {
                int rr = r0 + mt * 16;
                int cc = c0 + nt * 8;
                *(float2*)&sC[rr * EPI_STRIDE + cc] =
                    make_float2(acc[mt][nt][0], acc[mt][nt][1]);
                *(float2*)&sC[(rr + 8) * EPI_STRIDE + cc] =
                    make_float2(acc[mt][nt][2], acc[mt][nt][3]);
            }
    }
    __syncthreads();

    // ---- row-oriented epilogue ----
    const int wrow = (wid & 3) * 32 + lane;
    const int e = rowBase + wrow;
    const int i1 = idxn[e];
    const int i2 = seg[e];
    const int ch = (wid >> 2) * 128;

    int prevseg = __shfl_up_sync(0xFFFFFFFFu, i2, 1);
    bool head = (lane == 0) || (prevseg != i2);
    unsigned hm = __ballot_sync(0xFFFFFFFFu, head);
    unsigned rest = (lane < 31) ? (hm & (0xFFFFFFFEu << lane)) : 0u;
    int e_end = rest ? (__ffs(rest) - 2) : 31;
    float* srow = &g_sum[(size_t)i2 * 256];
    const float* a1row = &A1[(size_t)i1 * 256];
    const float* a2row = &A2[(size_t)i2 * 256];

#pragma unroll
    for (int g = 0; g < 32; ++g) {
        const int cb = ch + g * 4;
        float4 t  = *(const float4*)&sC[wrow * EPI_STRIDE + cb];
        float4 a1 = *(const float4*)&a1row[cb];
        float4 a2 = *(const float4*)&a2row[cb];
        float4 bv = *(const float4*)&bm[cb];
        float v[4];
        v[0] = fmaxf(t.x + a1.x + a2.x + bv.x, 0.f);
        v[1] = fmaxf(t.y + a1.y + a2.y + bv.y, 0.f);
        v[2] = fmaxf(t.z + a1.z + a2.z + bv.z, 0.f);
        v[3] = fmaxf(t.w + a1.w + a2.w + bv.w, 0.f);
#pragma unroll
        for (int j = 0; j < 4; ++j) {
            float x = v[j];
#pragma unroll
            for (int d2 = 1; d2 < 32; d2 <<= 1) {
                float o = __shfl_down_sync(0xFFFFFFFFu, x, d2);
                if (lane + d2 <= e_end) x += o;
            }
            if (head) atomicAdd(&srow[cb + j], x);
        }
    }
}

// ---------------- prep + final kernels ------------------------------------
__global__ void prep_weights(const float* __restrict__ Wn,
                             const float* __restrict__ Wm,
                             const float* __restrict__ We)
{
    int idx = blockIdx.x * blockDim.x + threadIdx.x;  // 65536
    int n = idx >> 8, k = idx & 255;

    float w0 = Wn[k * 256 + n];
    float w1 = Wm[k * 256 + n];
    float w2 = Wm[(256 + k) * 256 + n];
    float w3 = Wm[(512 + k) * 256 + n];
    __nv_bfloat16 h;
    h = __float2bfloat16(w0); g_wnt_h[n * 256 + k] = h;
    g_wnt_l[n * 256 + k] = __float2bfloat16(w0 - __bfloat162float(h));
    h = __float2bfloat16(w1); g_wm1t_h[n * 256 + k] = h;
    g_wm1t_l[n * 256 + k] = __float2bfloat16(w1 - __bfloat162float(h));
    h = __float2bfloat16(w2); g_wm2t_h[n * 256 + k] = h;
    g_wm2t_l[n * 256 + k] = __float2bfloat16(w2 - __bfloat162float(h));
    h = __float2bfloat16(w3); g_wm3t_h[n * 256 + k] = h;
    g_wm3t_l[n * 256 + k] = __float2bfloat16(w3 - __bfloat162float(h));

    if (k < 64) {
        float we = (k < 32) ? We[k * 256 + n] : 0.f;
        h = __float2bfloat16(we);
        g_wet_h[n * 64 + k] = h;
        g_wet_l[n * 64 + k] = __float2bfloat16(we - __bfloat162float(h));
    }
}

__global__ void prep_input(const float* __restrict__ input)
{
    int i = blockIdx.x * blockDim.x + threadIdx.x;
    if (i < NN * D) {
        float v = input[i];
        __nv_bfloat16 h = __float2bfloat16(v);
        g_in_h[i] = h;
        g_in_l[i] = __float2bfloat16(v - __bfloat162float(h));
    }
}

// grid = NN blocks of 256; counts via binary search on sorted seg;
// resets g_sum to 0 for the next replay (device globals start zeroed).
__global__ void final_kernel(const int* __restrict__ seg, float* __restrict__ out)
{
    __shared__ int s_cnt;
    const int n = blockIdx.x;
    if (threadIdx.x == 0) {
        int lo = 0, hi = NE;
        while (lo < hi) { int mid = (lo + hi) >> 1; if (seg[mid] <  n) lo = mid + 1; else hi = mid; }
        int lb = lo;
        lo = 0; hi = NE;
        while (lo < hi) { int mid = (lo + hi) >> 1; if (seg[mid] <= n) lo = mid + 1; else hi = mid; }
        s_cnt = lo - lb;
    }
    __syncthreads();
    const int c = s_cnt;
    const int i = n * 256 + threadIdx.x;
    float s = g_sum[i];
    out[i] = (c > 0) ? s / (float)c : 0.f;
    g_sum[i] = 0.f;
}

// ===========================================================================
extern "C" void kernel_launch(void* const* d_in, const int* in_sizes, int n_in,
                              void* d_out, int out_size)
{
    const float* input     = (const float*)d_in[0];
    const float* edgefeats = (const float*)d_in[1];
    const int*   idxn      = (const int*)  d_in[2];
    const int*   seg_ids   = (const int*)  d_in[3];
    const float* Wn        = (const float*)d_in[4];
    const float* bn        = (const float*)d_in[5];
    const float* We        = (const float*)d_in[6];
    const float* be        = (const float*)d_in[7];
    const float* Wm        = (const float*)d_in[8];
    const float* bm        = (const float*)d_in[9];
    float* out = (float*)d_out;

    float *p_A1, *p_A2;
    __nv_bfloat16 *p_inh, *p_inl, *p_nfh, *p_nfl;
    __nv_bfloat16 *p_wnth, *p_wntl, *p_w1h, *p_w1l, *p_w2h, *p_w2l, *p_w3h, *p_w3l;
    __nv_bfloat16 *p_weh, *p_wel;
    cudaGetSymbolAddress((void**)&p_A1, g_A1);
    cudaGetSymbolAddress((void**)&p_A2, g_A2);
    cudaGetSymbolAddress((void**)&p_inh, g_in_h);
    cudaGetSymbolAddress((void**)&p_inl, g_in_l);
    cudaGetSymbolAddress((void**)&p_nfh, g_nf_h);
    cudaGetSymbolAddress((void**)&p_nfl, g_nf_l);
    cudaGetSymbolAddress((void**)&p_wnth, g_wnt_h);
    cudaGetSymbolAddress((void**)&p_wntl, g_wnt_l);
    cudaGetSymbolAddress((void**)&p_w1h, g_wm1t_h);
    cudaGetSymbolAddress((void**)&p_w1l, g_wm1t_l);
    cudaGetSymbolAddress((void**)&p_w2h, g_wm2t_h);
    cudaGetSymbolAddress((void**)&p_w2l, g_wm2t_l);
    cudaGetSymbolAddress((void**)&p_w3h, g_wm3t_h);
    cudaGetSymbolAddress((void**)&p_w3l, g_wm3t_l);
    cudaGetSymbolAddress((void**)&p_weh, g_wet_h);
    cudaGetSymbolAddress((void**)&p_wel, g_wet_l);

    cudaFuncSetAttribute(mix_fused_kernel,
                         cudaFuncAttributeMaxDynamicSharedMemorySize, MIX_SMEM);
    cudaFuncSetAttribute(hmma_gemm<256, 3, true, 1>,
                         cudaFuncAttributeMaxDynamicSharedMemorySize, 131072);
    cudaFuncSetAttribute(hmma_gemm<256, 3, false, 0>,
                         cudaFuncAttributeMaxDynamicSharedMemorySize, 131072);

    prep_weights<<<256, 256>>>(Wn, Wm, We);
    prep_input<<<(NN * D + 255) / 256, 256>>>(input);

    {
        dim3 g((NN + 127) / 128, 2);
        hmma_gemm<256, 3, true, 1><<<g, 256, 131072>>>(
            p_inh, p_inl, p_wnth, p_wntl, bn, nullptr, p_nfh, p_nfl, NN);
        hmma_gemm<256, 3, false, 0><<<g, 256, 131072>>>(
            p_nfh, p_nfl, p_w1h, p_w1l, nullptr, p_A1, nullptr, nullptr, NN);
        hmma_gemm<256, 3, false, 0><<<g, 256, 131072>>>(
            p_nfh, p_nfl, p_w2h, p_w2l, nullptr, p_A2, nullptr, nullptr, NN);
    }
    mix_fused_kernel<<<NE / 128, 256, MIX_SMEM>>>(
        edgefeats, p_weh, p_wel, be, p_w3h, p_w3l, bm, p_A1, p_A2, idxn, seg_ids);

    final_kernel<<<NN, 256>>>(seg_ids, out);
}

// round 9
// speedup vs baseline: 2.0421x; 1.1749x over previous
#include <cuda_runtime.h>
#include <cuda_bf16.h>
#include <cuda_fp16.h>
#include <cstdint>

#define NN 10000
#define NE 320000
#define D  256

// ---------------- scratch (device globals; no allocation allowed) ----------
__device__ __align__(256) float g_A1[NN * D];
__device__ __align__(256) float g_A2[NN * D];
__device__ __align__(256) float g_sum[NN * D];   // zero-init at load; self-resetting

__device__ __align__(256) __nv_bfloat16 g_in_h[NN * D];
__device__ __align__(256) __nv_bfloat16 g_in_l[NN * D];
__device__ __align__(256) __nv_bfloat16 g_nf_h[NN * D];
__device__ __align__(256) __nv_bfloat16 g_nf_l[NN * D];

__device__ __align__(256) __nv_bfloat16 g_wnt_h[D * D],  g_wnt_l[D * D];
__device__ __align__(256) __nv_bfloat16 g_wm1t_h[D * D], g_wm1t_l[D * D];
__device__ __align__(256) __nv_bfloat16 g_wm2t_h[D * D], g_wm2t_l[D * D];
__device__ __align__(256) __half g_wm3t[D * D];          // Wm3^T fp16 [N][K]
__device__ __align__(256) __half g_wet[D * 64];          // We^T fp16 [N][64]

// =============================== PTX helpers ===============================
__device__ __forceinline__ uint32_t smem_u32(const void* p) {
    uint32_t a;
    asm("{ .reg .u64 t; cvta.to.shared.u64 t, %1; cvt.u32.u64 %0, t; }"
        : "=r"(a) : "l"(p));
    return a;
}
#define SW128(off) ((off) ^ (((off) >> 3) & 0x70))

#define CP_ASYNC16(dst, src) \
    asm volatile("cp.async.cg.shared.global [%0], [%1], 16;" \
        :: "r"(dst), "l"(src) : "memory")
#define CP_ASYNC16Z(dst, src, sz) \
    asm volatile("cp.async.cg.shared.global [%0], [%1], 16, %2;" \
        :: "r"(dst), "l"(src), "r"(sz) : "memory")
#define CP_COMMIT() asm volatile("cp.async.commit_group;" ::: "memory")
#define CP_WAIT(n)  asm volatile("cp.async.wait_group %0;" :: "n"(n) : "memory")

#define LDSM_X4(r0, r1, r2, r3, addr) \
    asm volatile("ldmatrix.sync.aligned.m8n8.x4.shared.b16 {%0,%1,%2,%3}, [%4];" \
        : "=r"(r0), "=r"(r1), "=r"(r2), "=r"(r3) : "r"(addr))

#define MMA_BF16(c, a, b0, b1) \
    asm volatile("mma.sync.aligned.m16n8k16.row.col.f32.bf16.bf16.f32 " \
        "{%0,%1,%2,%3}, {%4,%5,%6,%7}, {%8,%9}, {%0,%1,%2,%3};" \
        : "+f"((c)[0]), "+f"((c)[1]), "+f"((c)[2]), "+f"((c)[3]) \
        : "r"((a)[0]), "r"((a)[1]), "r"((a)[2]), "r"((a)[3]), "r"(b0), "r"(b1))

#define MMA_F16(c, a, b0, b1) \
    asm volatile("mma.sync.aligned.m16n8k16.row.col.f32.f16.f16.f32 " \
        "{%0,%1,%2,%3}, {%4,%5,%6,%7}, {%8,%9}, {%0,%1,%2,%3};" \
        : "+f"((c)[0]), "+f"((c)[1]), "+f"((c)[2]), "+f"((c)[3]) \
        : "r"((a)[0]), "r"((a)[1]), "r"((a)[2]), "r"((a)[3]), "r"(b0), "r"(b1))

// ===========================================================================
// Unified HMMA GEMM for node-side (unchanged, proven): C[M,256]
// ===========================================================================
template<int KDIM, int NPASS, bool RELU, int OUT>
__global__ __launch_bounds__(256)
void hmma_gemm(const __nv_bfloat16* __restrict__ Ah,
               const __nv_bfloat16* __restrict__ Al,
               const __nv_bfloat16* __restrict__ Bh_,
               const __nv_bfloat16* __restrict__ Bl_,
               const float* __restrict__ bias,
               float* __restrict__ Cf,
               __nv_bfloat16* __restrict__ Ch,
               __nv_bfloat16* __restrict__ Cl,
               int M)
{
    constexpr int OFF_AL2 = 16384;
    constexpr int OFF_BH2 = (NPASS == 3) ? 32768 : 16384;
    constexpr int OFF_BL2 = OFF_BH2 + 16384;
    constexpr int SBYTES  = OFF_BL2 + 16384;
    constexpr int NKC     = KDIM / 64;

    extern __shared__ char smem[];
    const uint32_t sbase = smem_u32(smem);
    const int tid = threadIdx.x;
    const int wid = tid >> 5;
    const int lane = tid & 31;
    const int rowBase = blockIdx.x * 128;
    const int colBase = blockIdx.y * 128;

    const int wm = wid >> 2;
    const int wn = wid & 3;
    const int lr = lane & 15;
    const int lc = lane >> 4;

    float acc[4][4][4];
#pragma unroll
    for (int mt = 0; mt < 4; ++mt)
#pragma unroll
        for (int nt = 0; nt < 4; ++nt)
#pragma unroll
            for (int q = 0; q < 4; ++q) acc[mt][nt][q] = 0.f;

    auto load_stage = [&](int buf, int kc) {
        const uint32_t st = sbase + buf * SBYTES;
        const int kBase = kc * 64;
#pragma unroll
        for (int l = 0; l < 4; ++l) {
            int idx = tid + l * 256;
            int r = idx >> 3, cc = idx & 7;
            int gr = rowBase + r;
            uint32_t sz = (gr < M) ? 16u : 0u;
            int grc = (gr < M) ? gr : (M - 1);
            uint32_t doff = SW128((uint32_t)(r * 128 + cc * 16));
            const char* sh = (const char*)(Ah + (size_t)grc * KDIM + kBase) + cc * 16;
            CP_ASYNC16Z(st + doff, sh, sz);
            if (NPASS == 3) {
                const char* sl = (const char*)(Al + (size_t)grc * KDIM + kBase) + cc * 16;
                CP_ASYNC16Z(st + OFF_AL2 + doff, sl, sz);
            }
        }
#pragma unroll
        for (int l = 0; l < 4; ++l) {
            int idx = tid + l * 256;
            int r = idx >> 3, cc = idx & 7;
            uint32_t doff = SW128((uint32_t)(r * 128 + cc * 16));
            const char* sh = (const char*)(Bh_ + (size_t)(colBase + r) * KDIM + kBase) + cc * 16;
            const char* sl = (const char*)(Bl_ + (size_t)(colBase + r) * KDIM + kBase) + cc * 16;
            CP_ASYNC16(st + OFF_BH2 + doff, sh);
            CP_ASYNC16(st + OFF_BL2 + doff, sl);
        }
    };

    load_stage(0, 0);
    CP_COMMIT();

    for (int kc = 0; kc < NKC; ++kc) {
        if (kc + 1 < NKC) {
            load_stage((kc + 1) & 1, kc + 1);
            CP_COMMIT();
            CP_WAIT(1);
        } else {
            CP_WAIT(0);
        }
        __syncthreads();

        const uint32_t st = sbase + (kc & 1) * SBYTES;
#pragma unroll
        for (int k16 = 0; k16 < 4; ++k16) {
            const uint32_t kOff = k16 * 32 + lc * 16;
            uint32_t ah[4][4], al[4][4];
#pragma unroll
            for (int mt = 0; mt < 4; ++mt) {
                int row = wm * 64 + mt * 16 + lr;
                uint32_t off = SW128((uint32_t)(row * 128) + kOff);
                LDSM_X4(ah[mt][0], ah[mt][1], ah[mt][2], ah[mt][3], st + off);
                if (NPASS == 3)
                    LDSM_X4(al[mt][0], al[mt][1], al[mt][2], al[mt][3],
                            st + OFF_AL2 + off);
            }
            uint32_t bh[2][4], bl[2][4];
#pragma unroll
            for (int ng = 0; ng < 2; ++ng) {
                int row = wn * 32 + ng * 16 + lr;
                uint32_t off = SW128((uint32_t)(row * 128) + kOff);
                LDSM_X4(bh[ng][0], bh[ng][1], bh[ng][2], bh[ng][3], st + OFF_BH2 + off);
                LDSM_X4(bl[ng][0], bl[ng][1], bl[ng][2], bl[ng][3], st + OFF_BL2 + off);
            }
#pragma unroll
            for (int mt = 0; mt < 4; ++mt)
#pragma unroll
                for (int nt = 0; nt < 4; ++nt) {
                    const int ng = nt >> 1, s = nt & 1;
                    MMA_BF16(acc[mt][nt], ah[mt], bh[ng][s], bh[ng][s + 2]);
                    MMA_BF16(acc[mt][nt], ah[mt], bl[ng][s], bl[ng][s + 2]);
                    if (NPASS == 3)
                        MMA_BF16(acc[mt][nt], al[mt], bh[ng][s], bh[ng][s + 2]);
                }
        }
        __syncthreads();
    }

    const int row0 = rowBase + wm * 64 + (lane >> 2);
    const int col0 = colBase + wn * 32 + ((lane & 3) << 1);
#pragma unroll
    for (int mt = 0; mt < 4; ++mt)
#pragma unroll
        for (int nt = 0; nt < 4; ++nt) {
            const int c = col0 + nt * 8;
            float v0 = acc[mt][nt][0], v1 = acc[mt][nt][1];
            float v2 = acc[mt][nt][2], v3 = acc[mt][nt][3];
            if (RELU) {
                float2 bb = *(const float2*)&bias[c];
                v0 = fmaxf(v0 + bb.x, 0.f); v1 = fmaxf(v1 + bb.y, 0.f);
                v2 = fmaxf(v2 + bb.x, 0.f); v3 = fmaxf(v3 + bb.y, 0.f);
            }
            const int r1 = row0 + mt * 16;
            const int r2 = r1 + 8;
            if (OUT == 0) {
                if (r1 < M) *(float2*)&Cf[(size_t)r1 * 256 + c] = make_float2(v0, v1);
                if (r2 < M) *(float2*)&Cf[(size_t)r2 * 256 + c] = make_float2(v2, v3);
            } else {
                __nv_bfloat162 h1, h2;
                h1.x = __float2bfloat16(v0); h1.y = __float2bfloat16(v1);
                h2.x = __float2bfloat16(v2); h2.y = __float2bfloat16(v3);
                if (r1 < M) *(__nv_bfloat162*)&Ch[(size_t)r1 * 256 + c] = h1;
                if (r2 < M) *(__nv_bfloat162*)&Ch[(size_t)r2 * 256 + c] = h2;
                if (OUT == 1) {
                    __nv_bfloat162 l1, l2;
                    l1.x = __float2bfloat16(v0 - __bfloat162float(h1.x));
                    l1.y = __float2bfloat16(v1 - __bfloat162float(h1.y));
                    l2.x = __float2bfloat16(v2 - __bfloat162float(h2.x));
                    l2.y = __float2bfloat16(v3 - __bfloat162float(h2.y));
                    if (r1 < M) *(__nv_bfloat162*)&Cl[(size_t)r1 * 256 + c] = l1;
                    if (r2 < M) *(__nv_bfloat162*)&Cl[(size_t)r2 * 256 + c] = l2;
                }
            }
        }
}

// ===========================================================================
// FUSED mix kernel, fp16 single-pass, all W3 resident in smem.
// smem map (224KB):
//   [0,64K)       EF chunks 0..3 ([128x64] fp16 swizzled, chunk c at c*16K)
//                 (prologue: raw fp32 edgefeats parked at [32K,48K))
//   [64K,192K)    W3 chunks 0..3 (each [256x64] fp16 swizzled, 32K)
//   [192K,224K)   We ([256x64] fp16 swizzled, 32K)
// ===========================================================================
#define EF_CHUNK  16384
#define RAW_OFF   32768
#define W3_OFF    65536
#define W3_CHUNK  32768
#define WE_OFF    196608
#define MIX_SMEM  229376
#define EPI_STRIDE 260

__global__ __launch_bounds__(256)
void mix_fused_kernel(const float* __restrict__ EFraw,
                      const __half* __restrict__ We_,
                      const float* __restrict__ be,
                      const __half* __restrict__ W3_,
                      const float* __restrict__ bm,
                      const float* __restrict__ A1, const float* __restrict__ A2,
                      const int* __restrict__ idxn, const int* __restrict__ seg)
{
    extern __shared__ char smem[];
    const uint32_t sbase = smem_u32(smem);
    const int tid = threadIdx.x;
    const int wid = tid >> 5;
    const int lane = tid & 31;
    const int rowBase = blockIdx.x * 128;

    const int wm = wid >> 2;       // 0..1 (64-row band)
    const int wn = wid & 3;        // 0..3 (64-col band)
    const int lr = lane & 15;
    const int lc = lane >> 4;

    float acc[4][8][4];
#pragma unroll
    for (int mt = 0; mt < 4; ++mt)
#pragma unroll
        for (int nt = 0; nt < 8; ++nt)
#pragma unroll
            for (int q = 0; q < 4; ++q) acc[mt][nt][q] = 0.f;

    // ---- prologue: G0 = raw ef + We; G1..G4 = W3 chunks ----
#pragma unroll
    for (int l = 0; l < 4; ++l) {          // raw fp32: 128 rows x 128B, linear
        int idx = tid + l * 256;
        int r = idx >> 3, cc = idx & 7;
        CP_ASYNC16(sbase + RAW_OFF + (uint32_t)(r * 128 + cc * 16),
                   (const char*)(EFraw + (size_t)(rowBase + r) * 32) + cc * 16);
    }
#pragma unroll
    for (int l = 0; l < 8; ++l) {          // We: 256 rows x 128B
        int idx = tid + l * 256;
        int r = idx >> 3, cc = idx & 7;
        CP_ASYNC16(sbase + WE_OFF + SW128((uint32_t)(r * 128 + cc * 16)),
                   (const char*)(We_ + (size_t)r * 64) + cc * 16);
    }
    CP_COMMIT();                           // G0
#pragma unroll
    for (int kc = 0; kc < 4; ++kc) {       // W3 chunk kc: 256 rows x 128B
#pragma unroll
        for (int l = 0; l < 8; ++l) {
            int idx = tid + l * 256;
            int r = idx >> 3, cc = idx & 7;
            CP_ASYNC16(sbase + W3_OFF + kc * W3_CHUNK +
                           SW128((uint32_t)(r * 128 + cc * 16)),
                       (const char*)(W3_ + (size_t)r * 256 + kc * 64) + cc * 16);
        }
        CP_COMMIT();                       // G1..G4
    }

    CP_WAIT(4);                            // G0 done; W3 still streaming
    __syncthreads();

    // ---- convert raw fp32 -> EF-in fp16 (chunk0 region, zero-pad k>=32) ----
#pragma unroll
    for (int l = 0; l < 4; ++l) {
        int idx = tid + l * 256;
        int r = idx >> 3, s = idx & 7;
        uint32_t dst = (uint32_t)SW128((uint32_t)(r * 128 + s * 16));
        if (s < 4) {
            float4 f0 = *(const float4*)(smem + RAW_OFF + r * 128 + s * 32);
            float4 f1 = *(const float4*)(smem + RAW_OFF + r * 128 + s * 32 + 16);
            __half h[8];
            h[0] = __float2half_rn(f0.x); h[1] = __float2half_rn(f0.y);
            h[2] = __float2half_rn(f0.z); h[3] = __float2half_rn(f0.w);
            h[4] = __float2half_rn(f1.x); h[5] = __float2half_rn(f1.y);
            h[6] = __float2half_rn(f1.z); h[7] = __float2half_rn(f1.w);
            *(uint4*)(smem + dst) = *(uint4*)h;
        } else {
            *(uint4*)(smem + dst) = make_uint4(0, 0, 0, 0);
        }
    }
    __syncthreads();

    // ---- stage 1: EF = efin @ We^T (K=64, single pass) ----
    {
        const uint32_t stA = sbase;
        const uint32_t stB = sbase + WE_OFF;
#pragma unroll
        for (int k16 = 0; k16 < 4; ++k16) {
            const uint32_t kOff = k16 * 32 + lc * 16;
            uint32_t a[4][4];
#pragma unroll
            for (int mt = 0; mt < 4; ++mt) {
                int row = wm * 64 + mt * 16 + lr;
                LDSM_X4(a[mt][0], a[mt][1], a[mt][2], a[mt][3],
                        stA + SW128((uint32_t)(row * 128) + kOff));
            }
            uint32_t b[4][4];
#pragma unroll
            for (int ng = 0; ng < 4; ++ng) {
                int row = wn * 64 + ng * 16 + lr;
                LDSM_X4(b[ng][0], b[ng][1], b[ng][2], b[ng][3],
                        stB + SW128((uint32_t)(row * 128) + kOff));
            }
#pragma unroll
            for (int mt = 0; mt < 4; ++mt)
#pragma unroll
                for (int nt = 0; nt < 8; ++nt) {
                    const int ng = nt >> 1, s = nt & 1;
                    MMA_F16(acc[mt][nt], a[mt], b[ng][s], b[ng][s + 2]);
                }
        }
    }
    __syncthreads();   // all reads of efin done (chunk0 will be overwritten)

    // ---- EF store: bias + relu -> fp16 chunks ----
    {
        const int r0 = wm * 64 + (lane >> 2);
        const int c0 = wn * 64 + ((lane & 3) << 1);
#pragma unroll
        for (int mt = 0; mt < 4; ++mt)
#pragma unroll
            for (int nt = 0; nt < 8; ++nt) {
                const int c = c0 + nt * 8;
                float2 bb = *(const float2*)&be[c];
                float v0 = fmaxf(acc[mt][nt][0] + bb.x, 0.f);
                float v1 = fmaxf(acc[mt][nt][1] + bb.y, 0.f);
                float v2 = fmaxf(acc[mt][nt][2] + bb.x, 0.f);
                float v3 = fmaxf(acc[mt][nt][3] + bb.y, 0.f);
                __half p1[2], p2[2];
                p1[0] = __float2half_rn(v0); p1[1] = __float2half_rn(v1);
                p2[0] = __float2half_rn(v2); p2[1] = __float2half_rn(v3);
                const int chunk = c >> 6, cl2 = (c & 63) * 2;
                const int r1 = r0 + mt * 16, r2 = r1 + 8;
                *(uint32_t*)(smem + chunk * EF_CHUNK +
                    SW128((uint32_t)(r1 * 128 + cl2))) = *(uint32_t*)p1;
                *(uint32_t*)(smem + chunk * EF_CHUNK +
                    SW128((uint32_t)(r2 * 128 + cl2))) = *(uint32_t*)p2;
                acc[mt][nt][0] = 0.f; acc[mt][nt][1] = 0.f;
                acc[mt][nt][2] = 0.f; acc[mt][nt][3] = 0.f;
            }
    }
    __syncthreads();   // EF visible

    // ---- stage 2: T = EF @ W3^T, W3 fully resident, single pass ----
#pragma unroll
    for (int kc = 0; kc < 4; ++kc) {
        if      (kc == 0) CP_WAIT(3);
        else if (kc == 1) CP_WAIT(2);
        else if (kc == 2) CP_WAIT(1);
        else              CP_WAIT(0);
        __syncthreads();               // publish this W3 chunk

        const uint32_t stA = sbase + kc * EF_CHUNK;
        const uint32_t stB = sbase + W3_OFF + kc * W3_CHUNK;
#pragma unroll
        for (int k16 = 0; k16 < 4; ++k16) {
            const uint32_t kOff = k16 * 32 + lc * 16;
            uint32_t a[4][4];
#pragma unroll
            for (int mt = 0; mt < 4; ++mt) {
                int row = wm * 64 + mt * 16 + lr;
                LDSM_X4(a[mt][0], a[mt][1], a[mt][2], a[mt][3],
                        stA + SW128((uint32_t)(row * 128) + kOff));
            }
            uint32_t b[4][4];
#pragma unroll
            for (int ng = 0; ng < 4; ++ng) {
                int row = wn * 64 + ng * 16 + lr;
                LDSM_X4(b[ng][0], b[ng][1], b[ng][2], b[ng][3],
                        stB + SW128((uint32_t)(row * 128) + kOff));
            }
#pragma unroll
            for (int mt = 0; mt < 4; ++mt)
#pragma unroll
                for (int nt = 0; nt < 8; ++nt) {
                    const int ng = nt >> 1, s = nt & 1;
                    MMA_F16(acc[mt][nt], a[mt], b[ng][s], b[ng][s + 2]);
                }
        }
    }
    __syncthreads();   // all MMA/LDSM done before sC overlays smem

    // ---- fragments -> padded smem [128][EPI_STRIDE] fp32 ----
    float* sC = (float*)smem;
    {
        const int r0 = wm * 64 + (lane >> 2);
        const int c0 = wn * 64 + ((lane & 3) << 1);
#pragma unroll
        for (int mt = 0; mt < 4; ++mt)
#pragma unroll
            for (int nt = 0; nt < 8; ++nt) {
                int rr = r0 + mt * 16;
                int cc = c0 + nt * 8;
                *(float2*)&sC[rr * EPI_STRIDE + cc] =
                    make_float2(acc[mt][nt][0], acc[mt][nt][1]);
                *(float2*)&sC[(rr + 8) * EPI_STRIDE + cc] =
                    make_float2(acc[mt][nt][2], acc[mt][nt][3]);
            }
    }
    __syncthreads();

    // ---- row-oriented epilogue ----
    const int wrow = (wid & 3) * 32 + lane;
    const int e = rowBase + wrow;
    const int i1 = idxn[e];
    const int i2 = seg[e];
    const int ch = (wid >> 2) * 128;

    int prevseg = __shfl_up_sync(0xFFFFFFFFu, i2, 1);
    bool head = (lane == 0) || (prevseg != i2);
    unsigned hm = __ballot_sync(0xFFFFFFFFu, head);
    unsigned rest = (lane < 31) ? (hm & (0xFFFFFFFEu << lane)) : 0u;
    int e_end = rest ? (__ffs(rest) - 2) : 31;
    float* srow = &g_sum[(size_t)i2 * 256];
    const float* a1row = &A1[(size_t)i1 * 256];
    const float* a2row = &A2[(size_t)i2 * 256];

#pragma unroll
    for (int g = 0; g < 32; ++g) {
        const int cb = ch + g * 4;
        float4 t  = *(const float4*)&sC[wrow * EPI_STRIDE + cb];
        float4 a1 = *(const float4*)&a1row[cb];
        float4 a2 = *(const float4*)&a2row[cb];
        float4 bv = *(const float4*)&bm[cb];
        float v[4];
        v[0] = fmaxf(t.x + a1.x + a2.x + bv.x, 0.f);
        v[1] = fmaxf(t.y + a1.y + a2.y + bv.y, 0.f);
        v[2] = fmaxf(t.z + a1.z + a2.z + bv.z, 0.f);
        v[3] = fmaxf(t.w + a1.w + a2.w + bv.w, 0.f);
#pragma unroll
        for (int j = 0; j < 4; ++j) {
            float x = v[j];
#pragma unroll
            for (int d2 = 1; d2 < 32; d2 <<= 1) {
                float o = __shfl_down_sync(0xFFFFFFFFu, x, d2);
                if (lane + d2 <= e_end) x += o;
            }
            if (head) atomicAdd(&srow[cb + j], x);
        }
    }
}

// ---------------- prep + final kernels ------------------------------------
__global__ void prep_weights(const float* __restrict__ Wn,
                             const float* __restrict__ Wm,
                             const float* __restrict__ We)
{
    int idx = blockIdx.x * blockDim.x + threadIdx.x;  // 65536
    int n = idx >> 8, k = idx & 255;

    float w0 = Wn[k * 256 + n];
    float w1 = Wm[k * 256 + n];
    float w2 = Wm[(256 + k) * 256 + n];
    float w3 = Wm[(512 + k) * 256 + n];
    __nv_bfloat16 h;
    h = __float2bfloat16(w0); g_wnt_h[n * 256 + k] = h;
    g_wnt_l[n * 256 + k] = __float2bfloat16(w0 - __bfloat162float(h));
    h = __float2bfloat16(w1); g_wm1t_h[n * 256 + k] = h;
    g_wm1t_l[n * 256 + k] = __float2bfloat16(w1 - __bfloat162float(h));
    h = __float2bfloat16(w2); g_wm2t_h[n * 256 + k] = h;
    g_wm2t_l[n * 256 + k] = __float2bfloat16(w2 - __bfloat162float(h));
    g_wm3t[n * 256 + k] = __float2half_rn(w3);

    if (k < 64) {
        float we = (k < 32) ? We[k * 256 + n] : 0.f;
        g_wet[n * 64 + k] = __float2half_rn(we);
    }
}

__global__ void prep_input(const float* __restrict__ input)
{
    int i = blockIdx.x * blockDim.x + threadIdx.x;
    if (i < NN * D) {
        float v = input[i];
        __nv_bfloat16 h = __float2bfloat16(v);
        g_in_h[i] = h;
        g_in_l[i] = __float2bfloat16(v - __bfloat162float(h));
    }
}

// grid = NN blocks of 256; counts via binary search on sorted seg;
// resets g_sum to 0 for the next replay (device globals start zeroed).
__global__ void final_kernel(const int* __restrict__ seg, float* __restrict__ out)
{
    __shared__ int s_cnt;
    const int n = blockIdx.x;
    if (threadIdx.x == 0) {
        int lo = 0, hi = NE;
        while (lo < hi) { int mid = (lo + hi) >> 1; if (seg[mid] <  n) lo = mid + 1; else hi = mid; }
        int lb = lo;
        lo = 0; hi = NE;
        while (lo < hi) { int mid = (lo + hi) >> 1; if (seg[mid] <= n) lo = mid + 1; else hi = mid; }
        s_cnt = lo - lb;
    }
    __syncthreads();
    const int c = s_cnt;
    const int i = n * 256 + threadIdx.x;
    float s = g_sum[i];
    out[i] = (c > 0) ? s / (float)c : 0.f;
    g_sum[i] = 0.f;
}

// ===========================================================================
extern "C" void kernel_launch(void* const* d_in, const int* in_sizes, int n_in,
                              void* d_out, int out_size)
{
    const float* input     = (const float*)d_in[0];
    const float* edgefeats = (const float*)d_in[1];
    const int*   idxn      = (const int*)  d_in[2];
    const int*   seg_ids   = (const int*)  d_in[3];
    const float* Wn        = (const float*)d_in[4];
    const float* bn        = (const float*)d_in[5];
    const float* We        = (const float*)d_in[6];
    const float* be        = (const float*)d_in[7];
    const float* Wm        = (const float*)d_in[8];
    const float* bm        = (const float*)d_in[9];
    float* out = (float*)d_out;

    float *p_A1, *p_A2;
    __nv_bfloat16 *p_inh, *p_inl, *p_nfh, *p_nfl;
    __nv_bfloat16 *p_wnth, *p_wntl, *p_w1h, *p_w1l, *p_w2h, *p_w2l;
    __half *p_w3, *p_we;
    cudaGetSymbolAddress((void**)&p_A1, g_A1);
    cudaGetSymbolAddress((void**)&p_A2, g_A2);
    cudaGetSymbolAddress((void**)&p_inh, g_in_h);
    cudaGetSymbolAddress((void**)&p_inl, g_in_l);
    cudaGetSymbolAddress((void**)&p_nfh, g_nf_h);
    cudaGetSymbolAddress((void**)&p_nfl, g_nf_l);
    cudaGetSymbolAddress((void**)&p_wnth, g_wnt_h);
    cudaGetSymbolAddress((void**)&p_wntl, g_wnt_l);
    cudaGetSymbolAddress((void**)&p_w1h, g_wm1t_h);
    cudaGetSymbolAddress((void**)&p_w1l, g_wm1t_l);
    cudaGetSymbolAddress((void**)&p_w2h, g_wm2t_h);
    cudaGetSymbolAddress((void**)&p_w2l, g_wm2t_l);
    cudaGetSymbolAddress((void**)&p_w3, g_wm3t);
    cudaGetSymbolAddress((void**)&p_we, g_wet);

    cudaFuncSetAttribute(mix_fused_kernel,
                         cudaFuncAttributeMaxDynamicSharedMemorySize, MIX_SMEM);
    cudaFuncSetAttribute(hmma_gemm<256, 3, true, 1>,
                         cudaFuncAttributeMaxDynamicSharedMemorySize, 131072);
    cudaFuncSetAttribute(hmma_gemm<256, 3, false, 0>,
                         cudaFuncAttributeMaxDynamicSharedMemorySize, 131072);

    prep_weights<<<256, 256>>>(Wn, Wm, We);
    prep_input<<<(NN * D + 255) / 256, 256>>>(input);

    {
        dim3 g((NN + 127) / 128, 2);
        hmma_gemm<256, 3, true, 1><<<g, 256, 131072>>>(
            p_inh, p_inl, p_wnth, p_wntl, bn, nullptr, p_nfh, p_nfl, NN);
        hmma_gemm<256, 3, false, 0><<<g, 256, 131072>>>(
            p_nfh, p_nfl, p_w1h, p_w1l, nullptr, p_A1, nullptr, nullptr, NN);
        hmma_gemm<256, 3, false, 0><<<g, 256, 131072>>>(
            p_nfh, p_nfl, p_w2h, p_w2l, nullptr, p_A2, nullptr, nullptr, NN);
    }
    mix_fused_kernel<<<NE / 128, 256, MIX_SMEM>>>(
        edgefeats, p_we, be, p_w3, bm, p_A1, p_A2, idxn, seg_ids);

    final_kernel<<<NN, 256>>>(seg_ids, out);
}

// round 11
// speedup vs baseline: 2.4299x; 1.1899x over previous
#include <cuda_runtime.h>
#include <cuda_bf16.h>
#include <cuda_fp16.h>
#include <cstdint>

#define NN 10000
#define NE 320000
#define D  256

// ---------------- scratch (device globals; no allocation allowed) ----------
__device__ __align__(256) float g_A1[NN * D];
__device__ __align__(256) float g_A2[NN * D];
__device__ __align__(256) float g_sum[NN * D];   // zero-init at load; self-resetting

__device__ __align__(256) __nv_bfloat16 g_in_h[NN * D];
__device__ __align__(256) __nv_bfloat16 g_in_l[NN * D];
__device__ __align__(256) __nv_bfloat16 g_nf_h[NN * D];
__device__ __align__(256) __nv_bfloat16 g_nf_l[NN * D];

__device__ __align__(256) __nv_bfloat16 g_wnt_h[D * D],  g_wnt_l[D * D];
__device__ __align__(256) __nv_bfloat16 g_wm1t_h[D * D], g_wm1t_l[D * D];
__device__ __align__(256) __nv_bfloat16 g_wm2t_h[D * D], g_wm2t_l[D * D];
__device__ __align__(256) __half g_wm3t[D * D];          // Wm3^T fp16 [N][K]
__device__ __align__(256) __half g_wet[D * 64];          // We^T fp16 [N][64]

// =============================== PTX helpers ===============================
__device__ __forceinline__ uint32_t smem_u32(const void* p) {
    uint32_t a;
    asm("{ .reg .u64 t; cvta.to.shared.u64 t, %1; cvt.u32.u64 %0, t; }"
        : "=r"(a) : "l"(p));
    return a;
}
#define SW128(off) ((off) ^ (((off) >> 3) & 0x70))

#define CP_ASYNC16(dst, src) \
    asm volatile("cp.async.cg.shared.global [%0], [%1], 16;" \
        :: "r"(dst), "l"(src) : "memory")
#define CP_ASYNC16Z(dst, src, sz) \
    asm volatile("cp.async.cg.shared.global [%0], [%1], 16, %2;" \
        :: "r"(dst), "l"(src), "r"(sz) : "memory")
#define CP_COMMIT() asm volatile("cp.async.commit_group;" ::: "memory")
#define CP_WAIT(n)  asm volatile("cp.async.wait_group %0;" :: "n"(n) : "memory")

#define LDSM_X4(r0, r1, r2, r3, addr) \
    asm volatile("ldmatrix.sync.aligned.m8n8.x4.shared.b16 {%0,%1,%2,%3}, [%4];" \
        : "=r"(r0), "=r"(r1), "=r"(r2), "=r"(r3) : "r"(addr))

#define MMA_BF16(c, a, b0, b1) \
    asm volatile("mma.sync.aligned.m16n8k16.row.col.f32.bf16.bf16.f32 " \
        "{%0,%1,%2,%3}, {%4,%5,%6,%7}, {%8,%9}, {%0,%1,%2,%3};" \
        : "+f"((c)[0]), "+f"((c)[1]), "+f"((c)[2]), "+f"((c)[3]) \
        : "r"((a)[0]), "r"((a)[1]), "r"((a)[2]), "r"((a)[3]), "r"(b0), "r"(b1))

#define MMA_F16(c, a, b0, b1) \
    asm volatile("mma.sync.aligned.m16n8k16.row.col.f32.f16.f16.f32 " \
        "{%0,%1,%2,%3}, {%4,%5,%6,%7}, {%8,%9}, {%0,%1,%2,%3};" \
        : "+f"((c)[0]), "+f"((c)[1]), "+f"((c)[2]), "+f"((c)[3]) \
        : "r"((a)[0]), "r"((a)[1]), "r"((a)[2]), "r"((a)[3]), "r"(b0), "r"(b1))

// ===========================================================================
// Unified HMMA GEMM for node-side (unchanged, proven): C[M,256]
// ===========================================================================
template<int KDIM, int NPASS, bool RELU, int OUT>
__global__ __launch_bounds__(256)
void hmma_gemm(const __nv_bfloat16* __restrict__ Ah,
               const __nv_bfloat16* __restrict__ Al,
               const __nv_bfloat16* __restrict__ Bh_,
               const __nv_bfloat16* __restrict__ Bl_,
               const float* __restrict__ bias,
               float* __restrict__ Cf,
               __nv_bfloat16* __restrict__ Ch,
               __nv_bfloat16* __restrict__ Cl,
               int M)
{
    constexpr int OFF_AL2 = 16384;
    constexpr int OFF_BH2 = (NPASS == 3) ? 32768 : 16384;
    constexpr int OFF_BL2 = OFF_BH2 + 16384;
    constexpr int SBYTES  = OFF_BL2 + 16384;
    constexpr int NKC     = KDIM / 64;

    extern __shared__ char smem[];
    const uint32_t sbase = smem_u32(smem);
    const int tid = threadIdx.x;
    const int wid = tid >> 5;
    const int lane = tid & 31;
    const int rowBase = blockIdx.x * 128;
    const int colBase = blockIdx.y * 128;

    const int wm = wid >> 2;
    const int wn = wid & 3;
    const int lr = lane & 15;
    const int lc = lane >> 4;

    float acc[4][4][4];
#pragma unroll
    for (int mt = 0; mt < 4; ++mt)
#pragma unroll
        for (int nt = 0; nt < 4; ++nt)
#pragma unroll
            for (int q = 0; q < 4; ++q) acc[mt][nt][q] = 0.f;

    auto load_stage = [&](int buf, int kc) {
        const uint32_t st = sbase + buf * SBYTES;
        const int kBase = kc * 64;
#pragma unroll
        for (int l = 0; l < 4; ++l) {
            int idx = tid + l * 256;
            int r = idx >> 3, cc = idx & 7;
            int gr = rowBase + r;
            uint32_t sz = (gr < M) ? 16u : 0u;
            int grc = (gr < M) ? gr : (M - 1);
            uint32_t doff = SW128((uint32_t)(r * 128 + cc * 16));
            const char* sh = (const char*)(Ah + (size_t)grc * KDIM + kBase) + cc * 16;
            CP_ASYNC16Z(st + doff, sh, sz);
            if (NPASS == 3) {
                const char* sl = (const char*)(Al + (size_t)grc * KDIM + kBase) + cc * 16;
                CP_ASYNC16Z(st + OFF_AL2 + doff, sl, sz);
            }
        }
#pragma unroll
        for (int l = 0; l < 4; ++l) {
            int idx = tid + l * 256;
            int r = idx >> 3, cc = idx & 7;
            uint32_t doff = SW128((uint32_t)(r * 128 + cc * 16));
            const char* sh = (const char*)(Bh_ + (size_t)(colBase + r) * KDIM + kBase) + cc * 16;
            const char* sl = (const char*)(Bl_ + (size_t)(colBase + r) * KDIM + kBase) + cc * 16;
            CP_ASYNC16(st + OFF_BH2 + doff, sh);
            CP_ASYNC16(st + OFF_BL2 + doff, sl);
        }
    };

    load_stage(0, 0);
    CP_COMMIT();

    for (int kc = 0; kc < NKC; ++kc) {
        if (kc + 1 < NKC) {
            load_stage((kc + 1) & 1, kc + 1);
            CP_COMMIT();
            CP_WAIT(1);
        } else {
            CP_WAIT(0);
        }
        __syncthreads();

        const uint32_t st = sbase + (kc & 1) * SBYTES;
#pragma unroll
        for (int k16 = 0; k16 < 4; ++k16) {
            const uint32_t kOff = k16 * 32 + lc * 16;
            uint32_t ah[4][4], al[4][4];
#pragma unroll
            for (int mt = 0; mt < 4; ++mt) {
                int row = wm * 64 + mt * 16 + lr;
                uint32_t off = SW128((uint32_t)(row * 128) + kOff);
                LDSM_X4(ah[mt][0], ah[mt][1], ah[mt][2], ah[mt][3], st + off);
                if (NPASS == 3)
                    LDSM_X4(al[mt][0], al[mt][1], al[mt][2], al[mt][3],
                            st + OFF_AL2 + off);
            }
            uint32_t bh[2][4], bl[2][4];
#pragma unroll
            for (int ng = 0; ng < 2; ++ng) {
                int row = wn * 32 + ng * 16 + lr;
                uint32_t off = SW128((uint32_t)(row * 128) + kOff);
                LDSM_X4(bh[ng][0], bh[ng][1], bh[ng][2], bh[ng][3], st + OFF_BH2 + off);
                LDSM_X4(bl[ng][0], bl[ng][1], bl[ng][2], bl[ng][3], st + OFF_BL2 + off);
            }
#pragma unroll
            for (int mt = 0; mt < 4; ++mt)
#pragma unroll
                for (int nt = 0; nt < 4; ++nt) {
                    const int ng = nt >> 1, s = nt & 1;
                    MMA_BF16(acc[mt][nt], ah[mt], bh[ng][s], bh[ng][s + 2]);
                    MMA_BF16(acc[mt][nt], ah[mt], bl[ng][s], bl[ng][s + 2]);
                    if (NPASS == 3)
                        MMA_BF16(acc[mt][nt], al[mt], bh[ng][s], bh[ng][s + 2]);
                }
        }
        __syncthreads();
    }

    const int row0 = rowBase + wm * 64 + (lane >> 2);
    const int col0 = colBase + wn * 32 + ((lane & 3) << 1);
#pragma unroll
    for (int mt = 0; mt < 4; ++mt)
#pragma unroll
        for (int nt = 0; nt < 4; ++nt) {
            const int c = col0 + nt * 8;
            float v0 = acc[mt][nt][0], v1 = acc[mt][nt][1];
            float v2 = acc[mt][nt][2], v3 = acc[mt][nt][3];
            if (RELU) {
                float2 bb = *(const float2*)&bias[c];
                v0 = fmaxf(v0 + bb.x, 0.f); v1 = fmaxf(v1 + bb.y, 0.f);
                v2 = fmaxf(v2 + bb.x, 0.f); v3 = fmaxf(v3 + bb.y, 0.f);
            }
            const int r1 = row0 + mt * 16;
            const int r2 = r1 + 8;
            if (OUT == 0) {
                if (r1 < M) *(float2*)&Cf[(size_t)r1 * 256 + c] = make_float2(v0, v1);
                if (r2 < M) *(float2*)&Cf[(size_t)r2 * 256 + c] = make_float2(v2, v3);
            } else {
                __nv_bfloat162 h1, h2;
                h1.x = __float2bfloat16(v0); h1.y = __float2bfloat16(v1);
                h2.x = __float2bfloat16(v2); h2.y = __float2bfloat16(v3);
                if (r1 < M) *(__nv_bfloat162*)&Ch[(size_t)r1 * 256 + c] = h1;
                if (r2 < M) *(__nv_bfloat162*)&Ch[(size_t)r2 * 256 + c] = h2;
                if (OUT == 1) {
                    __nv_bfloat162 l1, l2;
                    l1.x = __float2bfloat16(v0 - __bfloat162float(h1.x));
                    l1.y = __float2bfloat16(v1 - __bfloat162float(h1.y));
                    l2.x = __float2bfloat16(v2 - __bfloat162float(h2.x));
                    l2.y = __float2bfloat16(v3 - __bfloat162float(h2.y));
                    if (r1 < M) *(__nv_bfloat162*)&Cl[(size_t)r1 * 256 + c] = l1;
                    if (r2 < M) *(__nv_bfloat162*)&Cl[(size_t)r2 * 256 + c] = l2;
                }
            }
        }
}

// ===========================================================================
// FUSED mix kernel: 512 threads / 16 warps (4 per SMSP) for issue throughput.
// Warp tile 32 rows x 64 cols; acc[2][8][4] = 64 regs.
// smem map (224KB) unchanged:
//   [0,64K)    EF chunks 0..3 (raw fp32 parked at [32K,48K) in prologue)
//   [64K,192K) W3 chunks 0..3 (fp16, resident)
//   [192K,224K) We (fp16)
// ===========================================================================
#define EF_CHUNK  16384
#define RAW_OFF   32768
#define W3_OFF    65536
#define W3_CHUNK  32768
#define WE_OFF    196608
#define MIX_SMEM  229376
#define EPI_STRIDE 260
#define MIX_THREADS 512

__global__ __launch_bounds__(MIX_THREADS)
void mix_fused_kernel(const float* __restrict__ EFraw,
                      const __half* __restrict__ We_,
                      const float* __restrict__ be,
                      const __half* __restrict__ W3_,
                      const float* __restrict__ bm,
                      const float* __restrict__ A1, const float* __restrict__ A2,
                      const int* __restrict__ idxn, const int* __restrict__ seg)
{
    extern __shared__ char smem[];
    const uint32_t sbase = smem_u32(smem);
    const int tid = threadIdx.x;
    const int wid = tid >> 5;
    const int lane = tid & 31;
    const int rowBase = blockIdx.x * 128;

    const int wm = wid >> 2;       // 0..3 (32-row band)
    const int wn = wid & 3;        // 0..3 (64-col band)
    const int lr = lane & 15;
    const int lc = lane >> 4;

    float acc[2][8][4];
#pragma unroll
    for (int mt = 0; mt < 2; ++mt)
#pragma unroll
        for (int nt = 0; nt < 8; ++nt)
#pragma unroll
            for (int q = 0; q < 4; ++q) acc[mt][nt][q] = 0.f;

    // ---- prologue: G0 = raw ef + We; G1..G4 = W3 chunks ----
#pragma unroll
    for (int l = 0; l < 2; ++l) {          // raw fp32: 128 rows x 128B, linear
        int idx = tid + l * MIX_THREADS;
        int r = idx >> 3, cc = idx & 7;
        CP_ASYNC16(sbase + RAW_OFF + (uint32_t)(r * 128 + cc * 16),
                   (const char*)(EFraw + (size_t)(rowBase + r) * 32) + cc * 16);
    }
#pragma unroll
    for (int l = 0; l < 4; ++l) {          // We: 256 rows x 128B
        int idx = tid + l * MIX_THREADS;
        int r = idx >> 3, cc = idx & 7;
        CP_ASYNC16(sbase + WE_OFF + SW128((uint32_t)(r * 128 + cc * 16)),
                   (const char*)(We_ + (size_t)r * 64) + cc * 16);
    }
    CP_COMMIT();                           // G0
#pragma unroll
    for (int kc = 0; kc < 4; ++kc) {       // W3 chunk kc: 256 rows x 128B
#pragma unroll
        for (int l = 0; l < 4; ++l) {
            int idx = tid + l * MIX_THREADS;
            int r = idx >> 3, cc = idx & 7;
            CP_ASYNC16(sbase + W3_OFF + kc * W3_CHUNK +
                           SW128((uint32_t)(r * 128 + cc * 16)),
                       (const char*)(W3_ + (size_t)r * 256 + kc * 64) + cc * 16);
        }
        CP_COMMIT();                       // G1..G4
    }

    CP_WAIT(4);                            // G0 done; W3 still streaming
    __syncthreads();

    // ---- convert raw fp32 -> EF-in fp16 (chunk0 region, zero-pad k>=32) ----
#pragma unroll
    for (int l = 0; l < 2; ++l) {
        int idx = tid + l * MIX_THREADS;
        int r = idx >> 3, s = idx & 7;
        uint32_t dst = (uint32_t)SW128((uint32_t)(r * 128 + s * 16));
        if (s < 4) {
            float4 f0 = *(const float4*)(smem + RAW_OFF + r * 128 + s * 32);
            float4 f1 = *(const float4*)(smem + RAW_OFF + r * 128 + s * 32 + 16);
            __half h[8];
            h[0] = __float2half_rn(f0.x); h[1] = __float2half_rn(f0.y);
            h[2] = __float2half_rn(f0.z); h[3] = __float2half_rn(f0.w);
            h[4] = __float2half_rn(f1.x); h[5] = __float2half_rn(f1.y);
            h[6] = __float2half_rn(f1.z); h[7] = __float2half_rn(f1.w);
            *(uint4*)(smem + dst) = *(uint4*)h;
        } else {
            *(uint4*)(smem + dst) = make_uint4(0, 0, 0, 0);
        }
    }
    __syncthreads();

    // ---- stage 1: EF = efin @ We^T (K=64, single pass) ----
    {
        const uint32_t stA = sbase;
        const uint32_t stB = sbase + WE_OFF;
#pragma unroll
        for (int k16 = 0; k16 < 4; ++k16) {
            const uint32_t kOff = k16 * 32 + lc * 16;
            uint32_t a[2][4];
#pragma unroll
            for (int mt = 0; mt < 2; ++mt) {
                int row = wm * 32 + mt * 16 + lr;
                LDSM_X4(a[mt][0], a[mt][1], a[mt][2], a[mt][3],
                        stA + SW128((uint32_t)(row * 128) + kOff));
            }
            uint32_t b[4][4];
#pragma unroll
            for (int ng = 0; ng < 4; ++ng) {
                int row = wn * 64 + ng * 16 + lr;
                LDSM_X4(b[ng][0], b[ng][1], b[ng][2], b[ng][3],
                        stB + SW128((uint32_t)(row * 128) + kOff));
            }
#pragma unroll
            for (int mt = 0; mt < 2; ++mt)
#pragma unroll
                for (int nt = 0; nt < 8; ++nt) {
                    const int ng = nt >> 1, s = nt & 1;
                    MMA_F16(acc[mt][nt], a[mt], b[ng][s], b[ng][s + 2]);
                }
        }
    }
    __syncthreads();   // all reads of efin done (chunk0 will be overwritten)

    // ---- EF store: bias + relu -> fp16 chunks ----
    {
        const int r0 = wm * 32 + (lane >> 2);
        const int c0 = wn * 64 + ((lane & 3) << 1);
#pragma unroll
        for (int mt = 0; mt < 2; ++mt)
#pragma unroll
            for (int nt = 0; nt < 8; ++nt) {
                const int c = c0 + nt * 8;
                float2 bb = *(const float2*)&be[c];
                float v0 = fmaxf(acc[mt][nt][0] + bb.x, 0.f);
                float v1 = fmaxf(acc[mt][nt][1] + bb.y, 0.f);
                float v2 = fmaxf(acc[mt][nt][2] + bb.x, 0.f);
                float v3 = fmaxf(acc[mt][nt][3] + bb.y, 0.f);
                __half p1[2], p2[2];
                p1[0] = __float2half_rn(v0); p1[1] = __float2half_rn(v1);
                p2[0] = __float2half_rn(v2); p2[1] = __float2half_rn(v3);
                const int chunk = c >> 6, cl2 = (c & 63) * 2;
                const int r1 = r0 + mt * 16, r2 = r1 + 8;
                *(uint32_t*)(smem + chunk * EF_CHUNK +
                    SW128((uint32_t)(r1 * 128 + cl2))) = *(uint32_t*)p1;
                *(uint32_t*)(smem + chunk * EF_CHUNK +
                    SW128((uint32_t)(r2 * 128 + cl2))) = *(uint32_t*)p2;
                acc[mt][nt][0] = 0.f; acc[mt][nt][1] = 0.f;
                acc[mt][nt][2] = 0.f; acc[mt][nt][3] = 0.f;
            }
    }
    __syncthreads();   // EF visible

    // ---- stage 2: T = EF @ W3^T, W3 fully resident, single pass ----
#pragma unroll
    for (int kc = 0; kc < 4; ++kc) {
        if      (kc == 0) CP_WAIT(3);
        else if (kc == 1) CP_WAIT(2);
        else if (kc == 2) CP_WAIT(1);
        else              CP_WAIT(0);
        __syncthreads();               // publish this W3 chunk

        const uint32_t stA = sbase + kc * EF_CHUNK;
        const uint32_t stB = sbase + W3_OFF + kc * W3_CHUNK;
#pragma unroll
        for (int k16 = 0; k16 < 4; ++k16) {
            const uint32_t kOff = k16 * 32 + lc * 16;
            uint32_t a[2][4];
#pragma unroll
            for (int mt = 0; mt < 2; ++mt) {
                int row = wm * 32 + mt * 16 + lr;
                LDSM_X4(a[mt][0], a[mt][1], a[mt][2], a[mt][3],
                        stA + SW128((uint32_t)(row * 128) + kOff));
            }
            uint32_t b[4][4];
#pragma unroll
            for (int ng = 0; ng < 4; ++ng) {
                int row = wn * 64 + ng * 16 + lr;
                LDSM_X4(b[ng][0], b[ng][1], b[ng][2], b[ng][3],
                        stB + SW128((uint32_t)(row * 128) + kOff));
            }
#pragma unroll
            for (int mt = 0; mt < 2; ++mt)
#pragma unroll
                for (int nt = 0; nt < 8; ++nt) {
                    const int ng = nt >> 1, s = nt & 1;
                    MMA_F16(acc[mt][nt], a[mt], b[ng][s], b[ng][s + 2]);
                }
        }
    }
    __syncthreads();   // all MMA/LDSM done before sC overlays smem

    // ---- fragments -> padded smem [128][EPI_STRIDE] fp32 ----
    float* sC = (float*)smem;
    {
        const int r0 = wm * 32 + (lane >> 2);
        const int c0 = wn * 64 + ((lane & 3) << 1);
#pragma unroll
        for (int mt = 0; mt < 2; ++mt)
#pragma unroll
            for (int nt = 0; nt < 8; ++nt) {
                int rr = r0 + mt * 16;
                int cc = c0 + nt * 8;
                *(float2*)&sC[rr * EPI_STRIDE + cc] =
                    make_float2(acc[mt][nt][0], acc[mt][nt][1]);
                *(float2*)&sC[(rr + 8) * EPI_STRIDE + cc] =
                    make_float2(acc[mt][nt][2], acc[mt][nt][3]);
            }
    }
    __syncthreads();

    // ---- row-oriented epilogue: 16 warps, each 32 rows x 64 cols ----
    const int wrow = (wid & 3) * 32 + lane;
    const int e = rowBase + wrow;
    const int i1 = idxn[e];
    const int i2 = seg[e];
    const int ch = (wid >> 2) * 64;

    int prevseg = __shfl_up_sync(0xFFFFFFFFu, i2, 1);
    bool head = (lane == 0) || (prevseg != i2);
    unsigned hm = __ballot_sync(0xFFFFFFFFu, head);
    unsigned rest = (lane < 31) ? (hm & (0xFFFFFFFEu << lane)) : 0u;
    int e_end = rest ? (__ffs(rest) - 2) : 31;
    float* srow = &g_sum[(size_t)i2 * 256];
    const float* a1row = &A1[(size_t)i1 * 256];
    const float* a2row = &A2[(size_t)i2 * 256];

#pragma unroll
    for (int g = 0; g < 16; ++g) {
        const int cb = ch + g * 4;
        float4 t  = *(const float4*)&sC[wrow * EPI_STRIDE + cb];
        float4 a1 = *(const float4*)&a1row[cb];
        float4 a2 = *(const float4*)&a2row[cb];
        float4 bv = *(const float4*)&bm[cb];
        float v[4];
        v[0] = fmaxf(t.x + a1.x + a2.x + bv.x, 0.f);
        v[1] = fmaxf(t.y + a1.y + a2.y + bv.y, 0.f);
        v[2] = fmaxf(t.z + a1.z + a2.z + bv.z, 0.f);
        v[3] = fmaxf(t.w + a1.w + a2.w + bv.w, 0.f);
#pragma unroll
        for (int j = 0; j < 4; ++j) {
            float x = v[j];
#pragma unroll
            for (int d2 = 1; d2 < 32; d2 <<= 1) {
                float o = __shfl_down_sync(0xFFFFFFFFu, x, d2);
                if (lane + d2 <= e_end) x += o;
            }
            if (head) atomicAdd(&srow[cb + j], x);
        }
    }
}

// ---------------- merged prep kernel (weights + input) --------------------
__global__ void prep_all(const float* __restrict__ input,
                         const float* __restrict__ Wn,
                         const float* __restrict__ Wm,
                         const float* __restrict__ We)
{
    int i = blockIdx.x * blockDim.x + threadIdx.x;
    if (i < NN * D) {
        float v = input[i];
        __nv_bfloat16 h = __float2bfloat16(v);
        g_in_h[i] = h;
        g_in_l[i] = __float2bfloat16(v - __bfloat162float(h));
    }
    if (i < 65536) {
        int n = i >> 8, k = i & 255;
        float w0 = Wn[k * 256 + n];
        float w1 = Wm[k * 256 + n];
        float w2 = Wm[(256 + k) * 256 + n];
        float w3 = Wm[(512 + k) * 256 + n];
        __nv_bfloat16 h;
        h = __float2bfloat16(w0); g_wnt_h[n * 256 + k] = h;
        g_wnt_l[n * 256 + k] = __float2bfloat16(w0 - __bfloat162float(h));
        h = __float2bfloat16(w1); g_wm1t_h[n * 256 + k] = h;
        g_wm1t_l[n * 256 + k] = __float2bfloat16(w1 - __bfloat162float(h));
        h = __float2bfloat16(w2); g_wm2t_h[n * 256 + k] = h;
        g_wm2t_l[n * 256 + k] = __float2bfloat16(w2 - __bfloat162float(h));
        g_wm3t[n * 256 + k] = __float2half_rn(w3);
        if (k < 64) {
            float we = (k < 32) ? We[k * 256 + n] : 0.f;
            g_wet[n * 64 + k] = __float2half_rn(we);
        }
    }
}

// grid = NN blocks of 256; counts via binary search on sorted seg;
// resets g_sum to 0 for the next replay (device globals start zeroed).
__global__ void final_kernel(const int* __restrict__ seg, float* __restrict__ out)
{
    __shared__ int s_cnt;
    const int n = blockIdx.x;
    if (threadIdx.x == 0) {
        int lo = 0, hi = NE;
        while (lo < hi) { int mid = (lo + hi) >> 1; if (seg[mid] <  n) lo = mid + 1; else hi = mid; }
        int lb = lo;
        lo = 0; hi = NE;
        while (lo < hi) { int mid = (lo + hi) >> 1; if (seg[mid] <= n) lo = mid + 1; else hi = mid; }
        s_cnt = lo - lb;
    }
    __syncthreads();
    const int c = s_cnt;
    const int i = n * 256 + threadIdx.x;
    float s = g_sum[i];
    out[i] = (c > 0) ? s / (float)c : 0.f;
    g_sum[i] = 0.f;
}

// ===========================================================================
extern "C" void kernel_launch(void* const* d_in, const int* in_sizes, int n_in,
                              void* d_out, int out_size)
{
    const float* input     = (const float*)d_in[0];
    const float* edgefeats = (const float*)d_in[1];
    const int*   idxn      = (const int*)  d_in[2];
    const int*   seg_ids   = (const int*)  d_in[3];
    const float* Wn        = (const float*)d_in[4];
    const float* bn        = (const float*)d_in[5];
    const float* We        = (const float*)d_in[6];
    const float* be        = (const float*)d_in[7];
    const float* Wm        = (const float*)d_in[8];
    const float* bm        = (const float*)d_in[9];
    float* out = (float*)d_out;

    float *p_A1, *p_A2;
    __nv_bfloat16 *p_inh, *p_inl, *p_nfh, *p_nfl;
    __nv_bfloat16 *p_wnth, *p_wntl, *p_w1h, *p_w1l, *p_w2h, *p_w2l;
    __half *p_w3, *p_we;
    cudaGetSymbolAddress((void**)&p_A1, g_A1);
    cudaGetSymbolAddress((void**)&p_A2, g_A2);
    cudaGetSymbolAddress((void**)&p_inh, g_in_h);
    cudaGetSymbolAddress((void**)&p_inl, g_in_l);
    cudaGetSymbolAddress((void**)&p_nfh, g_nf_h);
    cudaGetSymbolAddress((void**)&p_nfl, g_nf_l);
    cudaGetSymbolAddress((void**)&p_wnth, g_wnt_h);
    cudaGetSymbolAddress((void**)&p_wntl, g_wnt_l);
    cudaGetSymbolAddress((void**)&p_w1h, g_wm1t_h);
    cudaGetSymbolAddress((void**)&p_w1l, g_wm1t_l);
    cudaGetSymbolAddress((void**)&p_w2h, g_wm2t_h);
    cudaGetSymbolAddress((void**)&p_w2l, g_wm2t_l);
    cudaGetSymbolAddress((void**)&p_w3, g_wm3t);
    cudaGetSymbolAddress((void**)&p_we, g_wet);

    cudaFuncSetAttribute(mix_fused_kernel,
                         cudaFuncAttributeMaxDynamicSharedMemorySize, MIX_SMEM);
    cudaFuncSetAttribute(hmma_gemm<256, 3, true, 1>,
                         cudaFuncAttributeMaxDynamicSharedMemorySize, 131072);
    cudaFuncSetAttribute(hmma_gemm<256, 3, false, 0>,
                         cudaFuncAttributeMaxDynamicSharedMemorySize, 131072);

    prep_all<<<(NN * D + 255) / 256, 256>>>(input, Wn, Wm, We);

    {
        dim3 g((NN + 127) / 128, 2);
        hmma_gemm<256, 3, true, 1><<<g, 256, 131072>>>(
            p_inh, p_inl, p_wnth, p_wntl, bn, nullptr, p_nfh, p_nfl, NN);
        hmma_gemm<256, 3, false, 0><<<g, 256, 131072>>>(
            p_nfh, p_nfl, p_w1h, p_w1l, nullptr, p_A1, nullptr, nullptr, NN);
        hmma_gemm<256, 3, false, 0><<<g, 256, 131072>>>(
            p_nfh, p_nfl, p_w2h, p_w2l, nullptr, p_A2, nullptr, nullptr, NN);
    }
    mix_fused_kernel<<<NE / 128, MIX_THREADS, MIX_SMEM>>>(
        edgefeats, p_we, be, p_w3, bm, p_A1, p_A2, idxn, seg_ids);

    final_kernel<<<NN, 256>>>(seg_ids, out);
}

// round 13
// speedup vs baseline: 3.1533x; 1.2977x over previous
#include <cuda_runtime.h>
#include <cuda_bf16.h>
#include <cuda_fp16.h>
#include <cstdint>

#define NN 10000
#define NE 320000
#define D  256

// ---------------- scratch (device globals; no allocation allowed) ----------
__device__ __align__(256) float g_A1[NN * D];
__device__ __align__(256) float g_A2[NN * D];
__device__ __align__(256) float g_sum[NN * D];   // zero-init at load; self-resetting

__device__ __align__(256) __nv_bfloat16 g_in_h[NN * D];
__device__ __align__(256) __nv_bfloat16 g_in_l[NN * D];
__device__ __align__(256) __nv_bfloat16 g_nf_h[NN * D];
__device__ __align__(256) __nv_bfloat16 g_nf_l[NN * D];

__device__ __align__(256) __nv_bfloat16 g_wnt_h[D * D],  g_wnt_l[D * D];
__device__ __align__(256) __nv_bfloat16 g_wm1t_h[D * D], g_wm1t_l[D * D];
__device__ __align__(256) __nv_bfloat16 g_wm2t_h[D * D], g_wm2t_l[D * D];
__device__ __align__(256) __half g_wm3t[D * D];          // Wm3^T fp16 [N][K]
__device__ __align__(256) __half g_wet[D * 64];          // We^T fp16 [N][64]

// =============================== PTX helpers ===============================
__device__ __forceinline__ uint32_t smem_u32(const void* p) {
    uint32_t a;
    asm("{ .reg .u64 t; cvta.to.shared.u64 t, %1; cvt.u32.u64 %0, t; }"
        : "=r"(a) : "l"(p));
    return a;
}
#define SW128(off) ((off) ^ (((off) >> 3) & 0x70))

#define CP_ASYNC16(dst, src) \
    asm volatile("cp.async.cg.shared.global [%0], [%1], 16;" \
        :: "r"(dst), "l"(src) : "memory")
#define CP_ASYNC16Z(dst, src, sz) \
    asm volatile("cp.async.cg.shared.global [%0], [%1], 16, %2;" \
        :: "r"(dst), "l"(src), "r"(sz) : "memory")
#define CP_COMMIT() asm volatile("cp.async.commit_group;" ::: "memory")
#define CP_WAIT(n)  asm volatile("cp.async.wait_group %0;" :: "n"(n) : "memory")

#define LDSM_X4(r0, r1, r2, r3, addr) \
    asm volatile("ldmatrix.sync.aligned.m8n8.x4.shared.b16 {%0,%1,%2,%3}, [%4];" \
        : "=r"(r0), "=r"(r1), "=r"(r2), "=r"(r3) : "r"(addr))

#define MMA_BF16(c, a, b0, b1) \
    asm volatile("mma.sync.aligned.m16n8k16.row.col.f32.bf16.bf16.f32 " \
        "{%0,%1,%2,%3}, {%4,%5,%6,%7}, {%8,%9}, {%0,%1,%2,%3};" \
        : "+f"((c)[0]), "+f"((c)[1]), "+f"((c)[2]), "+f"((c)[3]) \
        : "r"((a)[0]), "r"((a)[1]), "r"((a)[2]), "r"((a)[3]), "r"(b0), "r"(b1))

#define MMA_F16(c, a, b0, b1) \
    asm volatile("mma.sync.aligned.m16n8k16.row.col.f32.f16.f16.f32 " \
        "{%0,%1,%2,%3}, {%4,%5,%6,%7}, {%8,%9}, {%0,%1,%2,%3};" \
        : "+f"((c)[0]), "+f"((c)[1]), "+f"((c)[2]), "+f"((c)[3]) \
        : "r"((a)[0]), "r"((a)[1]), "r"((a)[2]), "r"((a)[3]), "r"(b0), "r"(b1))

// ===========================================================================
// Unified HMMA GEMM for node-side (unchanged, proven): C[M,256]
// ===========================================================================
template<int KDIM, int NPASS, bool RELU, int OUT>
__global__ __launch_bounds__(256)
void hmma_gemm(const __nv_bfloat16* __restrict__ Ah,
               const __nv_bfloat16* __restrict__ Al,
               const __nv_bfloat16* __restrict__ Bh_,
               const __nv_bfloat16* __restrict__ Bl_,
               const float* __restrict__ bias,
               float* __restrict__ Cf,
               __nv_bfloat16* __restrict__ Ch,
               __nv_bfloat16* __restrict__ Cl,
               int M)
{
    constexpr int OFF_AL2 = 16384;
    constexpr int OFF_BH2 = (NPASS == 3) ? 32768 : 16384;
    constexpr int OFF_BL2 = OFF_BH2 + 16384;
    constexpr int SBYTES  = OFF_BL2 + 16384;
    constexpr int NKC     = KDIM / 64;

    extern __shared__ char smem[];
    const uint32_t sbase = smem_u32(smem);
    const int tid = threadIdx.x;
    const int wid = tid >> 5;
    const int lane = tid & 31;
    const int rowBase = blockIdx.x * 128;
    const int colBase = blockIdx.y * 128;

    const int wm = wid >> 2;
    const int wn = wid & 3;
    const int lr = lane & 15;
    const int lc = lane >> 4;

    float acc[4][4][4];
#pragma unroll
    for (int mt = 0; mt < 4; ++mt)
#pragma unroll
        for (int nt = 0; nt < 4; ++nt)
#pragma unroll
            for (int q = 0; q < 4; ++q) acc[mt][nt][q] = 0.f;

    auto load_stage = [&](int buf, int kc) {
        const uint32_t st = sbase + buf * SBYTES;
        const int kBase = kc * 64;
#pragma unroll
        for (int l = 0; l < 4; ++l) {
            int idx = tid + l * 256;
            int r = idx >> 3, cc = idx & 7;
            int gr = rowBase + r;
            uint32_t sz = (gr < M) ? 16u : 0u;
            int grc = (gr < M) ? gr : (M - 1);
            uint32_t doff = SW128((uint32_t)(r * 128 + cc * 16));
            const char* sh = (const char*)(Ah + (size_t)grc * KDIM + kBase) + cc * 16;
            CP_ASYNC16Z(st + doff, sh, sz);
            if (NPASS == 3) {
                const char* sl = (const char*)(Al + (size_t)grc * KDIM + kBase) + cc * 16;
                CP_ASYNC16Z(st + OFF_AL2 + doff, sl, sz);
            }
        }
#pragma unroll
        for (int l = 0; l < 4; ++l) {
            int idx = tid + l * 256;
            int r = idx >> 3, cc = idx & 7;
            uint32_t doff = SW128((uint32_t)(r * 128 + cc * 16));
            const char* sh = (const char*)(Bh_ + (size_t)(colBase + r) * KDIM + kBase) + cc * 16;
            const char* sl = (const char*)(Bl_ + (size_t)(colBase + r) * KDIM + kBase) + cc * 16;
            CP_ASYNC16(st + OFF_BH2 + doff, sh);
            CP_ASYNC16(st + OFF_BL2 + doff, sl);
        }
    };

    load_stage(0, 0);
    CP_COMMIT();

    for (int kc = 0; kc < NKC; ++kc) {
        if (kc + 1 < NKC) {
            load_stage((kc + 1) & 1, kc + 1);
            CP_COMMIT();
            CP_WAIT(1);
        } else {
            CP_WAIT(0);
        }
        __syncthreads();

        const uint32_t st = sbase + (kc & 1) * SBYTES;
#pragma unroll
        for (int k16 = 0; k16 < 4; ++k16) {
            const uint32_t kOff = k16 * 32 + lc * 16;
            uint32_t ah[4][4], al[4][4];
#pragma unroll
            for (int mt = 0; mt < 4; ++mt) {
                int row = wm * 64 + mt * 16 + lr;
                uint32_t off = SW128((uint32_t)(row * 128) + kOff);
                LDSM_X4(ah[mt][0], ah[mt][1], ah[mt][2], ah[mt][3], st + off);
                if (NPASS == 3)
                    LDSM_X4(al[mt][0], al[mt][1], al[mt][2], al[mt][3],
                            st + OFF_AL2 + off);
            }
            uint32_t bh[2][4], bl[2][4];
#pragma unroll
            for (int ng = 0; ng < 2; ++ng) {
                int row = wn * 32 + ng * 16 + lr;
                uint32_t off = SW128((uint32_t)(row * 128) + kOff);
                LDSM_X4(bh[ng][0], bh[ng][1], bh[ng][2], bh[ng][3], st + OFF_BH2 + off);
                LDSM_X4(bl[ng][0], bl[ng][1], bl[ng][2], bl[ng][3], st + OFF_BL2 + off);
            }
#pragma unroll
            for (int mt = 0; mt < 4; ++mt)
#pragma unroll
                for (int nt = 0; nt < 4; ++nt) {
                    const int ng = nt >> 1, s = nt & 1;
                    MMA_BF16(acc[mt][nt], ah[mt], bh[ng][s], bh[ng][s + 2]);
                    MMA_BF16(acc[mt][nt], ah[mt], bl[ng][s], bl[ng][s + 2]);
                    if (NPASS == 3)
                        MMA_BF16(acc[mt][nt], al[mt], bh[ng][s], bh[ng][s + 2]);
                }
        }
        __syncthreads();
    }

    const int row0 = rowBase + wm * 64 + (lane >> 2);
    const int col0 = colBase + wn * 32 + ((lane & 3) << 1);
#pragma unroll
    for (int mt = 0; mt < 4; ++mt)
#pragma unroll
        for (int nt = 0; nt < 4; ++nt) {
            const int c = col0 + nt * 8;
            float v0 = acc[mt][nt][0], v1 = acc[mt][nt][1];
            float v2 = acc[mt][nt][2], v3 = acc[mt][nt][3];
            if (RELU) {
                float2 bb = *(const float2*)&bias[c];
                v0 = fmaxf(v0 + bb.x, 0.f); v1 = fmaxf(v1 + bb.y, 0.f);
                v2 = fmaxf(v2 + bb.x, 0.f); v3 = fmaxf(v3 + bb.y, 0.f);
            }
            const int r1 = row0 + mt * 16;
            const int r2 = r1 + 8;
            if (OUT == 0) {
                if (r1 < M) *(float2*)&Cf[(size_t)r1 * 256 + c] = make_float2(v0, v1);
                if (r2 < M) *(float2*)&Cf[(size_t)r2 * 256 + c] = make_float2(v2, v3);
            } else {
                __nv_bfloat162 h1, h2;
                h1.x = __float2bfloat16(v0); h1.y = __float2bfloat16(v1);
                h2.x = __float2bfloat16(v2); h2.y = __float2bfloat16(v3);
                if (r1 < M) *(__nv_bfloat162*)&Ch[(size_t)r1 * 256 + c] = h1;
                if (r2 < M) *(__nv_bfloat162*)&Ch[(size_t)r2 * 256 + c] = h2;
                if (OUT == 1) {
                    __nv_bfloat162 l1, l2;
                    l1.x = __float2bfloat16(v0 - __bfloat162float(h1.x));
                    l1.y = __float2bfloat16(v1 - __bfloat162float(h1.y));
                    l2.x = __float2bfloat16(v2 - __bfloat162float(h2.x));
                    l2.y = __float2bfloat16(v3 - __bfloat162float(h2.y));
                    if (r1 < M) *(__nv_bfloat162*)&Cl[(size_t)r1 * 256 + c] = l1;
                    if (r2 < M) *(__nv_bfloat162*)&Cl[(size_t)r2 * 256 + c] = l2;
                }
            }
        }
}

// ===========================================================================
// FUSED mix kernel: 512 threads / 16 warps; fp16 single-pass; W3 resident.
// Edge-major epilogue: warp = 8 consecutive edges, lane = 8 columns ->
// fully coalesced A1/A2 row gathers, register run-compression over sorted
// seg ids (no shuffles), coalesced atomic flushes.
// ===========================================================================
#define EF_CHUNK  16384
#define RAW_OFF   32768
#define W3_OFF    65536
#define W3_CHUNK  32768
#define WE_OFF    196608
#define MIX_SMEM  229376
#define EPI_STRIDE 260
#define MIX_THREADS 512

__global__ __launch_bounds__(MIX_THREADS)
void mix_fused_kernel(const float* __restrict__ EFraw,
                      const __half* __restrict__ We_,
                      const float* __restrict__ be,
                      const __half* __restrict__ W3_,
                      const float* __restrict__ bm,
                      const float* __restrict__ A1, const float* __restrict__ A2,
                      const int* __restrict__ idxn, const int* __restrict__ seg)
{
    extern __shared__ char smem[];
    const uint32_t sbase = smem_u32(smem);
    const int tid = threadIdx.x;
    const int wid = tid >> 5;
    const int lane = tid & 31;
    const int rowBase = blockIdx.x * 128;

    const int wm = wid >> 2;       // 0..3 (32-row band)
    const int wn = wid & 3;        // 0..3 (64-col band)
    const int lr = lane & 15;
    const int lc = lane >> 4;

    float acc[2][8][4];
#pragma unroll
    for (int mt = 0; mt < 2; ++mt)
#pragma unroll
        for (int nt = 0; nt < 8; ++nt)
#pragma unroll
            for (int q = 0; q < 4; ++q) acc[mt][nt][q] = 0.f;

    // ---- prologue: G0 = raw ef + We; G1..G4 = W3 chunks ----
#pragma unroll
    for (int l = 0; l < 2; ++l) {          // raw fp32: 128 rows x 128B, linear
        int idx = tid + l * MIX_THREADS;
        int r = idx >> 3, cc = idx & 7;
        CP_ASYNC16(sbase + RAW_OFF + (uint32_t)(r * 128 + cc * 16),
                   (const char*)(EFraw + (size_t)(rowBase + r) * 32) + cc * 16);
    }
#pragma unroll
    for (int l = 0; l < 4; ++l) {          // We: 256 rows x 128B
        int idx = tid + l * MIX_THREADS;
        int r = idx >> 3, cc = idx & 7;
        CP_ASYNC16(sbase + WE_OFF + SW128((uint32_t)(r * 128 + cc * 16)),
                   (const char*)(We_ + (size_t)r * 64) + cc * 16);
    }
    CP_COMMIT();                           // G0
#pragma unroll
    for (int kc = 0; kc < 4; ++kc) {       // W3 chunk kc: 256 rows x 128B
#pragma unroll
        for (int l = 0; l < 4; ++l) {
            int idx = tid + l * MIX_THREADS;
            int r = idx >> 3, cc = idx & 7;
            CP_ASYNC16(sbase + W3_OFF + kc * W3_CHUNK +
                           SW128((uint32_t)(r * 128 + cc * 16)),
                       (const char*)(W3_ + (size_t)r * 256 + kc * 64) + cc * 16);
        }
        CP_COMMIT();                       // G1..G4
    }

    CP_WAIT(4);                            // G0 done; W3 still streaming
    __syncthreads();

    // ---- convert raw fp32 -> EF-in fp16 (chunk0 region, zero-pad k>=32) ----
#pragma unroll
    for (int l = 0; l < 2; ++l) {
        int idx = tid + l * MIX_THREADS;
        int r = idx >> 3, s = idx & 7;
        uint32_t dst = (uint32_t)SW128((uint32_t)(r * 128 + s * 16));
        if (s < 4) {
            float4 f0 = *(const float4*)(smem + RAW_OFF + r * 128 + s * 32);
            float4 f1 = *(const float4*)(smem + RAW_OFF + r * 128 + s * 32 + 16);
            __half h[8];
            h[0] = __float2half_rn(f0.x); h[1] = __float2half_rn(f0.y);
            h[2] = __float2half_rn(f0.z); h[3] = __float2half_rn(f0.w);
            h[4] = __float2half_rn(f1.x); h[5] = __float2half_rn(f1.y);
            h[6] = __float2half_rn(f1.z); h[7] = __float2half_rn(f1.w);
            *(uint4*)(smem + dst) = *(uint4*)h;
        } else {
            *(uint4*)(smem + dst) = make_uint4(0, 0, 0, 0);
        }
    }
    __syncthreads();

    // ---- stage 1: EF = efin @ We^T (K=64, single pass) ----
    {
        const uint32_t stA = sbase;
        const uint32_t stB = sbase + WE_OFF;
#pragma unroll
        for (int k16 = 0; k16 < 4; ++k16) {
            const uint32_t kOff = k16 * 32 + lc * 16;
            uint32_t a[2][4];
#pragma unroll
            for (int mt = 0; mt < 2; ++mt) {
                int row = wm * 32 + mt * 16 + lr;
                LDSM_X4(a[mt][0], a[mt][1], a[mt][2], a[mt][3],
                        stA + SW128((uint32_t)(row * 128) + kOff));
            }
            uint32_t b[4][4];
#pragma unroll
            for (int ng = 0; ng < 4; ++ng) {
                int row = wn * 64 + ng * 16 + lr;
                LDSM_X4(b[ng][0], b[ng][1], b[ng][2], b[ng][3],
                        stB + SW128((uint32_t)(row * 128) + kOff));
            }
#pragma unroll
            for (int mt = 0; mt < 2; ++mt)
#pragma unroll
                for (int nt = 0; nt < 8; ++nt) {
                    const int ng = nt >> 1, s = nt & 1;
                    MMA_F16(acc[mt][nt], a[mt], b[ng][s], b[ng][s + 2]);
                }
        }
    }
    __syncthreads();   // all reads of efin done (chunk0 will be overwritten)

    // ---- EF store: bias + relu -> fp16 chunks ----
    {
        const int r0 = wm * 32 + (lane >> 2);
        const int c0 = wn * 64 + ((lane & 3) << 1);
#pragma unroll
        for (int mt = 0; mt < 2; ++mt)
#pragma unroll
            for (int nt = 0; nt < 8; ++nt) {
                const int c = c0 + nt * 8;
                float2 bb = *(const float2*)&be[c];
                float v0 = fmaxf(acc[mt][nt][0] + bb.x, 0.f);
                float v1 = fmaxf(acc[mt][nt][1] + bb.y, 0.f);
                float v2 = fmaxf(acc[mt][nt][2] + bb.x, 0.f);
                float v3 = fmaxf(acc[mt][nt][3] + bb.y, 0.f);
                __half p1[2], p2[2];
                p1[0] = __float2half_rn(v0); p1[1] = __float2half_rn(v1);
                p2[0] = __float2half_rn(v2); p2[1] = __float2half_rn(v3);
                const int chunk = c >> 6, cl2 = (c & 63) * 2;
                const int r1 = r0 + mt * 16, r2 = r1 + 8;
                *(uint32_t*)(smem + chunk * EF_CHUNK +
                    SW128((uint32_t)(r1 * 128 + cl2))) = *(uint32_t*)p1;
                *(uint32_t*)(smem + chunk * EF_CHUNK +
                    SW128((uint32_t)(r2 * 128 + cl2))) = *(uint32_t*)p2;
                acc[mt][nt][0] = 0.f; acc[mt][nt][1] = 0.f;
                acc[mt][nt][2] = 0.f; acc[mt][nt][3] = 0.f;
            }
    }
    __syncthreads();   // EF visible

    // ---- stage 2: T = EF @ W3^T, W3 fully resident, single pass ----
#pragma unroll
    for (int kc = 0; kc < 4; ++kc) {
        if      (kc == 0) CP_WAIT(3);
        else if (kc == 1) CP_WAIT(2);
        else if (kc == 2) CP_WAIT(1);
        else              CP_WAIT(0);
        __syncthreads();               // publish this W3 chunk

        const uint32_t stA = sbase + kc * EF_CHUNK;
        const uint32_t stB = sbase + W3_OFF + kc * W3_CHUNK;
#pragma unroll
        for (int k16 = 0; k16 < 4; ++k16) {
            const uint32_t kOff = k16 * 32 + lc * 16;
            uint32_t a[2][4];
#pragma unroll
            for (int mt = 0; mt < 2; ++mt) {
                int row = wm * 32 + mt * 16 + lr;
                LDSM_X4(a[mt][0], a[mt][1], a[mt][2], a[mt][3],
                        stA + SW128((uint32_t)(row * 128) + kOff));
            }
            uint32_t b[4][4];
#pragma unroll
            for (int ng = 0; ng < 4; ++ng) {
                int row = wn * 64 + ng * 16 + lr;
                LDSM_X4(b[ng][0], b[ng][1], b[ng][2], b[ng][3],
                        stB + SW128((uint32_t)(row * 128) + kOff));
            }
#pragma unroll
            for (int mt = 0; mt < 2; ++mt)
#pragma unroll
                for (int nt = 0; nt < 8; ++nt) {
                    const int ng = nt >> 1, s = nt & 1;
                    MMA_F16(acc[mt][nt], a[mt], b[ng][s], b[ng][s + 2]);
                }
        }
    }
    __syncthreads();   // all MMA/LDSM done before sC overlays smem

    // ---- fragments -> padded smem [128][EPI_STRIDE] fp32 ----
    float* sC = (float*)smem;
    {
        const int r0 = wm * 32 + (lane >> 2);
        const int c0 = wn * 64 + ((lane & 3) << 1);
#pragma unroll
        for (int mt = 0; mt < 2; ++mt)
#pragma unroll
            for (int nt = 0; nt < 8; ++nt) {
                int rr = r0 + mt * 16;
                int cc = c0 + nt * 8;
                *(float2*)&sC[rr * EPI_STRIDE + cc] =
                    make_float2(acc[mt][nt][0], acc[mt][nt][1]);
                *(float2*)&sC[(rr + 8) * EPI_STRIDE + cc] =
                    make_float2(acc[mt][nt][2], acc[mt][nt][3]);
            }
    }
    __syncthreads();

    // ---- edge-major epilogue: warp = 8 consecutive edges, lane = 8 cols ----
    {
        const int cb = lane * 8;                 // this lane's 8 columns
        float bv[8];
        *(float4*)&bv[0] = *(const float4*)&bm[cb];
        *(float4*)&bv[4] = *(const float4*)&bm[cb + 4];

        const int e0 = rowBase + wid * 8;
        float racc[8];
#pragma unroll
        for (int j = 0; j < 8; ++j) racc[j] = 0.f;
        int rseg = __ldg(&seg[e0]);

#pragma unroll
        for (int i = 0; i < 8; ++i) {
            const int e = e0 + i;
            const int i1 = __ldg(&idxn[e]);
            const int i2 = __ldg(&seg[e]);
            const float* tr = &sC[(wid * 8 + i) * EPI_STRIDE + cb];
            float4 t0 = *(const float4*)&tr[0];
            float4 t1 = *(const float4*)&tr[4];
            float4 a10 = *(const float4*)&A1[(size_t)i1 * 256 + cb];
            float4 a11 = *(const float4*)&A1[(size_t)i1 * 256 + cb + 4];
            float4 a20 = *(const float4*)&A2[(size_t)i2 * 256 + cb];
            float4 a21 = *(const float4*)&A2[(size_t)i2 * 256 + cb + 4];
            float v[8];
            v[0] = fmaxf(t0.x + a10.x + a20.x + bv[0], 0.f);
            v[1] = fmaxf(t0.y + a10.y + a20.y + bv[1], 0.f);
            v[2] = fmaxf(t0.z + a10.z + a20.z + bv[2], 0.f);
            v[3] = fmaxf(t0.w + a10.w + a20.w + bv[3], 0.f);
            v[4] = fmaxf(t1.x + a11.x + a21.x + bv[4], 0.f);
            v[5] = fmaxf(t1.y + a11.y + a21.y + bv[5], 0.f);
            v[6] = fmaxf(t1.z + a11.z + a21.z + bv[6], 0.f);
            v[7] = fmaxf(t1.w + a11.w + a21.w + bv[7], 0.f);

            if (i2 != rseg) {
                float* srow = &g_sum[(size_t)rseg * 256 + cb];
#pragma unroll
                for (int j = 0; j < 8; ++j) atomicAdd(&srow[j], racc[j]);
                rseg = i2;
#pragma unroll
                for (int j = 0; j < 8; ++j) racc[j] = v[j];
            } else {
#pragma unroll
                for (int j = 0; j < 8; ++j) racc[j] += v[j];
            }
        }
        float* srow = &g_sum[(size_t)rseg * 256 + cb];
#pragma unroll
        for (int j = 0; j < 8; ++j) atomicAdd(&srow[j], racc[j]);
    }
}

// ---------------- merged prep kernel (weights + input) --------------------
__global__ void prep_all(const float* __restrict__ input,
                         const float* __restrict__ Wn,
                         const float* __restrict__ Wm,
                         const float* __restrict__ We)
{
    int i = blockIdx.x * blockDim.x + threadIdx.x;
    if (i < NN * D) {
        float v = input[i];
        __nv_bfloat16 h = __float2bfloat16(v);
        g_in_h[i] = h;
        g_in_l[i] = __float2bfloat16(v - __bfloat162float(h));
    }
    if (i < 65536) {
        int n = i >> 8, k = i & 255;
        float w0 = Wn[k * 256 + n];
        float w1 = Wm[k * 256 + n];
        float w2 = Wm[(256 + k) * 256 + n];
        float w3 = Wm[(512 + k) * 256 + n];
        __nv_bfloat16 h;
        h = __float2bfloat16(w0); g_wnt_h[n * 256 + k] = h;
        g_wnt_l[n * 256 + k] = __float2bfloat16(w0 - __bfloat162float(h));
        h = __float2bfloat16(w1); g_wm1t_h[n * 256 + k] = h;
        g_wm1t_l[n * 256 + k] = __float2bfloat16(w1 - __bfloat162float(h));
        h = __float2bfloat16(w2); g_wm2t_h[n * 256 + k] = h;
        g_wm2t_l[n * 256 + k] = __float2bfloat16(w2 - __bfloat162float(h));
        g_wm3t[n * 256 + k] = __float2half_rn(w3);
        if (k < 64) {
            float we = (k < 32) ? We[k * 256 + n] : 0.f;
            g_wet[n * 64 + k] = __float2half_rn(we);
        }
    }
}

// grid = NN blocks of 256; counts via binary search on sorted seg;
// resets g_sum to 0 for the next replay (device globals start zeroed).
__global__ void final_kernel(const int* __restrict__ seg, float* __restrict__ out)
{
    __shared__ int s_cnt;
    const int n = blockIdx.x;
    if (threadIdx.x == 0) {
        int lo = 0, hi = NE;
        while (lo < hi) { int mid = (lo + hi) >> 1; if (seg[mid] <  n) lo = mid + 1; else hi = mid; }
        int lb = lo;
        lo = 0; hi = NE;
        while (lo < hi) { int mid = (lo + hi) >> 1; if (seg[mid] <= n) lo = mid + 1; else hi = mid; }
        s_cnt = lo - lb;
    }
    __syncthreads();
    const int c = s_cnt;
    const int i = n * 256 + threadIdx.x;
    float s = g_sum[i];
    out[i] = (c > 0) ? s / (float)c : 0.f;
    g_sum[i] = 0.f;
}

// ===========================================================================
extern "C" void kernel_launch(void* const* d_in, const int* in_sizes, int n_in,
                              void* d_out, int out_size)
{
    const float* input     = (const float*)d_in[0];
    const float* edgefeats = (const float*)d_in[1];
    const int*   idxn      = (const int*)  d_in[2];
    const int*   seg_ids   = (const int*)  d_in[3];
    const float* Wn        = (const float*)d_in[4];
    const float* bn        = (const float*)d_in[5];
    const float* We        = (const float*)d_in[6];
    const float* be        = (const float*)d_in[7];
    const float* Wm        = (const float*)d_in[8];
    const float* bm        = (const float*)d_in[9];
    float* out = (float*)d_out;

    float *p_A1, *p_A2;
    __nv_bfloat16 *p_inh, *p_inl, *p_nfh, *p_nfl;
    __nv_bfloat16 *p_wnth, *p_wntl, *p_w1h, *p_w1l, *p_w2h, *p_w2l;
    __half *p_w3, *p_we;
    cudaGetSymbolAddress((void**)&p_A1, g_A1);
    cudaGetSymbolAddress((void**)&p_A2, g_A2);
    cudaGetSymbolAddress((void**)&p_inh, g_in_h);
    cudaGetSymbolAddress((void**)&p_inl, g_in_l);
    cudaGetSymbolAddress((void**)&p_nfh, g_nf_h);
    cudaGetSymbolAddress((void**)&p_nfl, g_nf_l);
    cudaGetSymbolAddress((void**)&p_wnth, g_wnt_h);
    cudaGetSymbolAddress((void**)&p_wntl, g_wnt_l);
    cudaGetSymbolAddress((void**)&p_w1h, g_wm1t_h);
    cudaGetSymbolAddress((void**)&p_w1l, g_wm1t_l);
    cudaGetSymbolAddress((void**)&p_w2h, g_wm2t_h);
    cudaGetSymbolAddress((void**)&p_w2l, g_wm2t_l);
    cudaGetSymbolAddress((void**)&p_w3, g_wm3t);
    cudaGetSymbolAddress((void**)&p_we, g_wet);

    cudaFuncSetAttribute(mix_fused_kernel,
                         cudaFuncAttributeMaxDynamicSharedMemorySize, MIX_SMEM);
    cudaFuncSetAttribute(hmma_gemm<256, 3, true, 1>,
                         cudaFuncAttributeMaxDynamicSharedMemorySize, 131072);
    cudaFuncSetAttribute(hmma_gemm<256, 3, false, 0>,
                         cudaFuncAttributeMaxDynamicSharedMemorySize, 131072);

    prep_all<<<(NN * D + 255) / 256, 256>>>(input, Wn, Wm, We);

    {
        dim3 g((NN + 127) / 128, 2);
        hmma_gemm<256, 3, true, 1><<<g, 256, 131072>>>(
            p_inh, p_inl, p_wnth, p_wntl, bn, nullptr, p_nfh, p_nfl, NN);
        hmma_gemm<256, 3, false, 0><<<g, 256, 131072>>>(
            p_nfh, p_nfl, p_w1h, p_w1l, nullptr, p_A1, nullptr, nullptr, NN);
        hmma_gemm<256, 3, false, 0><<<g, 256, 131072>>>(
            p_nfh, p_nfl, p_w2h, p_w2l, nullptr, p_A2, nullptr, nullptr, NN);
    }
    mix_fused_kernel<<<NE / 128, MIX_THREADS, MIX_SMEM>>>(
        edgefeats, p_we, be, p_w3, bm, p_A1, p_A2, idxn, seg_ids);

    final_kernel<<<NN, 256>>>(seg_ids, out);
}

// round 14
// speedup vs baseline: 3.4768x; 1.1026x over previous
#include <cuda_runtime.h>
#include <cuda_fp16.h>
#include <cstdint>

#define NN 10000
#define NE 320000
#define D  256

// ---------------- scratch (device globals; no allocation allowed) ----------
__device__ __align__(256) __half g_A1[NN * D];
__device__ __align__(256) __half g_A2[NN * D];
__device__ __align__(256) float g_sum[NN * D];   // zero-init at load; self-resetting

__device__ __align__(256) __half g_in[NN * D];
__device__ __align__(256) __half g_nf[NN * D];

__device__ __align__(256) __half g_wnt_h[D * D],  g_wnt_l[D * D];
__device__ __align__(256) __half g_wm1t_h[D * D], g_wm1t_l[D * D];
__device__ __align__(256) __half g_wm2t_h[D * D], g_wm2t_l[D * D];
__device__ __align__(256) __half g_wm3t[D * D];          // Wm3^T fp16 [N][K]
__device__ __align__(256) __half g_wet[D * 64];          // We^T fp16 [N][64]

// =============================== PTX helpers ===============================
__device__ __forceinline__ uint32_t smem_u32(const void* p) {
    uint32_t a;
    asm("{ .reg .u64 t; cvta.to.shared.u64 t, %1; cvt.u32.u64 %0, t; }"
        : "=r"(a) : "l"(p));
    return a;
}
#define SW128(off) ((off) ^ (((off) >> 3) & 0x70))

#define CP_ASYNC16(dst, src) \
    asm volatile("cp.async.cg.shared.global [%0], [%1], 16;" \
        :: "r"(dst), "l"(src) : "memory")
#define CP_ASYNC16Z(dst, src, sz) \
    asm volatile("cp.async.cg.shared.global [%0], [%1], 16, %2;" \
        :: "r"(dst), "l"(src), "r"(sz) : "memory")
#define CP_COMMIT() asm volatile("cp.async.commit_group;" ::: "memory")
#define CP_WAIT(n)  asm volatile("cp.async.wait_group %0;" :: "n"(n) : "memory")

#define LDSM_X4(r0, r1, r2, r3, addr) \
    asm volatile("ldmatrix.sync.aligned.m8n8.x4.shared.b16 {%0,%1,%2,%3}, [%4];" \
        : "=r"(r0), "=r"(r1), "=r"(r2), "=r"(r3) : "r"(addr))

#define MMA_F16(c, a, b0, b1) \
    asm volatile("mma.sync.aligned.m16n8k16.row.col.f32.f16.f16.f32 " \
        "{%0,%1,%2,%3}, {%4,%5,%6,%7}, {%8,%9}, {%0,%1,%2,%3};" \
        : "+f"((c)[0]), "+f"((c)[1]), "+f"((c)[2]), "+f"((c)[3]) \
        : "r"((a)[0]), "r"((a)[1]), "r"((a)[2]), "r"((a)[3]), "r"(b0), "r"(b1))

// ===========================================================================
// fp16 2-pass HMMA GEMM for node-side: C[M,256] = op(A[M,K] @ (Bh+Bl)[256,K]^T)
// A fp16 single (its rounding is random, averaged over K); B fp16 hi/lo.
// Tile 128x128, BK=64, 8 warps of 64x32. fp16 out.
// ===========================================================================
template<int KDIM, bool RELU>
__global__ __launch_bounds__(256)
void hmma_f16(const __half* __restrict__ A,
              const __half* __restrict__ Bh_,
              const __half* __restrict__ Bl_,
              const float* __restrict__ bias,
              __half* __restrict__ C,
              int M)
{
    constexpr int OFF_BH = 16384;
    constexpr int OFF_BL = 32768;
    constexpr int SBYTES = 49152;
    constexpr int NKC    = KDIM / 64;

    extern __shared__ char smem[];
    const uint32_t sbase = smem_u32(smem);
    const int tid = threadIdx.x;
    const int wid = tid >> 5;
    const int lane = tid & 31;
    const int rowBase = blockIdx.x * 128;
    const int colBase = blockIdx.y * 128;

    const int wm = wid >> 2;
    const int wn = wid & 3;
    const int lr = lane & 15;
    const int lc = lane >> 4;

    float acc[4][4][4];
#pragma unroll
    for (int mt = 0; mt < 4; ++mt)
#pragma unroll
        for (int nt = 0; nt < 4; ++nt)
#pragma unroll
            for (int q = 0; q < 4; ++q) acc[mt][nt][q] = 0.f;

    auto load_stage = [&](int buf, int kc) {
        const uint32_t st = sbase + buf * SBYTES;
        const int kBase = kc * 64;
#pragma unroll
        for (int l = 0; l < 4; ++l) {
            int idx = tid + l * 256;
            int r = idx >> 3, cc = idx & 7;
            int gr = rowBase + r;
            uint32_t sz = (gr < M) ? 16u : 0u;
            int grc = (gr < M) ? gr : (M - 1);
            uint32_t doff = SW128((uint32_t)(r * 128 + cc * 16));
            const char* sa = (const char*)(A + (size_t)grc * KDIM + kBase) + cc * 16;
            CP_ASYNC16Z(st + doff, sa, sz);
        }
#pragma unroll
        for (int l = 0; l < 4; ++l) {
            int idx = tid + l * 256;
            int r = idx >> 3, cc = idx & 7;
            uint32_t doff = SW128((uint32_t)(r * 128 + cc * 16));
            const char* sh = (const char*)(Bh_ + (size_t)(colBase + r) * KDIM + kBase) + cc * 16;
            const char* sl = (const char*)(Bl_ + (size_t)(colBase + r) * KDIM + kBase) + cc * 16;
            CP_ASYNC16(st + OFF_BH + doff, sh);
            CP_ASYNC16(st + OFF_BL + doff, sl);
        }
    };

    load_stage(0, 0);
    CP_COMMIT();

    for (int kc = 0; kc < NKC; ++kc) {
        if (kc + 1 < NKC) {
            load_stage((kc + 1) & 1, kc + 1);
            CP_COMMIT();
            CP_WAIT(1);
        } else {
            CP_WAIT(0);
        }
        __syncthreads();

        const uint32_t st = sbase + (kc & 1) * SBYTES;
#pragma unroll
        for (int k16 = 0; k16 < 4; ++k16) {
            const uint32_t kOff = k16 * 32 + lc * 16;
            uint32_t a[4][4];
#pragma unroll
            for (int mt = 0; mt < 4; ++mt) {
                int row = wm * 64 + mt * 16 + lr;
                LDSM_X4(a[mt][0], a[mt][1], a[mt][2], a[mt][3],
                        st + SW128((uint32_t)(row * 128) + kOff));
            }
            uint32_t bh[2][4], bl[2][4];
#pragma unroll
            for (int ng = 0; ng < 2; ++ng) {
                int row = wn * 32 + ng * 16 + lr;
                uint32_t off = SW128((uint32_t)(row * 128) + kOff);
                LDSM_X4(bh[ng][0], bh[ng][1], bh[ng][2], bh[ng][3], st + OFF_BH + off);
                LDSM_X4(bl[ng][0], bl[ng][1], bl[ng][2], bl[ng][3], st + OFF_BL + off);
            }
#pragma unroll
            for (int mt = 0; mt < 4; ++mt)
#pragma unroll
                for (int nt = 0; nt < 4; ++nt) {
                    const int ng = nt >> 1, s = nt & 1;
                    MMA_F16(acc[mt][nt], a[mt], bh[ng][s], bh[ng][s + 2]);
                    MMA_F16(acc[mt][nt], a[mt], bl[ng][s], bl[ng][s + 2]);
                }
        }
        __syncthreads();
    }

    const int row0 = rowBase + wm * 64 + (lane >> 2);
    const int col0 = colBase + wn * 32 + ((lane & 3) << 1);
#pragma unroll
    for (int mt = 0; mt < 4; ++mt)
#pragma unroll
        for (int nt = 0; nt < 4; ++nt) {
            const int c = col0 + nt * 8;
            float v0 = acc[mt][nt][0], v1 = acc[mt][nt][1];
            float v2 = acc[mt][nt][2], v3 = acc[mt][nt][3];
            if (RELU) {
                float2 bb = *(const float2*)&bias[c];
                v0 = fmaxf(v0 + bb.x, 0.f); v1 = fmaxf(v1 + bb.y, 0.f);
                v2 = fmaxf(v2 + bb.x, 0.f); v3 = fmaxf(v3 + bb.y, 0.f);
            }
            __half2 h1, h2;
            h1.x = __float2half_rn(v0); h1.y = __float2half_rn(v1);
            h2.x = __float2half_rn(v2); h2.y = __float2half_rn(v3);
            const int r1 = row0 + mt * 16;
            const int r2 = r1 + 8;
            if (r1 < M) *(__half2*)&C[(size_t)r1 * 256 + c] = h1;
            if (r2 < M) *(__half2*)&C[(size_t)r2 * 256 + c] = h2;
        }
}

// ===========================================================================
// FUSED mix kernel: 512 threads / 16 warps; fp16 single-pass; W3 resident.
// Edge-major epilogue (R12, proven); A1/A2 now fp16 (half the gather bytes).
// ===========================================================================
#define EF_CHUNK  16384
#define RAW_OFF   32768
#define W3_OFF    65536
#define W3_CHUNK  32768
#define WE_OFF    196608
#define MIX_SMEM  229376
#define EPI_STRIDE 260
#define MIX_THREADS 512

__global__ __launch_bounds__(MIX_THREADS)
void mix_fused_kernel(const float* __restrict__ EFraw,
                      const __half* __restrict__ We_,
                      const float* __restrict__ be,
                      const __half* __restrict__ W3_,
                      const float* __restrict__ bm,
                      const __half* __restrict__ A1, const __half* __restrict__ A2,
                      const int* __restrict__ idxn, const int* __restrict__ seg)
{
    extern __shared__ char smem[];
    const uint32_t sbase = smem_u32(smem);
    const int tid = threadIdx.x;
    const int wid = tid >> 5;
    const int lane = tid & 31;
    const int rowBase = blockIdx.x * 128;

    const int wm = wid >> 2;       // 0..3 (32-row band)
    const int wn = wid & 3;        // 0..3 (64-col band)
    const int lr = lane & 15;
    const int lc = lane >> 4;

    float acc[2][8][4];
#pragma unroll
    for (int mt = 0; mt < 2; ++mt)
#pragma unroll
        for (int nt = 0; nt < 8; ++nt)
#pragma unroll
            for (int q = 0; q < 4; ++q) acc[mt][nt][q] = 0.f;

    // ---- prologue: G0 = raw ef + We; G1..G4 = W3 chunks ----
#pragma unroll
    for (int l = 0; l < 2; ++l) {          // raw fp32: 128 rows x 128B, linear
        int idx = tid + l * MIX_THREADS;
        int r = idx >> 3, cc = idx & 7;
        CP_ASYNC16(sbase + RAW_OFF + (uint32_t)(r * 128 + cc * 16),
                   (const char*)(EFraw + (size_t)(rowBase + r) * 32) + cc * 16);
    }
#pragma unroll
    for (int l = 0; l < 4; ++l) {          // We: 256 rows x 128B
        int idx = tid + l * MIX_THREADS;
        int r = idx >> 3, cc = idx & 7;
        CP_ASYNC16(sbase + WE_OFF + SW128((uint32_t)(r * 128 + cc * 16)),
                   (const char*)(We_ + (size_t)r * 64) + cc * 16);
    }
    CP_COMMIT();                           // G0
#pragma unroll
    for (int kc = 0; kc < 4; ++kc) {       // W3 chunk kc: 256 rows x 128B
#pragma unroll
        for (int l = 0; l < 4; ++l) {
            int idx = tid + l * MIX_THREADS;
            int r = idx >> 3, cc = idx & 7;
            CP_ASYNC16(sbase + W3_OFF + kc * W3_CHUNK +
                           SW128((uint32_t)(r * 128 + cc * 16)),
                       (const char*)(W3_ + (size_t)r * 256 + kc * 64) + cc * 16);
        }
        CP_COMMIT();                       // G1..G4
    }

    CP_WAIT(4);                            // G0 done; W3 still streaming
    __syncthreads();

    // ---- convert raw fp32 -> EF-in fp16 (chunk0 region, zero-pad k>=32) ----
#pragma unroll
    for (int l = 0; l < 2; ++l) {
        int idx = tid + l * MIX_THREADS;
        int r = idx >> 3, s = idx & 7;
        uint32_t dst = (uint32_t)SW128((uint32_t)(r * 128 + s * 16));
        if (s < 4) {
            float4 f0 = *(const float4*)(smem + RAW_OFF + r * 128 + s * 32);
            float4 f1 = *(const float4*)(smem + RAW_OFF + r * 128 + s * 32 + 16);
            __half h[8];
            h[0] = __float2half_rn(f0.x); h[1] = __float2half_rn(f0.y);
            h[2] = __float2half_rn(f0.z); h[3] = __float2half_rn(f0.w);
            h[4] = __float2half_rn(f1.x); h[5] = __float2half_rn(f1.y);
            h[6] = __float2half_rn(f1.z); h[7] = __float2half_rn(f1.w);
            *(uint4*)(smem + dst) = *(uint4*)h;
        } else {
            *(uint4*)(smem + dst) = make_uint4(0, 0, 0, 0);
        }
    }
    __syncthreads();

    // ---- stage 1: EF = efin @ We^T (K=64, single pass) ----
    {
        const uint32_t stA = sbase;
        const uint32_t stB = sbase + WE_OFF;
#pragma unroll
        for (int k16 = 0; k16 < 4; ++k16) {
            const uint32_t kOff = k16 * 32 + lc * 16;
            uint32_t a[2][4];
#pragma unroll
            for (int mt = 0; mt < 2; ++mt) {
                int row = wm * 32 + mt * 16 + lr;
                LDSM_X4(a[mt][0], a[mt][1], a[mt][2], a[mt][3],
                        stA + SW128((uint32_t)(row * 128) + kOff));
            }
            uint32_t b[4][4];
#pragma unroll
            for (int ng = 0; ng < 4; ++ng) {
                int row = wn * 64 + ng * 16 + lr;
                LDSM_X4(b[ng][0], b[ng][1], b[ng][2], b[ng][3],
                        stB + SW128((uint32_t)(row * 128) + kOff));
            }
#pragma unroll
            for (int mt = 0; mt < 2; ++mt)
#pragma unroll
                for (int nt = 0; nt < 8; ++nt) {
                    const int ng = nt >> 1, s = nt & 1;
                    MMA_F16(acc[mt][nt], a[mt], b[ng][s], b[ng][s + 2]);
                }
        }
    }
    __syncthreads();   // all reads of efin done (chunk0 will be overwritten)

    // ---- EF store: bias + relu -> fp16 chunks ----
    {
        const int r0 = wm * 32 + (lane >> 2);
        const int c0 = wn * 64 + ((lane & 3) << 1);
#pragma unroll
        for (int mt = 0; mt < 2; ++mt)
#pragma unroll
            for (int nt = 0; nt < 8; ++nt) {
                const int c = c0 + nt * 8;
                float2 bb = *(const float2*)&be[c];
                float v0 = fmaxf(acc[mt][nt][0] + bb.x, 0.f);
                float v1 = fmaxf(acc[mt][nt][1] + bb.y, 0.f);
                float v2 = fmaxf(acc[mt][nt][2] + bb.x, 0.f);
                float v3 = fmaxf(acc[mt][nt][3] + bb.y, 0.f);
                __half p1[2], p2[2];
                p1[0] = __float2half_rn(v0); p1[1] = __float2half_rn(v1);
                p2[0] = __float2half_rn(v2); p2[1] = __float2half_rn(v3);
                const int chunk = c >> 6, cl2 = (c & 63) * 2;
                const int r1 = r0 + mt * 16, r2 = r1 + 8;
                *(uint32_t*)(smem + chunk * EF_CHUNK +
                    SW128((uint32_t)(r1 * 128 + cl2))) = *(uint32_t*)p1;
                *(uint32_t*)(smem + chunk * EF_CHUNK +
                    SW128((uint32_t)(r2 * 128 + cl2))) = *(uint32_t*)p2;
                acc[mt][nt][0] = 0.f; acc[mt][nt][1] = 0.f;
                acc[mt][nt][2] = 0.f; acc[mt][nt][3] = 0.f;
            }
    }
    __syncthreads();   // EF visible

    // ---- stage 2: T = EF @ W3^T, W3 fully resident, single pass ----
#pragma unroll
    for (int kc = 0; kc < 4; ++kc) {
        if      (kc == 0) CP_WAIT(3);
        else if (kc == 1) CP_WAIT(2);
        else if (kc == 2) CP_WAIT(1);
        else              CP_WAIT(0);
        __syncthreads();               // publish this W3 chunk

        const uint32_t stA = sbase + kc * EF_CHUNK;
        const uint32_t stB = sbase + W3_OFF + kc * W3_CHUNK;
#pragma unroll
        for (int k16 = 0; k16 < 4; ++k16) {
            const uint32_t kOff = k16 * 32 + lc * 16;
            uint32_t a[2][4];
#pragma unroll
            for (int mt = 0; mt < 2; ++mt) {
                int row = wm * 32 + mt * 16 + lr;
                LDSM_X4(a[mt][0], a[mt][1], a[mt][2], a[mt][3],
                        stA + SW128((uint32_t)(row * 128) + kOff));
            }
            uint32_t b[4][4];
#pragma unroll
            for (int ng = 0; ng < 4; ++ng) {
                int row = wn * 64 + ng * 16 + lr;
                LDSM_X4(b[ng][0], b[ng][1], b[ng][2], b[ng][3],
                        stB + SW128((uint32_t)(row * 128) + kOff));
            }
#pragma unroll
            for (int mt = 0; mt < 2; ++mt)
#pragma unroll
                for (int nt = 0; nt < 8; ++nt) {
                    const int ng = nt >> 1, s = nt & 1;
                    MMA_F16(acc[mt][nt], a[mt], b[ng][s], b[ng][s + 2]);
                }
        }
    }
    __syncthreads();   // all MMA/LDSM done before sC overlays smem

    // ---- fragments -> padded smem [128][EPI_STRIDE] fp32 ----
    float* sC = (float*)smem;
    {
        const int r0 = wm * 32 + (lane >> 2);
        const int c0 = wn * 64 + ((lane & 3) << 1);
#pragma unroll
        for (int mt = 0; mt < 2; ++mt)
#pragma unroll
            for (int nt = 0; nt < 8; ++nt) {
                int rr = r0 + mt * 16;
                int cc = c0 + nt * 8;
                *(float2*)&sC[rr * EPI_STRIDE + cc] =
                    make_float2(acc[mt][nt][0], acc[mt][nt][1]);
                *(float2*)&sC[(rr + 8) * EPI_STRIDE + cc] =
                    make_float2(acc[mt][nt][2], acc[mt][nt][3]);
            }
    }
    __syncthreads();

    // ---- edge-major epilogue: warp = 8 consecutive edges, lane = 8 cols ----
    {
        const int cb = lane * 8;                 // this lane's 8 columns
        float bv[8];
        *(float4*)&bv[0] = *(const float4*)&bm[cb];
        *(float4*)&bv[4] = *(const float4*)&bm[cb + 4];

        const int e0 = rowBase + wid * 8;
        float racc[8];
#pragma unroll
        for (int j = 0; j < 8; ++j) racc[j] = 0.f;
        int rseg = __ldg(&seg[e0]);

#pragma unroll
        for (int i = 0; i < 8; ++i) {
            const int e = e0 + i;
            const int i1 = __ldg(&idxn[e]);
            const int i2 = __ldg(&seg[e]);
            const float* tr = &sC[(wid * 8 + i) * EPI_STRIDE + cb];
            float4 t0 = *(const float4*)&tr[0];
            float4 t1 = *(const float4*)&tr[4];
            uint4 pa1 = *(const uint4*)&A1[(size_t)i1 * 256 + cb];
            uint4 pa2 = *(const uint4*)&A2[(size_t)i2 * 256 + cb];
            const __half2* ha1 = (const __half2*)&pa1;
            const __half2* ha2 = (const __half2*)&pa2;
            float2 a1f[4], a2f[4];
#pragma unroll
            for (int q = 0; q < 4; ++q) {
                a1f[q] = __half22float2(ha1[q]);
                a2f[q] = __half22float2(ha2[q]);
            }
            float v[8];
            v[0] = fmaxf(t0.x + a1f[0].x + a2f[0].x + bv[0], 0.f);
            v[1] = fmaxf(t0.y + a1f[0].y + a2f[0].y + bv[1], 0.f);
            v[2] = fmaxf(t0.z + a1f[1].x + a2f[1].x + bv[2], 0.f);
            v[3] = fmaxf(t0.w + a1f[1].y + a2f[1].y + bv[3], 0.f);
            v[4] = fmaxf(t1.x + a1f[2].x + a2f[2].x + bv[4], 0.f);
            v[5] = fmaxf(t1.y + a1f[2].y + a2f[2].y + bv[5], 0.f);
            v[6] = fmaxf(t1.z + a1f[3].x + a2f[3].x + bv[6], 0.f);
            v[7] = fmaxf(t1.w + a1f[3].y + a2f[3].y + bv[7], 0.f);

            if (i2 != rseg) {
                float* srow = &g_sum[(size_t)rseg * 256 + cb];
#pragma unroll
                for (int j = 0; j < 8; ++j) atomicAdd(&srow[j], racc[j]);
                rseg = i2;
#pragma unroll
                for (int j = 0; j < 8; ++j) racc[j] = v[j];
            } else {
#pragma unroll
                for (int j = 0; j < 8; ++j) racc[j] += v[j];
            }
        }
        float* srow = &g_sum[(size_t)rseg * 256 + cb];
#pragma unroll
        for (int j = 0; j < 8; ++j) atomicAdd(&srow[j], racc[j]);
    }
}

// ---------------- merged prep kernel (weights + input) --------------------
__global__ void prep_all(const float* __restrict__ input,
                         const float* __restrict__ Wn,
                         const float* __restrict__ Wm,
                         const float* __restrict__ We)
{
    int i = blockIdx.x * blockDim.x + threadIdx.x;
    if (i < NN * D) {
        g_in[i] = __float2half_rn(input[i]);
    }
    if (i < 65536) {
        int n = i >> 8, k = i & 255;
        float w0 = Wn[k * 256 + n];
        float w1 = Wm[k * 256 + n];
        float w2 = Wm[(256 + k) * 256 + n];
        float w3 = Wm[(512 + k) * 256 + n];
        __half h;
        h = __float2half_rn(w0); g_wnt_h[n * 256 + k] = h;
        g_wnt_l[n * 256 + k] = __float2half_rn(w0 - __half2float(h));
        h = __float2half_rn(w1); g_wm1t_h[n * 256 + k] = h;
        g_wm1t_l[n * 256 + k] = __float2half_rn(w1 - __half2float(h));
        h = __float2half_rn(w2); g_wm2t_h[n * 256 + k] = h;
        g_wm2t_l[n * 256 + k] = __float2half_rn(w2 - __half2float(h));
        g_wm3t[n * 256 + k] = __float2half_rn(w3);
        if (k < 64) {
            float we = (k < 32) ? We[k * 256 + n] : 0.f;
            g_wet[n * 64 + k] = __float2half_rn(we);
        }
    }
}

// grid = NN blocks of 256; counts via binary search on sorted seg;
// resets g_sum to 0 for the next replay (device globals start zeroed).
__global__ void final_kernel(const int* __restrict__ seg, float* __restrict__ out)
{
    __shared__ int s_cnt;
    const int n = blockIdx.x;
    if (threadIdx.x == 0) {
        int lo = 0, hi = NE;
        while (lo < hi) { int mid = (lo + hi) >> 1; if (seg[mid] <  n) lo = mid + 1; else hi = mid; }
        int lb = lo;
        lo = 0; hi = NE;
        while (lo < hi) { int mid = (lo + hi) >> 1; if (seg[mid] <= n) lo = mid + 1; else hi = mid; }
        s_cnt = lo - lb;
    }
    __syncthreads();
    const int c = s_cnt;
    const int i = n * 256 + threadIdx.x;
    float s = g_sum[i];
    out[i] = (c > 0) ? s / (float)c : 0.f;
    g_sum[i] = 0.f;
}

// ===========================================================================
extern "C" void kernel_launch(void* const* d_in, const int* in_sizes, int n_in,
                              void* d_out, int out_size)
{
    const float* input     = (const float*)d_in[0];
    const float* edgefeats = (const float*)d_in[1];
    const int*   idxn      = (const int*)  d_in[2];
    const int*   seg_ids   = (const int*)  d_in[3];
    const float* Wn        = (const float*)d_in[4];
    const float* bn        = (const float*)d_in[5];
    const float* We        = (const float*)d_in[6];
    const float* be        = (const float*)d_in[7];
    const float* Wm        = (const float*)d_in[8];
    const float* bm        = (const float*)d_in[9];
    float* out = (float*)d_out;

    __half *p_A1, *p_A2, *p_in, *p_nf;
    __half *p_wnth, *p_wntl, *p_w1h, *p_w1l, *p_w2h, *p_w2l, *p_w3, *p_we;
    cudaGetSymbolAddress((void**)&p_A1, g_A1);
    cudaGetSymbolAddress((void**)&p_A2, g_A2);
    cudaGetSymbolAddress((void**)&p_in, g_in);
    cudaGetSymbolAddress((void**)&p_nf, g_nf);
    cudaGetSymbolAddress((void**)&p_wnth, g_wnt_h);
    cudaGetSymbolAddress((void**)&p_wntl, g_wnt_l);
    cudaGetSymbolAddress((void**)&p_w1h, g_wm1t_h);
    cudaGetSymbolAddress((void**)&p_w1l, g_wm1t_l);
    cudaGetSymbolAddress((void**)&p_w2h, g_wm2t_h);
    cudaGetSymbolAddress((void**)&p_w2l, g_wm2t_l);
    cudaGetSymbolAddress((void**)&p_w3, g_wm3t);
    cudaGetSymbolAddress((void**)&p_we, g_wet);

    cudaFuncSetAttribute(mix_fused_kernel,
                         cudaFuncAttributeMaxDynamicSharedMemorySize, MIX_SMEM);
    cudaFuncSetAttribute(hmma_f16<256, true>,
                         cudaFuncAttributeMaxDynamicSharedMemorySize, 98304);
    cudaFuncSetAttribute(hmma_f16<256, false>,
                         cudaFuncAttributeMaxDynamicSharedMemorySize, 98304);

    prep_all<<<(NN * D + 255) / 256, 256>>>(input, Wn, Wm, We);

    {
        dim3 g((NN + 127) / 128, 2);
        hmma_f16<256, true><<<g, 256, 98304>>>(p_in, p_wnth, p_wntl, bn, p_nf, NN);
        hmma_f16<256, false><<<g, 256, 98304>>>(p_nf, p_w1h, p_w1l, nullptr, p_A1, NN);
        hmma_f16<256, false><<<g, 256, 98304>>>(p_nf, p_w2h, p_w2l, nullptr, p_A2, NN);
    }
    mix_fused_kernel<<<NE / 128, MIX_THREADS, MIX_SMEM>>>(
        edgefeats, p_we, be, p_w3, bm, p_A1, p_A2, idxn, seg_ids);

    final_kernel<<<NN, 256>>>(seg_ids, out);
}

// round 17
// speedup vs baseline: 3.5871x; 1.0317x over previous
#include <cuda_runtime.h>
#include <cuda_fp16.h>
#include <cstdint>

#define NN 10000
#define NE 320000
#define D  256
#define NTILES (NE / 128)

// ---------------- scratch (device globals; no allocation allowed) ----------
__device__ __align__(256) __half g_A1[NN * D];
__device__ __align__(256) __half g_A2[NN * D];
__device__ __align__(256) float g_sum[NN * D];   // zero-init at load; self-resetting

__device__ __align__(256) __half g_in[NN * D];
__device__ __align__(256) __half g_nf[NN * D];

__device__ __align__(256) __half g_wnt_h[D * D],  g_wnt_l[D * D];
__device__ __align__(256) __half g_wm1t_h[D * D], g_wm1t_l[D * D];
__device__ __align__(256) __half g_wm2t_h[D * D], g_wm2t_l[D * D];
__device__ __align__(256) __half g_wm3t[D * D];          // Wm3^T fp16 [N][K]
__device__ __align__(256) __half g_wet[D * 64];          // We^T fp16 [N][64]

// =============================== PTX helpers ===============================
__device__ __forceinline__ uint32_t smem_u32(const void* p) {
    uint32_t a;
    asm("{ .reg .u64 t; cvta.to.shared.u64 t, %1; cvt.u32.u64 %0, t; }"
        : "=r"(a) : "l"(p));
    return a;
}
#define SW128(off) ((off) ^ (((off) >> 3) & 0x70))

#define CP_ASYNC16(dst, src) \
    asm volatile("cp.async.cg.shared.global [%0], [%1], 16;" \
        :: "r"(dst), "l"(src) : "memory")
#define CP_ASYNC16Z(dst, src, sz) \
    asm volatile("cp.async.cg.shared.global [%0], [%1], 16, %2;" \
        :: "r"(dst), "l"(src), "r"(sz) : "memory")
#define CP_COMMIT() asm volatile("cp.async.commit_group;" ::: "memory")
#define CP_WAIT(n)  asm volatile("cp.async.wait_group %0;" :: "n"(n) : "memory")

#define LDSM_X4(r0, r1, r2, r3, addr) \
    asm volatile("ldmatrix.sync.aligned.m8n8.x4.shared.b16 {%0,%1,%2,%3}, [%4];" \
        : "=r"(r0), "=r"(r1), "=r"(r2), "=r"(r3) : "r"(addr))

#define MMA_F16(c, a, b0, b1) \
    asm volatile("mma.sync.aligned.m16n8k16.row.col.f32.f16.f16.f32 " \
        "{%0,%1,%2,%3}, {%4,%5,%6,%7}, {%8,%9}, {%0,%1,%2,%3};" \
        : "+f"((c)[0]), "+f"((c)[1]), "+f"((c)[2]), "+f"((c)[3]) \
        : "r"((a)[0]), "r"((a)[1]), "r"((a)[2]), "r"((a)[3]), "r"(b0), "r"(b1))

// ===========================================================================
// fp16 2-pass HMMA GEMM for node-side, dual-output (blockIdx.z selects B/C).
// C[M,256] = op(A[M,K] @ (Bh+Bl)[256,K]^T). Tile 128x128, BK=64, 8 warps.
// ===========================================================================
template<int KDIM, bool RELU>
__global__ __launch_bounds__(256)
void hmma_f16(const __half* __restrict__ A,
              const __half* __restrict__ Bh_a, const __half* __restrict__ Bl_a,
              const __half* __restrict__ Bh_b, const __half* __restrict__ Bl_b,
              const float* __restrict__ bias,
              __half* __restrict__ Ca, __half* __restrict__ Cb,
              int M)
{
    constexpr int OFF_BH = 16384;
    constexpr int OFF_BL = 32768;
    constexpr int SBYTES = 49152;
    constexpr int NKC    = KDIM / 64;

    const __half* Bh_ = blockIdx.z ? Bh_b : Bh_a;
    const __half* Bl_ = blockIdx.z ? Bl_b : Bl_a;
    __half* C = blockIdx.z ? Cb : Ca;

    extern __shared__ char smem[];
    const uint32_t sbase = smem_u32(smem);
    const int tid = threadIdx.x;
    const int wid = tid >> 5;
    const int lane = tid & 31;
    const int rowBase = blockIdx.x * 128;
    const int colBase = blockIdx.y * 128;

    const int wm = wid >> 2;
    const int wn = wid & 3;
    const int lr = lane & 15;
    const int lc = lane >> 4;

    float acc[4][4][4];
#pragma unroll
    for (int mt = 0; mt < 4; ++mt)
#pragma unroll
        for (int nt = 0; nt < 4; ++nt)
#pragma unroll
            for (int q = 0; q < 4; ++q) acc[mt][nt][q] = 0.f;

    auto load_stage = [&](int buf, int kc) {
        const uint32_t st = sbase + buf * SBYTES;
        const int kBase = kc * 64;
#pragma unroll
        for (int l = 0; l < 4; ++l) {
            int idx = tid + l * 256;
            int r = idx >> 3, cc = idx & 7;
            int gr = rowBase + r;
            uint32_t sz = (gr < M) ? 16u : 0u;
            int grc = (gr < M) ? gr : (M - 1);
            uint32_t doff = SW128((uint32_t)(r * 128 + cc * 16));
            const char* sa = (const char*)(A + (size_t)grc * KDIM + kBase) + cc * 16;
            CP_ASYNC16Z(st + doff, sa, sz);
        }
#pragma unroll
        for (int l = 0; l < 4; ++l) {
            int idx = tid + l * 256;
            int r = idx >> 3, cc = idx & 7;
            uint32_t doff = SW128((uint32_t)(r * 128 + cc * 16));
            const char* sh = (const char*)(Bh_ + (size_t)(colBase + r) * KDIM + kBase) + cc * 16;
            const char* sl = (const char*)(Bl_ + (size_t)(colBase + r) * KDIM + kBase) + cc * 16;
            CP_ASYNC16(st + OFF_BH + doff, sh);
            CP_ASYNC16(st + OFF_BL + doff, sl);
        }
    };

    load_stage(0, 0);
    CP_COMMIT();

    for (int kc = 0; kc < NKC; ++kc) {
        if (kc + 1 < NKC) {
            load_stage((kc + 1) & 1, kc + 1);
            CP_COMMIT();
            CP_WAIT(1);
        } else {
            CP_WAIT(0);
        }
        __syncthreads();

        const uint32_t st = sbase + (kc & 1) * SBYTES;
#pragma unroll
        for (int k16 = 0; k16 < 4; ++k16) {
            const uint32_t kOff = k16 * 32 + lc * 16;
            uint32_t a[4][4];
#pragma unroll
            for (int mt = 0; mt < 4; ++mt) {
                int row = wm * 64 + mt * 16 + lr;
                LDSM_X4(a[mt][0], a[mt][1], a[mt][2], a[mt][3],
                        st + SW128((uint32_t)(row * 128) + kOff));
            }
            uint32_t bh[2][4], bl[2][4];
#pragma unroll
            for (int ng = 0; ng < 2; ++ng) {
                int row = wn * 32 + ng * 16 + lr;
                uint32_t off = SW128((uint32_t)(row * 128) + kOff);
                LDSM_X4(bh[ng][0], bh[ng][1], bh[ng][2], bh[ng][3], st + OFF_BH + off);
                LDSM_X4(bl[ng][0], bl[ng][1], bl[ng][2], bl[ng][3], st + OFF_BL + off);
            }
#pragma unroll
            for (int mt = 0; mt < 4; ++mt)
#pragma unroll
                for (int nt = 0; nt < 4; ++nt) {
                    const int ng = nt >> 1, s = nt & 1;
                    MMA_F16(acc[mt][nt], a[mt], bh[ng][s], bh[ng][s + 2]);
                    MMA_F16(acc[mt][nt], a[mt], bl[ng][s], bl[ng][s + 2]);
                }
        }
        __syncthreads();
    }

    const int row0 = rowBase + wm * 64 + (lane >> 2);
    const int col0 = colBase + wn * 32 + ((lane & 3) << 1);
#pragma unroll
    for (int mt = 0; mt < 4; ++mt)
#pragma unroll
        for (int nt = 0; nt < 4; ++nt) {
            const int c = col0 + nt * 8;
            float v0 = acc[mt][nt][0], v1 = acc[mt][nt][1];
            float v2 = acc[mt][nt][2], v3 = acc[mt][nt][3];
            if (RELU) {
                float2 bb = *(const float2*)&bias[c];
                v0 = fmaxf(v0 + bb.x, 0.f); v1 = fmaxf(v1 + bb.y, 0.f);
                v2 = fmaxf(v2 + bb.x, 0.f); v3 = fmaxf(v3 + bb.y, 0.f);
            }
            __half2 h1, h2;
            h1.x = __float2half_rn(v0); h1.y = __float2half_rn(v1);
            h2.x = __float2half_rn(v2); h2.y = __float2half_rn(v3);
            const int r1 = row0 + mt * 16;
            const int r2 = r1 + 8;
            if (r1 < M) *(__half2*)&C[(size_t)r1 * 256 + c] = h1;
            if (r2 < M) *(__half2*)&C[(size_t)r2 * 256 + c] = h2;
        }
}

// ===========================================================================
// PERSISTENT fused mix kernel: grid = 148 CTAs, each loops over edge tiles.
// W3 (128K) + We (32K) loaded once per CTA, resident for all tiles.
// smem 224K: [0,64K) EF chunks / raw / sC ; [64K,192K) W3 ; [192K,224K) We
// ===========================================================================
#define EF_CHUNK  16384
#define RAW_OFF   32768
#define W3_OFF    65536
#define W3_CHUNK  32768
#define WE_OFF    196608
#define MIX_SMEM  229376
#define MIX_THREADS 512
#define SC_SW(r, cbyte) (((uint32_t)((r) * 512 + (cbyte))) ^ (((uint32_t)((r) & 7)) << 4))

__global__ __launch_bounds__(MIX_THREADS)
void mix_persist(const float* __restrict__ EFraw,
                 const __half* __restrict__ We_,
                 const float* __restrict__ be,
                 const __half* __restrict__ W3_,
                 const float* __restrict__ bm,
                 const __half* __restrict__ A1, const __half* __restrict__ A2,
                 const int* __restrict__ idxn, const int* __restrict__ seg)
{
    extern __shared__ char smem[];
    const uint32_t sbase = smem_u32(smem);
    const int tid = threadIdx.x;
    const int wid = tid >> 5;
    const int lane = tid & 31;

    const int wm = wid >> 2;       // 0..3 (32-row band)
    const int wn = wid & 3;        // 0..3 (64-col band)
    const int lr = lane & 15;
    const int lc = lane >> 4;

    // ---- one-time: load We + all W3 chunks ----
#pragma unroll
    for (int l = 0; l < 4; ++l) {          // We: 256 rows x 128B
        int idx = tid + l * MIX_THREADS;
        int r = idx >> 3, cc = idx & 7;
        CP_ASYNC16(sbase + WE_OFF + SW128((uint32_t)(r * 128 + cc * 16)),
                   (const char*)(We_ + (size_t)r * 64) + cc * 16);
    }
#pragma unroll
    for (int kc = 0; kc < 4; ++kc) {
#pragma unroll
        for (int l = 0; l < 4; ++l) {
            int idx = tid + l * MIX_THREADS;
            int r = idx >> 3, cc = idx & 7;
            CP_ASYNC16(sbase + W3_OFF + kc * W3_CHUNK +
                           SW128((uint32_t)(r * 128 + cc * 16)),
                       (const char*)(W3_ + (size_t)r * 256 + kc * 64) + cc * 16);
        }
    }
    CP_COMMIT();

    for (int t = blockIdx.x; t < NTILES; t += gridDim.x) {
        const int rowBase = t * 128;
        __syncthreads();   // previous tile's epilogue done with sC region

        // ---- raw fp32 ef tile: 128 rows x 128B, linear at RAW_OFF ----
#pragma unroll
        for (int l = 0; l < 2; ++l) {
            int idx = tid + l * MIX_THREADS;
            int r = idx >> 3, cc = idx & 7;
            CP_ASYNC16(sbase + RAW_OFF + (uint32_t)(r * 128 + cc * 16),
                       (const char*)(EFraw + (size_t)(rowBase + r) * 32) + cc * 16);
        }
        CP_COMMIT();
        CP_WAIT(0);        // (first tile also drains We/W3 group)
        __syncthreads();

        // ---- convert raw fp32 -> efin fp16 (chunk0, zero-pad k>=32) ----
#pragma unroll
        for (int l = 0; l < 2; ++l) {
            int idx = tid + l * MIX_THREADS;
            int r = idx >> 3, s = idx & 7;
            uint32_t dst = (uint32_t)SW128((uint32_t)(r * 128 + s * 16));
            if (s < 4) {
                float4 f0 = *(const float4*)(smem + RAW_OFF + r * 128 + s * 32);
                float4 f1 = *(const float4*)(smem + RAW_OFF + r * 128 + s * 32 + 16);
                __half h[8];
                h[0] = __float2half_rn(f0.x); h[1] = __float2half_rn(f0.y);
                h[2] = __float2half_rn(f0.z); h[3] = __float2half_rn(f0.w);
                h[4] = __float2half_rn(f1.x); h[5] = __float2half_rn(f1.y);
                h[6] = __float2half_rn(f1.z); h[7] = __float2half_rn(f1.w);
                *(uint4*)(smem + dst) = *(uint4*)h;
            } else {
                *(uint4*)(smem + dst) = make_uint4(0, 0, 0, 0);
            }
        }
        __syncthreads();

        float acc[2][8][4];
#pragma unroll
        for (int mt = 0; mt < 2; ++mt)
#pragma unroll
            for (int nt = 0; nt < 8; ++nt)
#pragma unroll
                for (int q = 0; q < 4; ++q) acc[mt][nt][q] = 0.f;

        // ---- stage 1: EF = efin @ We^T (K=64) ----
        {
            const uint32_t stA = sbase;
            const uint32_t stB = sbase + WE_OFF;
#pragma unroll
            for (int k16 = 0; k16 < 4; ++k16) {
                const uint32_t kOff = k16 * 32 + lc * 16;
                uint32_t a[2][4];
#pragma unroll
                for (int mt = 0; mt < 2; ++mt) {
                    int row = wm * 32 + mt * 16 + lr;
                    LDSM_X4(a[mt][0], a[mt][1], a[mt][2], a[mt][3],
                            stA + SW128((uint32_t)(row * 128) + kOff));
                }
                uint32_t b[4][4];
#pragma unroll
                for (int ng = 0; ng < 4; ++ng) {
                    int row = wn * 64 + ng * 16 + lr;
                    LDSM_X4(b[ng][0], b[ng][1], b[ng][2], b[ng][3],
                            stB + SW128((uint32_t)(row * 128) + kOff));
                }
#pragma unroll
                for (int mt = 0; mt < 2; ++mt)
#pragma unroll
                    for (int nt = 0; nt < 8; ++nt) {
                        const int ng = nt >> 1, s = nt & 1;
                        MMA_F16(acc[mt][nt], a[mt], b[ng][s], b[ng][s + 2]);
                    }
            }
        }
        __syncthreads();   // efin reads done; chunks will be overwritten

        // ---- EF store: bias + relu -> fp16 chunks 0..3 ----
        {
            const int r0 = wm * 32 + (lane >> 2);
            const int c0 = wn * 64 + ((lane & 3) << 1);
#pragma unroll
            for (int mt = 0; mt < 2; ++mt)
#pragma unroll
                for (int nt = 0; nt < 8; ++nt) {
                    const int c = c0 + nt * 8;
                    float2 bb = *(const float2*)&be[c];
                    float v0 = fmaxf(acc[mt][nt][0] + bb.x, 0.f);
                    float v1 = fmaxf(acc[mt][nt][1] + bb.y, 0.f);
                    float v2 = fmaxf(acc[mt][nt][2] + bb.x, 0.f);
                    float v3 = fmaxf(acc[mt][nt][3] + bb.y, 0.f);
                    __half p1[2], p2[2];
                    p1[0] = __float2half_rn(v0); p1[1] = __float2half_rn(v1);
                    p2[0] = __float2half_rn(v2); p2[1] = __float2half_rn(v3);
                    const int chunk = c >> 6, cl2 = (c & 63) * 2;
                    const int r1 = r0 + mt * 16, r2 = r1 + 8;
                    *(uint32_t*)(smem + chunk * EF_CHUNK +
                        SW128((uint32_t)(r1 * 128 + cl2))) = *(uint32_t*)p1;
                    *(uint32_t*)(smem + chunk * EF_CHUNK +
                        SW128((uint32_t)(r2 * 128 + cl2))) = *(uint32_t*)p2;
                    acc[mt][nt][0] = 0.f; acc[mt][nt][1] = 0.f;
                    acc[mt][nt][2] = 0.f; acc[mt][nt][3] = 0.f;
                }
        }
        __syncthreads();   // EF visible

        // ---- stage 2: T = EF @ W3^T; both operands static -> no syncs ----
#pragma unroll
        for (int kc = 0; kc < 4; ++kc) {
            const uint32_t stA = sbase + kc * EF_CHUNK;
            const uint32_t stB = sbase + W3_OFF + kc * W3_CHUNK;
#pragma unroll
            for (int k16 = 0; k16 < 4; ++k16) {
                const uint32_t kOff = k16 * 32 + lc * 16;
                uint32_t a[2][4];
#pragma unroll
                for (int mt = 0; mt < 2; ++mt) {
                    int row = wm * 32 + mt * 16 + lr;
                    LDSM_X4(a[mt][0], a[mt][1], a[mt][2], a[mt][3],
                            stA + SW128((uint32_t)(row * 128) + kOff));
                }
                uint32_t b[4][4];
#pragma unroll
                for (int ng = 0; ng < 4; ++ng) {
                    int row = wn * 64 + ng * 16 + lr;
                    LDSM_X4(b[ng][0], b[ng][1], b[ng][2], b[ng][3],
                            stB + SW128((uint32_t)(row * 128) + kOff));
                }
#pragma unroll
                for (int mt = 0; mt < 2; ++mt)
#pragma unroll
                    for (int nt = 0; nt < 8; ++nt) {
                        const int ng = nt >> 1, s = nt & 1;
                        MMA_F16(acc[mt][nt], a[mt], b[ng][s], b[ng][s + 2]);
                    }
            }
        }
        __syncthreads();   // stage2 reads done; sC overlays chunks

        // ---- fragments -> fp16 sC [128][256] with XOR swizzle (64KB) ----
        {
            const int r0 = wm * 32 + (lane >> 2);
            const int c0 = wn * 64 + ((lane & 3) << 1);
#pragma unroll
            for (int mt = 0; mt < 2; ++mt)
#pragma unroll
                for (int nt = 0; nt < 8; ++nt) {
                    const int c = c0 + nt * 8;
                    const int r1 = r0 + mt * 16, r2 = r1 + 8;
                    __half2 h1, h2;
                    h1.x = __float2half_rn(acc[mt][nt][0]);
                    h1.y = __float2half_rn(acc[mt][nt][1]);
                    h2.x = __float2half_rn(acc[mt][nt][2]);
                    h2.y = __float2half_rn(acc[mt][nt][3]);
                    *(__half2*)(smem + SC_SW(r1, c * 2)) = h1;
                    *(__half2*)(smem + SC_SW(r2, c * 2)) = h2;
                }
        }
        __syncthreads();

        // ---- edge-major epilogue: warp = 8 edges, lane = 8 cols ----
        {
            const int cb = lane * 8;
            float bv[8];
            *(float4*)&bv[0] = *(const float4*)&bm[cb];
            *(float4*)&bv[4] = *(const float4*)&bm[cb + 4];

            const int e0 = rowBase + wid * 8;
            float racc[8];
#pragma unroll
            for (int j = 0; j < 8; ++j) racc[j] = 0.f;
            int rseg = __ldg(&seg[e0]);

#pragma unroll
            for (int i = 0; i < 8; ++i) {
                const int e = e0 + i;
                const int i1 = __ldg(&idxn[e]);
                const int i2 = __ldg(&seg[e]);
                const int row = wid * 8 + i;
                uint4 pt = *(const uint4*)(smem + SC_SW(row, lane * 16));
                uint4 pa1 = *(const uint4*)&A1[(size_t)i1 * 256 + cb];
                uint4 pa2 = *(const uint4*)&A2[(size_t)i2 * 256 + cb];
                const __half2* ht  = (const __half2*)&pt;
                const __half2* ha1 = (const __half2*)&pa1;
                const __half2* ha2 = (const __half2*)&pa2;
                float v[8];
#pragma unroll
                for (int q = 0; q < 4; ++q) {
                    float2 tf = __half22float2(ht[q]);
                    float2 a1f = __half22float2(ha1[q]);
                    float2 a2f = __half22float2(ha2[q]);
                    v[q * 2 + 0] = fmaxf(tf.x + a1f.x + a2f.x + bv[q * 2 + 0], 0.f);
                    v[q * 2 + 1] = fmaxf(tf.y + a1f.y + a2f.y + bv[q * 2 + 1], 0.f);
                }
                if (i2 != rseg) {
                    float* srow = &g_sum[(size_t)rseg * 256 + cb];
#pragma unroll
                    for (int j = 0; j < 8; ++j) atomicAdd(&srow[j], racc[j]);
                    rseg = i2;
#pragma unroll
                    for (int j = 0; j < 8; ++j) racc[j] = v[j];
                } else {
#pragma unroll
                    for (int j = 0; j < 8; ++j) racc[j] += v[j];
                }
            }
            float* srow = &g_sum[(size_t)rseg * 256 + cb];
#pragma unroll
            for (int j = 0; j < 8; ++j) atomicAdd(&srow[j], racc[j]);
        }
    }
}

// ---------------- merged prep kernel (weights + input) --------------------
__global__ void prep_all(const float* __restrict__ input,
                         const float* __restrict__ Wn,
                         const float* __restrict__ Wm,
                         const float* __restrict__ We)
{
    int i = blockIdx.x * blockDim.x + threadIdx.x;
    if (i < NN * D) {
        g_in[i] = __float2half_rn(input[i]);
    }
    if (i < 65536) {
        int n = i >> 8, k = i & 255;
        float w0 = Wn[k * 256 + n];
        float w1 = Wm[k * 256 + n];
        float w2 = Wm[(256 + k) * 256 + n];
        float w3 = Wm[(512 + k) * 256 + n];
        __half h;
        h = __float2half_rn(w0); g_wnt_h[n * 256 + k] = h;
        g_wnt_l[n * 256 + k] = __float2half_rn(w0 - __half2float(h));
        h = __float2half_rn(w1); g_wm1t_h[n * 256 + k] = h;
        g_wm1t_l[n * 256 + k] = __float2half_rn(w1 - __half2float(h));
        h = __float2half_rn(w2); g_wm2t_h[n * 256 + k] = h;
        g_wm2t_l[n * 256 + k] = __float2half_rn(w2 - __half2float(h));
        g_wm3t[n * 256 + k] = __float2half_rn(w3);
        if (k < 64) {
            float we = (k < 32) ? We[k * 256 + n] : 0.f;
            g_wet[n * 64 + k] = __float2half_rn(we);
        }
    }
}

// grid = NN blocks of 256; counts via binary search on sorted seg;
// resets g_sum to 0 for the next replay (device globals start zeroed).
__global__ void final_kernel(const int* __restrict__ seg, float* __restrict__ out)
{
    __shared__ int s_cnt;
    const int n = blockIdx.x;
    if (threadIdx.x == 0) {
        int lo = 0, hi = NE;
        while (lo < hi) { int mid = (lo + hi) >> 1; if (seg[mid] <  n) lo = mid + 1; else hi = mid; }
        int lb = lo;
        lo = 0; hi = NE;
        while (lo < hi) { int mid = (lo + hi) >> 1; if (seg[mid] <= n) lo = mid + 1; else hi = mid; }
        s_cnt = lo - lb;
    }
    __syncthreads();
    const int c = s_cnt;
    const int i = n * 256 + threadIdx.x;
    float s = g_sum[i];
    out[i] = (c > 0) ? s / (float)c : 0.f;
    g_sum[i] = 0.f;
}

// ===========================================================================
extern "C" void kernel_launch(void* const* d_in, const int* in_sizes, int n_in,
                              void* d_out, int out_size)
{
    const float* input     = (const float*)d_in[0];
    const float* edgefeats = (const float*)d_in[1];
    const int*   idxn      = (const int*)  d_in[2];
    const int*   seg_ids   = (const int*)  d_in[3];
    const float* Wn        = (const float*)d_in[4];
    const float* bn        = (const float*)d_in[5];
    const float* We        = (const float*)d_in[6];
    const float* be        = (const float*)d_in[7];
    const float* Wm        = (const float*)d_in[8];
    const float* bm        = (const float*)d_in[9];
    float* out = (float*)d_out;

    __half *p_A1, *p_A2, *p_in, *p_nf;
    __half *p_wnth, *p_wntl, *p_w1h, *p_w1l, *p_w2h, *p_w2l, *p_w3, *p_we;
    cudaGetSymbolAddress((void**)&p_A1, g_A1);
    cudaGetSymbolAddress((void**)&p_A2, g_A2);
    cudaGetSymbolAddress((void**)&p_in, g_in);
    cudaGetSymbolAddress((void**)&p_nf, g_nf);
    cudaGetSymbolAddress((void**)&p_wnth, g_wnt_h);
    cudaGetSymbolAddress((void**)&p_wntl, g_wnt_l);
    cudaGetSymbolAddress((void**)&p_w1h, g_wm1t_h);
    cudaGetSymbolAddress((void**)&p_w1l, g_wm1t_l);
    cudaGetSymbolAddress((void**)&p_w2h, g_wm2t_h);
    cudaGetSymbolAddress((void**)&p_w2l, g_wm2t_l);
    cudaGetSymbolAddress((void**)&p_w3, g_wm3t);
    cudaGetSymbolAddress((void**)&p_we, g_wet);

    cudaFuncSetAttribute(mix_persist,
                         cudaFuncAttributeMaxDynamicSharedMemorySize, MIX_SMEM);
    cudaFuncSetAttribute(hmma_f16<256, true>,
                         cudaFuncAttributeMaxDynamicSharedMemorySize, 98304);
    cudaFuncSetAttribute(hmma_f16<256, false>,
                         cudaFuncAttributeMaxDynamicSharedMemorySize, 98304);

    prep_all<<<(NN * D + 255) / 256, 256>>>(input, Wn, Wm, We);

    {
        dim3 gn(79, 2, 1);
        hmma_f16<256, true><<<gn, 256, 98304>>>(
            p_in, p_wnth, p_wntl, p_wnth, p_wntl, bn, p_nf, p_nf, NN);
        dim3 gd(79, 2, 2);
        hmma_f16<256, false><<<gd, 256, 98304>>>(
            p_nf, p_w1h, p_w1l, p_w2h, p_w2l, nullptr, p_A1, p_A2, NN);
    }
    mix_persist<<<148, MIX_THREADS, MIX_SMEM>>>(
        edgefeats, p_we, be, p_w3, bm, p_A1, p_A2, idxn, seg_ids);

    final_kernel<<<NN, 256>>>(seg_ids, out);
}